// round 6
// baseline (speedup 1.0000x reference)
#include <cuda_runtime.h>
#include <cuda_bf16.h>
#include <math.h>
#include <cstdint>

#define TTOK 49152      // total tokens = 2*6*64*64
#define NWIN 384

// ---------------- scratch (device globals; no allocations allowed) ----------
__device__ float g_qkv[TTOK*576];       // qkv fp32 (reused self & mutual)
__device__ float g_attnbuf[TTOK*192];   // proj output (window order)
__device__ float g_xres[TTOK*192];      // x + attn residual (original order)
__device__ float g_pos[64*192];
__device__ float g_biasf[8*128*128];    // rel-pos bias per head [h][m_key][n_query]
__device__ int   g_cnt[8];
__device__ int   g_gidx[8*TTOK];
__device__ float g_gw[8*TTOK];
__device__ int   g_grank[8*TTOK];
__device__ float g_contrib0[TTOK*192];
__device__ float g_contrib1[TTOK*192];
// bf16 activation buffers for tensor-core GEMMs
__device__ __nv_bfloat16 g_xw_bf[TTOK*192];
__device__ __nv_bfloat16 g_xm_bf[TTOK*192];
__device__ __nv_bfloat16 g_xout_bf[TTOK*384];
__device__ __nv_bfloat16 g_xn2_bf[TTOK*192];
// transposed bf16 weights [N][K]
__device__ __nv_bfloat16 g_wt_qs[576*192];
__device__ __nv_bfloat16 g_wt_qm[576*192];
__device__ __nv_bfloat16 g_wt_p [192*384];
__device__ __nv_bfloat16 g_wt_w1[8*384*192];
__device__ __nv_bfloat16 g_wt_w2[8*192*384];

// ---------------- helpers ------------------------------------------------
typedef unsigned long long ull;
__device__ __forceinline__ float warpsum_all(float v) {
    #pragma unroll
    for (int o = 16; o; o >>= 1) v += __shfl_xor_sync(0xffffffffu, v, o);
    return v;
}
__device__ __forceinline__ uint32_t smem_u32(const void* p) {
    uint32_t a;
    asm("{ .reg .u64 t; cvta.to.shared.u64 t, %1; cvt.u32.u64 %0, t; }" : "=r"(a) : "l"(p));
    return a;
}
__device__ __forceinline__ void ldsm_x4(uint32_t& r0, uint32_t& r1, uint32_t& r2,
                                        uint32_t& r3, uint32_t addr) {
    asm volatile("ldmatrix.sync.aligned.m8n8.x4.shared.b16 {%0,%1,%2,%3}, [%4];"
                 : "=r"(r0), "=r"(r1), "=r"(r2), "=r"(r3) : "r"(addr));
}
__device__ __forceinline__ void mma16816(float* c, uint32_t a0, uint32_t a1,
                                         uint32_t a2, uint32_t a3,
                                         uint32_t b0, uint32_t b1) {
    asm volatile("mma.sync.aligned.m16n8k16.row.col.f32.bf16.bf16.f32 "
        "{%0,%1,%2,%3}, {%4,%5,%6,%7}, {%8,%9}, {%0,%1,%2,%3};"
        : "+f"(c[0]), "+f"(c[1]), "+f"(c[2]), "+f"(c[3])
        : "r"(a0), "r"(a1), "r"(a2), "r"(a3), "r"(b0), "r"(b1));
}
__device__ __forceinline__ void cp16(uint32_t dst, const void* src, bool v) {
    asm volatile("cp.async.cg.shared.global [%0], [%1], 16, %2;"
                 :: "r"(dst), "l"(src), "r"(v ? 16u : 0u));
}
#define CP_COMMIT() asm volatile("cp.async.commit_group;")
#define CP_WAIT1()  asm volatile("cp.async.wait_group 1;")
#define CP_WAIT0()  asm volatile("cp.async.wait_group 0;")
#define SMEM_SWZ(o) ((o) ^ (((o) >> 3) & 0x70))

// ---- packed f32x2 ops (Blackwell FFMA2) ----
__device__ __forceinline__ ull fma2(ull a, ull b, ull c) {
    ull d;
    asm("fma.rn.f32x2 %0, %1, %2, %3;" : "=l"(d) : "l"(a), "l"(b), "l"(c));
    return d;
}
__device__ __forceinline__ ull pack2(float x, float y) {
    ull r;
    asm("mov.b64 %0, {%1,%2};" : "=l"(r) : "f"(x), "f"(y));
    return r;
}
__device__ __forceinline__ float2 unpack2(ull v) {
    float x, y;
    asm("mov.b64 {%0,%1}, %2;" : "=f"(x), "=f"(y) : "l"(v));
    return make_float2(x, y);
}

// ---- shared 128x64 warp-tile MMA over one 64-K chunk (8 warps: 4m x 2n) ----
__device__ __forceinline__ void mma_tile(uint32_t aB, uint32_t bB,
                                         float (&c)[2][4][4], int wm, int wn, int lane) {
    int g = lane >> 3, l7 = lane & 7;
    #pragma unroll
    for (int ks = 0; ks < 4; ks++) {
        uint32_t a[2][4];
        #pragma unroll
        for (int mi = 0; mi < 2; mi++) {
            int r = wm*32 + mi*16 + ((g & 1) << 3) + l7;
            int kb = ks*32 + ((g >> 1) << 4);
            ldsm_x4(a[mi][0], a[mi][1], a[mi][2], a[mi][3],
                    aB + SMEM_SWZ((uint32_t)(r*128 + kb)));
        }
        uint32_t b[4][2];
        #pragma unroll
        for (int np = 0; np < 2; np++) {
            int r = wn*32 + np*16 + ((g >> 1) << 3) + l7;
            int kb = ks*32 + ((g & 1) << 4);
            uint32_t r0, r1, r2, r3;
            ldsm_x4(r0, r1, r2, r3, bB + SMEM_SWZ((uint32_t)(r*128 + kb)));
            b[np*2][0] = r0;   b[np*2][1] = r1;
            b[np*2+1][0] = r2; b[np*2+1][1] = r3;
        }
        #pragma unroll
        for (int mi = 0; mi < 2; mi++)
            #pragma unroll
            for (int nj = 0; nj < 4; nj++)
                mma16816(c[mi][nj], a[mi][0], a[mi][1], a[mi][2], a[mi][3],
                         b[nj][0], b[nj][1]);
    }
}

// ================= bf16 HMMA GEMM: block tile 128 x 64, cp.async 2-stage ====
__global__ __launch_bounds__(256) void gemm_mma(
        const __nv_bfloat16* __restrict__ A,
        const __nv_bfloat16* __restrict__ Bt,
        const float* __restrict__ bias,
        float* __restrict__ Cf, int K, int ldC) {
    extern __shared__ uint8_t dyn_raw[];
    int tid = threadIdx.x, wid = tid >> 5, lane = tid & 31;
    int wm = wid >> 1, wn = wid & 1;
    int row0 = blockIdx.x * 128, col0 = blockIdx.y * 64;

    uint32_t aBase = (smem_u32(dyn_raw) + 1023u) & ~1023u;
    uint32_t bBase = aBase + 32768;

    int srow = tid >> 3, c16 = tid & 7;
    const __nv_bfloat16* arp[4]; uint32_t aOff[4];
    #pragma unroll
    for (int i = 0; i < 4; i++) {
        int r = i*32 + srow;
        aOff[i] = SMEM_SWZ((uint32_t)(r*128 + c16*16));
        arp[i] = A + (size_t)(row0 + r)*K + c16*8;
    }
    const __nv_bfloat16* brp[2]; uint32_t bOff[2];
    #pragma unroll
    for (int i = 0; i < 2; i++) {
        int r = i*32 + srow;
        bOff[i] = SMEM_SWZ((uint32_t)(r*128 + c16*16));
        brp[i] = Bt + (size_t)(col0 + r)*K + c16*8;
    }

    float c[2][4][4] = {};
    int nch = K >> 6;

    #pragma unroll
    for (int i = 0; i < 4; i++) cp16(aBase + aOff[i], arp[i], true);
    #pragma unroll
    for (int i = 0; i < 2; i++) cp16(bBase + bOff[i], brp[i], true);
    CP_COMMIT();

    for (int ic = 0; ic < nch; ic++) {
        if (ic + 1 < nch) {
            int buf = (ic + 1) & 1, kc = (ic + 1) << 6;
            #pragma unroll
            for (int i = 0; i < 4; i++)
                cp16(aBase + buf*16384 + aOff[i], arp[i] + kc, true);
            #pragma unroll
            for (int i = 0; i < 2; i++)
                cp16(bBase + buf*8192 + bOff[i], brp[i] + kc, true);
            CP_COMMIT();
            CP_WAIT1();
        } else {
            CP_WAIT0();
        }
        __syncthreads();
        mma_tile(aBase + (ic & 1)*16384, bBase + (ic & 1)*8192, c, wm, wn, lane);
        __syncthreads();
    }

    int qr = lane >> 2, qc = (lane & 3) * 2;
    #pragma unroll
    for (int mi = 0; mi < 2; mi++) {
        #pragma unroll
        for (int h = 0; h < 2; h++) {
            int lr = wm*32 + mi*16 + h*8 + qr;
            #pragma unroll
            for (int nj = 0; nj < 4; nj++) {
                int col = col0 + wn*32 + nj*8 + qc;
                size_t crow = (size_t)(row0 + lr)*ldC + col;
                *reinterpret_cast<float2*>(Cf + crow) =
                    make_float2(c[mi][nj][2*h] + bias[col],
                                c[mi][nj][2*h+1] + bias[col+1]);
            }
        }
    }
}

// ======== fused MoE: FC1(gelu) + FC2(scatter), H resident in smem ==========
// smem: A panels 3x16KB | H panels 6x16KB | W double-buffer 2x8KB
__global__ __launch_bounds__(256) void moe_fused(const float* __restrict__ b1,
                                                 const float* __restrict__ b2) {
    extern __shared__ uint8_t dyn_raw[];
    __shared__ int s_tok[128]; __shared__ float s_wgt[128]; __shared__ int s_rnk[128];
    int tid = threadIdx.x, wid = tid >> 5, lane = tid & 31;
    int wm = wid >> 1, wn = wid & 1;
    int e = blockIdx.y;
    int cnt = g_cnt[e];
    int row0 = blockIdx.x * 128;
    if (row0 >= cnt) return;

    if (tid < 128) {
        int slot = row0 + tid;
        if (slot < cnt) {
            s_tok[tid] = g_gidx[e*TTOK + slot];
            s_wgt[tid] = g_gw[e*TTOK + slot];
            s_rnk[tid] = g_grank[e*TTOK + slot];
        } else s_tok[tid] = -1;
    }
    __syncthreads();

    uint32_t aBase = (smem_u32(dyn_raw) + 1023u) & ~1023u;
    uint32_t hBase = aBase + 49152;
    uint32_t wBase = hBase + 98304;
    uint8_t* sPtr = dyn_raw + (aBase - smem_u32(dyn_raw));

    const __nv_bfloat16* W1te = g_wt_w1 + (size_t)e*73728;
    const __nv_bfloat16* W2te = g_wt_w2 + (size_t)e*73728;
    const float* b1e = b1 + e*384;
    const float* b2e = b2 + e*192;

    int srow = tid >> 3, c16 = tid & 7;
    // stage A (gathered): 3 panels of 128x64 bf16
    #pragma unroll
    for (int pp = 0; pp < 3; pp++) {
        #pragma unroll
        for (int i = 0; i < 4; i++) {
            int r = i*32 + srow;
            int tk = s_tok[r];
            bool v = (tk >= 0);
            cp16(aBase + pp*16384 + SMEM_SWZ((uint32_t)(r*128 + c16*16)),
                 g_xn2_bf + (size_t)(v ? tk : 0)*192 + pp*64 + c16*8, v);
        }
    }
    // stage W tile 0 (FC1 nt=0,kc=0), same commit group as A
    #pragma unroll
    for (int i = 0; i < 2; i++) {
        int rr = i*32 + srow;
        cp16(wBase + SMEM_SWZ((uint32_t)(rr*128 + c16*16)),
             W1te + (size_t)rr*192 + c16*8, true);
    }
    CP_COMMIT();

    float c[2][4][4];
    int qr = lane >> 2, qc = (lane & 3) * 2;

    for (int idx = 0; idx < 36; idx++) {
        if (idx + 1 < 36) {
            int s = idx + 1, buf = s & 1;
            if (s < 18) {
                int nt = s/3, kc = s%3;
                #pragma unroll
                for (int i = 0; i < 2; i++) {
                    int rr = i*32 + srow;
                    cp16(wBase + buf*8192 + SMEM_SWZ((uint32_t)(rr*128 + c16*16)),
                         W1te + (size_t)(nt*64 + rr)*192 + kc*64 + c16*8, true);
                }
            } else {
                int j = s - 18; int nt = j/6, kc = j%6;
                #pragma unroll
                for (int i = 0; i < 2; i++) {
                    int rr = i*32 + srow;
                    cp16(wBase + buf*8192 + SMEM_SWZ((uint32_t)(rr*128 + c16*16)),
                         W2te + (size_t)(nt*64 + rr)*384 + kc*64 + c16*8, true);
                }
            }
            CP_COMMIT();
            CP_WAIT1();
        } else {
            CP_WAIT0();
        }
        __syncthreads();
        bool fc1 = (idx < 18);
        int j = fc1 ? idx : idx - 18;
        int nt = fc1 ? j/3 : j/6;
        int kc = fc1 ? j%3 : j%6;
        if (kc == 0) {
            #pragma unroll
            for (int mi = 0; mi < 2; mi++)
                #pragma unroll
                for (int nj = 0; nj < 4; nj++)
                    #pragma unroll
                    for (int q = 0; q < 4; q++) c[mi][nj][q] = 0.f;
        }
        uint32_t aB = fc1 ? (aBase + kc*16384) : (hBase + kc*16384);
        mma_tile(aB, wBase + (idx & 1)*8192, c, wm, wn, lane);
        bool lastk = fc1 ? (kc == 2) : (kc == 5);
        if (lastk) {
            if (fc1) {
                // gelu -> H panel nt (bf16, standard swizzle)
                #pragma unroll
                for (int mi = 0; mi < 2; mi++)
                    #pragma unroll
                    for (int h = 0; h < 2; h++) {
                        int lr = wm*32 + mi*16 + h*8 + qr;
                        #pragma unroll
                        for (int nj = 0; nj < 4; nj++) {
                            int colL = wn*32 + nj*8 + qc;
                            float h0 = c[mi][nj][2*h]   + b1e[nt*64 + colL];
                            float h1 = c[mi][nj][2*h+1] + b1e[nt*64 + colL + 1];
                            h0 = h0 * normcdff(h0);
                            h1 = h1 * normcdff(h1);
                            __nv_bfloat162 p;
                            p.x = __float2bfloat16_rn(h0);
                            p.y = __float2bfloat16_rn(h1);
                            *reinterpret_cast<__nv_bfloat162*>(
                                sPtr + 49152 + nt*16384 +
                                SMEM_SWZ((uint32_t)(lr*128 + colL*2))) = p;
                        }
                    }
            } else {
                // weighted scatter -> contrib buffers
                #pragma unroll
                for (int mi = 0; mi < 2; mi++)
                    #pragma unroll
                    for (int h = 0; h < 2; h++) {
                        int lr = wm*32 + mi*16 + h*8 + qr;
                        int tk = s_tok[lr];
                        if (tk >= 0) {
                            float w = s_wgt[lr];
                            float* dst = (s_rnk[lr] == 0) ? g_contrib0 : g_contrib1;
                            #pragma unroll
                            for (int nj = 0; nj < 4; nj++) {
                                int col = nt*64 + wn*32 + nj*8 + qc;
                                *reinterpret_cast<float2*>(dst + (size_t)tk*192 + col) =
                                    make_float2(w*(c[mi][nj][2*h]   + b2e[col]),
                                                w*(c[mi][nj][2*h+1] + b2e[col+1]));
                            }
                        }
                    }
            }
        }
        __syncthreads();
    }
}

// ---------------- prep: sine positional encoding + zero counters ------------
__global__ void k_pos() {
    int c = threadIdx.x;
    if (c < 8) g_cnt[c] = 0;
    const float TWO_PI = 6.283185307179586f;
    const float denom = 8.0f + 1e-6f;
    int f = (c < 96) ? c : c - 96;
    float expo = (float)(f & ~1) / 96.0f;
    float dt = powf(10000.0f, expo);
    for (int n = 0; n < 64; n++) {
        int i = n >> 3, j = n & 7;
        float base = (c < 96) ? (float)(i + 1) : (float)(j + 1);
        float v = base / denom * TWO_PI / dt;
        g_pos[n*192 + c] = (f & 1) ? cosf(v) : sinf(v);
    }
}

// ---------------- prep: rel-pos bias table [h][m_key][n_query] ---------------
__global__ void k_bias(const float* __restrict__ rpb) {
    int m = blockIdx.x, n = threadIdx.x;
    int dn = n >> 6, hn = (n >> 3) & 7, wn = n & 7;
    int dm = m >> 6, hm = (m >> 3) & 7, wm = m & 7;
    int rp = (dn - dm + 1)*225 + (hn - hm + 7)*15 + (wn - wm + 7);
    #pragma unroll
    for (int h = 0; h < 8; h++)
        g_biasf[h*16384 + m*128 + n] = rpb[rp*8 + h];
}

// ------------- prep: coalesced tiled weight transpose -> bf16 [N][K] ---------
__global__ __launch_bounds__(256) void k_transpose_t(
        const float* __restrict__ qs, const float* __restrict__ qm,
        const float* __restrict__ pw, const float* __restrict__ W1,
        const float* __restrict__ W2) {
    __shared__ float tile[64][65];
    int bid = blockIdx.x;
    const float* src; __nv_bfloat16* dst; int K, N, tk, tn;
    if (bid < 27)       { src = qs; dst = g_wt_qs; K = 192; N = 576; tk = bid/9; tn = bid%9; }
    else if (bid < 54)  { int j = bid-27; src = qm; dst = g_wt_qm; K = 192; N = 576; tk = j/9; tn = j%9; }
    else if (bid < 72)  { int j = bid-54; src = pw; dst = g_wt_p;  K = 384; N = 192; tk = j/3; tn = j%3; }
    else if (bid < 216) { int j = bid-72;  int e = j/18; j %= 18;
                          src = W1 + (size_t)e*73728; dst = g_wt_w1 + (size_t)e*73728;
                          K = 192; N = 384; tk = j/6; tn = j%6; }
    else                { int j = bid-216; int e = j/18; j %= 18;
                          src = W2 + (size_t)e*73728; dst = g_wt_w2 + (size_t)e*73728;
                          K = 384; N = 192; tk = j/3; tn = j%3; }
    int rr = threadIdx.x >> 6, cc = threadIdx.x & 63;
    #pragma unroll 4
    for (int i = 0; i < 16; i++) {
        int r = rr + 4*i;
        tile[r][cc] = src[(size_t)(tk*64 + r)*N + tn*64 + cc];
    }
    __syncthreads();
    #pragma unroll 4
    for (int i = 0; i < 16; i++) {
        int r = rr + 4*i;
        dst[(size_t)(tn*64 + r)*K + tk*64 + cc] = __float2bfloat16_rn(tile[cc][r]);
    }
}

// ---------------- LN1 + roll + window partition -> bf16 (warp per token) -----
__global__ __launch_bounds__(256) void ln_partition(const float* __restrict__ x,
                             const float* __restrict__ w1,
                             const float* __restrict__ b1) {
    int t = (blockIdx.x*blockDim.x + threadIdx.x) >> 5;
    int lane = threadIdx.x & 31;
    int win = t >> 7, n = t & 127;
    int b_  = win / 192; int rem = win % 192;
    int dd  = rem / 64;  int rem2 = rem % 64;
    int hh  = rem2 >> 3; int ww = rem2 & 7;
    int wd  = n >> 6, wh = (n >> 3) & 7, wwp = n & 7;
    int ds = dd*2 + wd, hs = hh*8 + wh, ws = ww*8 + wwp;
    int d = ds + 1; if (d >= 6) d -= 6;
    int h = (hs + 4) & 63;
    int w = (ws + 4) & 63;
    const float* xr = x + (size_t)(((b_*6 + d)*64 + h)*64 + w)*192;
    float v[6];
    float s1 = 0.f, s2 = 0.f;
    #pragma unroll
    for (int k = 0; k < 6; k++) {
        v[k] = xr[lane + 32*k];
        s1 += v[k]; s2 += v[k]*v[k];
    }
    s1 = warpsum_all(s1); s2 = warpsum_all(s2);
    float mu  = s1 * (1.f/192.f);
    float var = s2 * (1.f/192.f) - mu*mu;
    float rstd = rsqrtf(var + 1e-5f);
    const float* pr = g_pos + (n & 63)*192;
    #pragma unroll
    for (int k = 0; k < 6; k++) {
        int cc = lane + 32*k;
        float y = (v[k] - mu) * rstd * w1[cc] + b1[cc];
        g_xw_bf[(size_t)t*192 + cc] = __float2bfloat16_rn(y);
        g_xm_bf[(size_t)t*192 + cc] = __float2bfloat16_rn(y + pr[cc]);
    }
}

// ---------------- self attention: flash-style, LDS.128 + f32x2 ---------------
#define KVS 28   // padded row stride (floats): 112B, 16B-aligned rows
__global__ __launch_bounds__(128) void attn_self(const float* __restrict__ mask) {
    __shared__ __align__(16) float ks[128*KVS];
    __shared__ __align__(16) float vs[128*KVS];
    int win = blockIdx.x >> 3, h = blockIdx.x & 7;
    int n = threadIdx.x;
    size_t base = (size_t)(win*128 + n)*576 + h*24;
    const float4* qp = reinterpret_cast<const float4*>(g_qkv + base);
    const float4* kp = reinterpret_cast<const float4*>(g_qkv + base + 192);
    const float4* vp = reinterpret_cast<const float4*>(g_qkv + base + 384);
    const float SC = 0.20412414523193154f;   // 24^-0.5
    ull q2[12];
    #pragma unroll
    for (int i = 0; i < 6; i++) {
        float4 a = qp[i];
        q2[2*i]   = pack2(a.x*SC, a.y*SC);
        q2[2*i+1] = pack2(a.z*SC, a.w*SC);
        *reinterpret_cast<float4*>(&ks[n*KVS + 4*i]) = kp[i];
        *reinterpret_cast<float4*>(&vs[n*KVS + 4*i]) = vp[i];
    }
    __syncthreads();
    const float* mrow = mask + (size_t)(win % 192)*16384;
    const float* brow = g_biasf + (size_t)h*16384;
    ull o2[12] = {};
    float ssum = 0.f;
    #pragma unroll 2
    for (int m = 0; m < 128; m++) {
        const ulonglong2* kr = reinterpret_cast<const ulonglong2*>(ks + m*KVS);
        ull acc = 0ull;
        #pragma unroll
        for (int i = 0; i < 6; i++) {
            ulonglong2 t = kr[i];
            acc = fma2(q2[2*i], t.x, acc);
            acc = fma2(q2[2*i+1], t.y, acc);
        }
        float2 ac = unpack2(acc);
        float s = ac.x + ac.y + mrow[m*128 + n] + brow[m*128 + n];
        float p = __expf(s);
        ssum += p;
        ull pp = pack2(p, p);
        const ulonglong2* vr = reinterpret_cast<const ulonglong2*>(vs + m*KVS);
        #pragma unroll
        for (int i = 0; i < 6; i++) {
            ulonglong2 t = vr[i];
            o2[2*i]   = fma2(t.x, pp, o2[2*i]);
            o2[2*i+1] = fma2(t.y, pp, o2[2*i+1]);
        }
    }
    float inv = 1.f / ssum;
    __nv_bfloat162* ob = reinterpret_cast<__nv_bfloat162*>(
        g_xout_bf + (size_t)(win*128 + n)*384 + 192 + h*24);
    #pragma unroll
    for (int i = 0; i < 12; i++) {
        float2 o = unpack2(o2[i]);
        __nv_bfloat162 p;
        p.x = __float2bfloat16_rn(o.x*inv);
        p.y = __float2bfloat16_rn(o.y*inv);
        ob[i] = p;
    }
}

// ---------------- mutual attention: flash-style, LDS.128 + f32x2 -------------
__global__ __launch_bounds__(128) void attn_mut(const float* __restrict__ mask) {
    __shared__ __align__(16) float ks[2][64*KVS];
    __shared__ __align__(16) float vs[2][64*KVS];
    int win = blockIdx.x >> 3, h = blockIdx.x & 7;
    int tid = threadIdx.x;
    int p = tid >> 6, r = tid & 63;
    int kvtok = (p == 0) ? r : 64 + r;
    int qtok  = (p == 0) ? 64 + r : r;
    size_t kb = (size_t)(win*128 + kvtok)*576 + h*24;
    size_t qb = (size_t)(win*128 + qtok)*576 + h*24;
    const float4* qp = reinterpret_cast<const float4*>(g_qkv + qb);
    const float4* kp = reinterpret_cast<const float4*>(g_qkv + kb + 192);
    const float4* vp = reinterpret_cast<const float4*>(g_qkv + kb + 384);
    const float SC = 0.20412414523193154f;
    ull q2[12];
    #pragma unroll
    for (int i = 0; i < 6; i++) {
        float4 a = qp[i];
        q2[2*i]   = pack2(a.x*SC, a.y*SC);
        q2[2*i+1] = pack2(a.z*SC, a.w*SC);
        *reinterpret_cast<float4*>(&ks[p][r*KVS + 4*i]) = kp[i];
        *reinterpret_cast<float4*>(&vs[p][r*KVS + 4*i]) = vp[i];
    }
    __syncthreads();
    const float* mrow = mask + (size_t)(win % 192)*16384;
    ull o2[12] = {};
    float ssum = 0.f;
    #pragma unroll 2
    for (int m = 0; m < 64; m++) {
        const ulonglong2* kr = reinterpret_cast<const ulonglong2*>(&ks[p][m*KVS]);
        ull acc = 0ull;
        #pragma unroll
        for (int i = 0; i < 6; i++) {
            ulonglong2 t = kr[i];
            acc = fma2(q2[2*i], t.x, acc);
            acc = fma2(q2[2*i+1], t.y, acc);
        }
        float2 ac = unpack2(acc);
        float s = ac.x + ac.y + mrow[m*128 + r];   // mask symmetric
        float pv = __expf(s);
        ssum += pv;
        ull pp = pack2(pv, pv);
        const ulonglong2* vr = reinterpret_cast<const ulonglong2*>(&vs[p][m*KVS]);
        #pragma unroll
        for (int i = 0; i < 6; i++) {
            ulonglong2 t = vr[i];
            o2[2*i]   = fma2(t.x, pp, o2[2*i]);
            o2[2*i+1] = fma2(t.y, pp, o2[2*i+1]);
        }
    }
    float inv = 1.f / ssum;
    int orow = (p == 0) ? r : 64 + r;
    __nv_bfloat162* ob = reinterpret_cast<__nv_bfloat162*>(
        g_xout_bf + (size_t)(win*128 + orow)*384 + h*24);
    #pragma unroll
    for (int i = 0; i < 12; i++) {
        float2 o = unpack2(o2[i]);
        __nv_bfloat162 pr;
        pr.x = __float2bfloat16_rn(o.x*inv);
        pr.y = __float2bfloat16_rn(o.y*inv);
        ob[i] = pr;
    }
}

// --------- residual scatter + LN2 + gate top-2 (warp per token) --------------
__global__ __launch_bounds__(256) void resid_gate(const float* __restrict__ x,
                           const float* __restrict__ n2w, const float* __restrict__ n2b,
                           const float* __restrict__ gw,  const float* __restrict__ gb) {
    __shared__ float s_gw[8*192];
    for (int i = threadIdx.x; i < 1536; i += 256) {
        int j = i / 192, cc = i % 192;
        s_gw[i] = gw[cc*8 + j];
    }
    __syncthreads();
    int t = (blockIdx.x*blockDim.x + threadIdx.x) >> 5;
    int lane = threadIdx.x & 31;
    int b_ = t / 24576; int rrem = t % 24576;
    int d  = rrem / 4096; int r2 = rrem % 4096;
    int hh_ = r2 / 64; int ww_ = r2 % 64;
    int ds = d - 1; if (ds < 0) ds += 6;
    int hs = (hh_ + 60) & 63;
    int ws = (ww_ + 60) & 63;
    int dd = ds >> 1, wd = ds & 1;
    int hblk = hs >> 3, wh = hs & 7;
    int wblk = ws >> 3, wwp = ws & 7;
    int win = ((b_*3 + dd)*8 + hblk)*8 + wblk;
    int n = wd*64 + wh*8 + wwp;
    const float* ar = g_attnbuf + (size_t)(win*128 + n)*192;
    const float* xr = x + (size_t)t*192;
    float v[6];
    float s1 = 0.f, s2 = 0.f;
    #pragma unroll
    for (int k = 0; k < 6; k++) {
        int cc = lane + 32*k;
        v[k] = xr[cc] + ar[cc];
        g_xres[(size_t)t*192 + cc] = v[k];
        s1 += v[k]; s2 += v[k]*v[k];
    }
    s1 = warpsum_all(s1); s2 = warpsum_all(s2);
    float mu  = s1 * (1.f/192.f);
    float var = s2 * (1.f/192.f) - mu*mu;
    float rstd = rsqrtf(var + 1e-5f);
    float g[8] = {};
    #pragma unroll
    for (int k = 0; k < 6; k++) {
        int cc = lane + 32*k;
        float xn = (v[k] - mu) * rstd * n2w[cc] + n2b[cc];
        g_xn2_bf[(size_t)t*192 + cc] = __float2bfloat16_rn(xn);
        #pragma unroll
        for (int j = 0; j < 8; j++) g[j] = fmaf(xn, s_gw[j*192 + cc], g[j]);
    }
    #pragma unroll
    for (int j = 0; j < 8; j++) g[j] = warpsum_all(g[j]);
    if (lane == 0) {
        float L[8];
        #pragma unroll
        for (int j = 0; j < 8; j++) L[j] = g[j] + gb[j];
        int e0 = 0;
        #pragma unroll
        for (int j = 1; j < 8; j++) if (L[j] > L[e0]) e0 = j;
        int e1 = (e0 == 0) ? 1 : 0;
        #pragma unroll
        for (int j = 0; j < 8; j++) if (j != e0 && L[j] > L[e1]) e1 = j;
        float w0 = 1.f / (1.f + __expf(L[e1] - L[e0]));
        float w1 = 1.f - w0;
        int p0 = atomicAdd(&g_cnt[e0], 1);
        g_gidx[e0*TTOK + p0] = t; g_gw[e0*TTOK + p0] = w0; g_grank[e0*TTOK + p0] = 0;
        int p1 = atomicAdd(&g_cnt[e1], 1);
        g_gidx[e1*TTOK + p1] = t; g_gw[e1*TTOK + p1] = w1; g_grank[e1*TTOK + p1] = 1;
    }
}

// ---------------- finalize ----------------------------------------------------
__global__ void finalize(float* __restrict__ out) {
    int i = blockIdx.x*blockDim.x + threadIdx.x;
    if (i < TTOK*48) {
        float4 a  = reinterpret_cast<const float4*>(g_xres)[i];
        float4 c0 = reinterpret_cast<const float4*>(g_contrib0)[i];
        float4 c1 = reinterpret_cast<const float4*>(g_contrib1)[i];
        reinterpret_cast<float4*>(out)[i] =
            make_float4(a.x + c0.x + c1.x, a.y + c0.y + c1.y,
                        a.z + c0.z + c1.z, a.w + c0.w + c1.w);
    }
}

// ---------------- host launcher -----------------------------------------------
extern "C" void kernel_launch(void* const* d_in, const int* in_sizes, int n_in,
                              void* d_out, int out_size) {
    const float* x    = (const float*)d_in[0];
    const float* mask = (const float*)d_in[1];
    const float* n1w  = (const float*)d_in[2];
    const float* n1b  = (const float*)d_in[3];
    const float* qsw  = (const float*)d_in[4];
    const float* qsb  = (const float*)d_in[5];
    const float* qmw  = (const float*)d_in[6];
    const float* qmb  = (const float*)d_in[7];
    const float* rpb  = (const float*)d_in[8];
    const float* pw   = (const float*)d_in[9];
    const float* pb   = (const float*)d_in[10];
    const float* n2w  = (const float*)d_in[11];
    const float* n2b  = (const float*)d_in[12];
    const float* gw   = (const float*)d_in[13];
    const float* gb   = (const float*)d_in[14];
    const float* W1   = (const float*)d_in[15];
    const float* b1   = (const float*)d_in[16];
    const float* W2   = (const float*)d_in[17];
    const float* b2   = (const float*)d_in[18];
    float* out = (float*)d_out;

    const int DSMEM = 50176;
    const int MSMEM = 164864;   // A 48KB + H 96KB + W 16KB + 1KB align pad
    cudaFuncSetAttribute(gemm_mma,  cudaFuncAttributeMaxDynamicSharedMemorySize, DSMEM);
    cudaFuncSetAttribute(moe_fused, cudaFuncAttributeMaxDynamicSharedMemorySize, MSMEM);

    void *p_xw, *p_xm, *p_xout, *p_qkv, *p_attn;
    void *p_wqs, *p_wqm, *p_wp;
    cudaGetSymbolAddress(&p_xw,  g_xw_bf);
    cudaGetSymbolAddress(&p_xm,  g_xm_bf);
    cudaGetSymbolAddress(&p_xout,g_xout_bf);
    cudaGetSymbolAddress(&p_qkv, g_qkv);
    cudaGetSymbolAddress(&p_attn,g_attnbuf);
    cudaGetSymbolAddress(&p_wqs, g_wt_qs);
    cudaGetSymbolAddress(&p_wqm, g_wt_qm);
    cudaGetSymbolAddress(&p_wp,  g_wt_p);

    k_pos<<<1, 192>>>();
    k_bias<<<128, 128>>>(rpb);
    k_transpose_t<<<360, 256>>>(qsw, qmw, pw, W1, W2);
    ln_partition<<<6144, 256>>>(x, n1w, n1b);
    gemm_mma<<<dim3(384, 9), 256, DSMEM>>>((const __nv_bfloat16*)p_xw,
        (const __nv_bfloat16*)p_wqs, qsb, (float*)p_qkv, 192, 576);
    attn_self<<<NWIN*8, 128>>>(mask);
    gemm_mma<<<dim3(384, 9), 256, DSMEM>>>((const __nv_bfloat16*)p_xm,
        (const __nv_bfloat16*)p_wqm, qmb, (float*)p_qkv, 192, 576);
    attn_mut<<<NWIN*8, 128>>>(mask);
    gemm_mma<<<dim3(384, 3), 256, DSMEM>>>((const __nv_bfloat16*)p_xout,
        (const __nv_bfloat16*)p_wp, pb, (float*)p_attn, 384, 192);
    resid_gate<<<6144, 256>>>(x, n2w, n2b, gw, gb);
    moe_fused<<<dim3(384, 8), 256, MSMEM>>>(b1, b2);
    finalize<<<9216, 256>>>(out);
}

// round 7
// speedup vs baseline: 1.1003x; 1.1003x over previous
#include <cuda_runtime.h>
#include <cuda_bf16.h>
#include <math.h>
#include <cstdint>

#define TTOK 49152      // total tokens = 2*6*64*64
#define NWIN 384

// ---------------- scratch (device globals; no allocations allowed) ----------
__device__ float g_qkv_s[TTOK*576];     // qkv fp32 (self)
__device__ float g_qkv_m[TTOK*576];     // qkv fp32 (mutual)
__device__ float g_attnbuf[TTOK*192];   // proj output (window order)
__device__ float g_xres[TTOK*192];      // x + attn residual (original order)
__device__ float g_pos[64*192];
__device__ float g_biasf[8*128*128];    // rel-pos bias per head [h][m_key][n_query]
__device__ int   g_cnt[8];
__device__ int   g_gidx[8*TTOK];
__device__ float g_gw[8*TTOK];
__device__ int   g_grank[8*TTOK];
__device__ float g_contrib0[TTOK*192];
__device__ float g_contrib1[TTOK*192];
// bf16 activation buffers for tensor-core GEMMs
__device__ __nv_bfloat16 g_xw_bf[TTOK*192];
__device__ __nv_bfloat16 g_xm_bf[TTOK*192];
__device__ __nv_bfloat16 g_xout_bf[TTOK*384];
__device__ __nv_bfloat16 g_xn2_bf[TTOK*192];
__device__ __nv_bfloat16 g_hbuf[(size_t)8*TTOK*384];
// transposed bf16 weights [N][K]
__device__ __nv_bfloat16 g_wt_qs[576*192];
__device__ __nv_bfloat16 g_wt_qm[576*192];
__device__ __nv_bfloat16 g_wt_p [192*384];
__device__ __nv_bfloat16 g_wt_w1[8*384*192];
__device__ __nv_bfloat16 g_wt_w2[8*192*384];

// ---------------- helpers ------------------------------------------------
typedef unsigned long long ull;
__device__ __forceinline__ float warpsum_all(float v) {
    #pragma unroll
    for (int o = 16; o; o >>= 1) v += __shfl_xor_sync(0xffffffffu, v, o);
    return v;
}
__device__ __forceinline__ uint32_t smem_u32(const void* p) {
    uint32_t a;
    asm("{ .reg .u64 t; cvta.to.shared.u64 t, %1; cvt.u32.u64 %0, t; }" : "=r"(a) : "l"(p));
    return a;
}
__device__ __forceinline__ void ldsm_x4(uint32_t& r0, uint32_t& r1, uint32_t& r2,
                                        uint32_t& r3, uint32_t addr) {
    asm volatile("ldmatrix.sync.aligned.m8n8.x4.shared.b16 {%0,%1,%2,%3}, [%4];"
                 : "=r"(r0), "=r"(r1), "=r"(r2), "=r"(r3) : "r"(addr));
}
__device__ __forceinline__ void mma16816(float* c, uint32_t a0, uint32_t a1,
                                         uint32_t a2, uint32_t a3,
                                         uint32_t b0, uint32_t b1) {
    asm volatile("mma.sync.aligned.m16n8k16.row.col.f32.bf16.bf16.f32 "
        "{%0,%1,%2,%3}, {%4,%5,%6,%7}, {%8,%9}, {%0,%1,%2,%3};"
        : "+f"(c[0]), "+f"(c[1]), "+f"(c[2]), "+f"(c[3])
        : "r"(a0), "r"(a1), "r"(a2), "r"(a3), "r"(b0), "r"(b1));
}
__device__ __forceinline__ void cp16(uint32_t dst, const void* src, bool v) {
    asm volatile("cp.async.cg.shared.global [%0], [%1], 16, %2;"
                 :: "r"(dst), "l"(src), "r"(v ? 16u : 0u));
}
#define CP_COMMIT() asm volatile("cp.async.commit_group;")
#define CP_WAIT1()  asm volatile("cp.async.wait_group 1;")
#define CP_WAIT0()  asm volatile("cp.async.wait_group 0;")
#define SMEM_SWZ(o) ((o) ^ (((o) >> 3) & 0x70))

// ---- packed f32x2 ops (Blackwell FFMA2) ----
__device__ __forceinline__ ull fma2(ull a, ull b, ull c) {
    ull d;
    asm("fma.rn.f32x2 %0, %1, %2, %3;" : "=l"(d) : "l"(a), "l"(b), "l"(c));
    return d;
}
__device__ __forceinline__ ull pack2(float x, float y) {
    ull r;
    asm("mov.b64 %0, {%1,%2};" : "=l"(r) : "f"(x), "f"(y));
    return r;
}
__device__ __forceinline__ float2 unpack2(ull v) {
    float x, y;
    asm("mov.b64 {%0,%1}, %2;" : "=f"(x), "=f"(y) : "l"(v));
    return make_float2(x, y);
}

// ---- shared 128x64 warp-tile MMA over one 64-K chunk (8 warps: 4m x 2n) ----
__device__ __forceinline__ void mma_tile(uint32_t aB, uint32_t bB,
                                         float (&c)[2][4][4], int wm, int wn, int lane) {
    int g = lane >> 3, l7 = lane & 7;
    #pragma unroll
    for (int ks = 0; ks < 4; ks++) {
        uint32_t a[2][4];
        #pragma unroll
        for (int mi = 0; mi < 2; mi++) {
            int r = wm*32 + mi*16 + ((g & 1) << 3) + l7;
            int kb = ks*32 + ((g >> 1) << 4);
            ldsm_x4(a[mi][0], a[mi][1], a[mi][2], a[mi][3],
                    aB + SMEM_SWZ((uint32_t)(r*128 + kb)));
        }
        uint32_t b[4][2];
        #pragma unroll
        for (int np = 0; np < 2; np++) {
            int r = wn*32 + np*16 + ((g >> 1) << 3) + l7;
            int kb = ks*32 + ((g & 1) << 4);
            uint32_t r0, r1, r2, r3;
            ldsm_x4(r0, r1, r2, r3, bB + SMEM_SWZ((uint32_t)(r*128 + kb)));
            b[np*2][0] = r0;   b[np*2][1] = r1;
            b[np*2+1][0] = r2; b[np*2+1][1] = r3;
        }
        #pragma unroll
        for (int mi = 0; mi < 2; mi++)
            #pragma unroll
            for (int nj = 0; nj < 4; nj++)
                mma16816(c[mi][nj], a[mi][0], a[mi][1], a[mi][2], a[mi][3],
                         b[nj][0], b[nj][1]);
    }
}

// ---- shared mode-0 GEMM core: C fp32 = A @ Bt^T + bias ---------------------
__device__ __forceinline__ void gemm_core0(
        const __nv_bfloat16* __restrict__ A,
        const __nv_bfloat16* __restrict__ Bt,
        const float* __restrict__ bias,
        float* __restrict__ Cf, int K, int ldC, uint8_t* dyn_raw) {
    int tid = threadIdx.x, wid = tid >> 5, lane = tid & 31;
    int wm = wid >> 1, wn = wid & 1;
    int row0 = blockIdx.x * 128, col0 = blockIdx.y * 64;

    uint32_t aBase = (smem_u32(dyn_raw) + 1023u) & ~1023u;
    uint32_t bBase = aBase + 32768;

    int srow = tid >> 3, c16 = tid & 7;
    const __nv_bfloat16* arp[4]; uint32_t aOff[4];
    #pragma unroll
    for (int i = 0; i < 4; i++) {
        int r = i*32 + srow;
        aOff[i] = SMEM_SWZ((uint32_t)(r*128 + c16*16));
        arp[i] = A + (size_t)(row0 + r)*K + c16*8;
    }
    const __nv_bfloat16* brp[2]; uint32_t bOff[2];
    #pragma unroll
    for (int i = 0; i < 2; i++) {
        int r = i*32 + srow;
        bOff[i] = SMEM_SWZ((uint32_t)(r*128 + c16*16));
        brp[i] = Bt + (size_t)(col0 + r)*K + c16*8;
    }

    float c[2][4][4] = {};
    int nch = K >> 6;

    #pragma unroll
    for (int i = 0; i < 4; i++) cp16(aBase + aOff[i], arp[i], true);
    #pragma unroll
    for (int i = 0; i < 2; i++) cp16(bBase + bOff[i], brp[i], true);
    CP_COMMIT();

    for (int ic = 0; ic < nch; ic++) {
        if (ic + 1 < nch) {
            int buf = (ic + 1) & 1, kc = (ic + 1) << 6;
            #pragma unroll
            for (int i = 0; i < 4; i++)
                cp16(aBase + buf*16384 + aOff[i], arp[i] + kc, true);
            #pragma unroll
            for (int i = 0; i < 2; i++)
                cp16(bBase + buf*8192 + bOff[i], brp[i] + kc, true);
            CP_COMMIT();
            CP_WAIT1();
        } else {
            CP_WAIT0();
        }
        __syncthreads();
        mma_tile(aBase + (ic & 1)*16384, bBase + (ic & 1)*8192, c, wm, wn, lane);
        __syncthreads();
    }

    int qr = lane >> 2, qc = (lane & 3) * 2;
    #pragma unroll
    for (int mi = 0; mi < 2; mi++) {
        #pragma unroll
        for (int h = 0; h < 2; h++) {
            int lr = wm*32 + mi*16 + h*8 + qr;
            #pragma unroll
            for (int nj = 0; nj < 4; nj++) {
                int col = col0 + wn*32 + nj*8 + qc;
                size_t crow = (size_t)(row0 + lr)*ldC + col;
                *reinterpret_cast<float2*>(Cf + crow) =
                    make_float2(c[mi][nj][2*h] + bias[col],
                                c[mi][nj][2*h+1] + bias[col+1]);
            }
        }
    }
}

// ---- merged QKV GEMM: z=0 self, z=1 mutual ----------------------------------
__global__ __launch_bounds__(256) void gemm_qkv(const float* __restrict__ qsb,
                                                const float* __restrict__ qmb) {
    extern __shared__ uint8_t dyn_raw[];
    if (blockIdx.z == 0)
        gemm_core0(g_xw_bf, g_wt_qs, qsb, g_qkv_s, 192, 576, dyn_raw);
    else
        gemm_core0(g_xm_bf, g_wt_qm, qmb, g_qkv_m, 192, 576, dyn_raw);
}

// ---- proj GEMM ---------------------------------------------------------------
__global__ __launch_bounds__(256) void gemm_proj(
        const __nv_bfloat16* __restrict__ A, const __nv_bfloat16* __restrict__ Bt,
        const float* __restrict__ bias, float* __restrict__ Cf, int K, int ldC) {
    extern __shared__ uint8_t dyn_raw[];
    gemm_core0(A, Bt, bias, Cf, K, ldC, dyn_raw);
}

// ================= MoE split GEMMs (round-5 proven form) ====================
// MODE 1: FC1 gather+gelu -> g_hbuf ; MODE 2: FC2 weighted scatter
template<int MODE>
__global__ __launch_bounds__(256) void gemm_moe(
        const __nv_bfloat16* __restrict__ A,
        const __nv_bfloat16* __restrict__ Bt,
        const float* __restrict__ bias, int K, int ldC) {
    extern __shared__ uint8_t dyn_raw[];
    __shared__ int s_tok[128]; __shared__ float s_wgt[128]; __shared__ int s_rnk[128];

    int tid = threadIdx.x, wid = tid >> 5, lane = tid & 31;
    int wm = wid >> 1, wn = wid & 1;
    int row0 = blockIdx.x * 128, col0 = blockIdx.y * 64;
    int e = blockIdx.z;
    int cnt = g_cnt[e];
    if (row0 >= cnt) return;
    const __nv_bfloat16* Bte = Bt + (size_t)e * ldC * K;
    const float* be = bias + (size_t)e * ldC;
    const __nv_bfloat16* Ae = (MODE == 2) ? (A + (size_t)e * TTOK * K) : A;

    if (tid < 128) {
        int slot = row0 + tid;
        if (slot < cnt) {
            s_tok[tid] = g_gidx[e*TTOK + slot];
            s_wgt[tid] = g_gw[e*TTOK + slot];
            s_rnk[tid] = g_grank[e*TTOK + slot];
        } else s_tok[tid] = -1;
    }
    __syncthreads();

    uint32_t aBase = (smem_u32(dyn_raw) + 1023u) & ~1023u;
    uint32_t bBase = aBase + 32768;

    int srow = tid >> 3, c16 = tid & 7;
    const __nv_bfloat16* arp[4]; bool av[4]; uint32_t aOff[4];
    #pragma unroll
    for (int i = 0; i < 4; i++) {
        int r = i*32 + srow;
        aOff[i] = SMEM_SWZ((uint32_t)(r*128 + c16*16));
        if (MODE == 1) {
            int tk = s_tok[r];
            av[i] = (tk >= 0);
            arp[i] = Ae + (size_t)(av[i] ? tk : 0)*K + c16*8;
        } else {
            av[i] = (row0 + r < cnt);
            arp[i] = Ae + (size_t)(av[i] ? (row0 + r) : 0)*K + c16*8;
        }
    }
    const __nv_bfloat16* brp[2]; uint32_t bOff[2];
    #pragma unroll
    for (int i = 0; i < 2; i++) {
        int r = i*32 + srow;
        bOff[i] = SMEM_SWZ((uint32_t)(r*128 + c16*16));
        brp[i] = Bte + (size_t)(col0 + r)*K + c16*8;
    }

    float c[2][4][4] = {};
    int nch = K >> 6;

    #pragma unroll
    for (int i = 0; i < 4; i++) cp16(aBase + aOff[i], arp[i], av[i]);
    #pragma unroll
    for (int i = 0; i < 2; i++) cp16(bBase + bOff[i], brp[i], true);
    CP_COMMIT();

    for (int ic = 0; ic < nch; ic++) {
        if (ic + 1 < nch) {
            int buf = (ic + 1) & 1, kc = (ic + 1) << 6;
            #pragma unroll
            for (int i = 0; i < 4; i++)
                cp16(aBase + buf*16384 + aOff[i], arp[i] + kc, av[i]);
            #pragma unroll
            for (int i = 0; i < 2; i++)
                cp16(bBase + buf*8192 + bOff[i], brp[i] + kc, true);
            CP_COMMIT();
            CP_WAIT1();
        } else {
            CP_WAIT0();
        }
        __syncthreads();
        mma_tile(aBase + (ic & 1)*16384, bBase + (ic & 1)*8192, c, wm, wn, lane);
        __syncthreads();
    }

    int qr = lane >> 2, qc = (lane & 3) * 2;
    #pragma unroll
    for (int mi = 0; mi < 2; mi++) {
        #pragma unroll
        for (int h = 0; h < 2; h++) {
            int lr = wm*32 + mi*16 + h*8 + qr;
            #pragma unroll
            for (int nj = 0; nj < 4; nj++) {
                int col = col0 + wn*32 + nj*8 + qc;
                float v0 = c[mi][nj][2*h + 0];
                float v1 = c[mi][nj][2*h + 1];
                if (MODE == 1) {
                    if (s_tok[lr] >= 0) {
                        float h0 = v0 + be[col], h1 = v1 + be[col+1];
                        h0 = h0 * normcdff(h0);
                        h1 = h1 * normcdff(h1);
                        __nv_bfloat162 p;
                        p.x = __float2bfloat16_rn(h0); p.y = __float2bfloat16_rn(h1);
                        *reinterpret_cast<__nv_bfloat162*>(
                            g_hbuf + ((size_t)e*TTOK + row0 + lr)*384 + col) = p;
                    }
                } else {
                    int tk = s_tok[lr];
                    if (tk >= 0) {
                        float w = s_wgt[lr];
                        float* dst = (s_rnk[lr] == 0) ? g_contrib0 : g_contrib1;
                        *reinterpret_cast<float2*>(dst + (size_t)tk*192 + col) =
                            make_float2(w*(v0 + be[col]), w*(v1 + be[col+1]));
                    }
                }
            }
        }
    }
}

// ---------------- prep: sine positional encoding + zero counters ------------
__global__ void k_pos() {
    int c = threadIdx.x;
    if (c < 8) g_cnt[c] = 0;
    const float TWO_PI = 6.283185307179586f;
    const float denom = 8.0f + 1e-6f;
    int f = (c < 96) ? c : c - 96;
    float expo = (float)(f & ~1) / 96.0f;
    float dt = powf(10000.0f, expo);
    for (int n = 0; n < 64; n++) {
        int i = n >> 3, j = n & 7;
        float base = (c < 96) ? (float)(i + 1) : (float)(j + 1);
        float v = base / denom * TWO_PI / dt;
        g_pos[n*192 + c] = (f & 1) ? cosf(v) : sinf(v);
    }
}

// ---------------- prep: rel-pos bias table [h][m_key][n_query] ---------------
__global__ void k_bias(const float* __restrict__ rpb) {
    int m = blockIdx.x, n = threadIdx.x;
    int dn = n >> 6, hn = (n >> 3) & 7, wn = n & 7;
    int dm = m >> 6, hm = (m >> 3) & 7, wm = m & 7;
    int rp = (dn - dm + 1)*225 + (hn - hm + 7)*15 + (wn - wm + 7);
    #pragma unroll
    for (int h = 0; h < 8; h++)
        g_biasf[h*16384 + m*128 + n] = rpb[rp*8 + h];
}

// ------------- prep: coalesced tiled weight transpose -> bf16 [N][K] ---------
__global__ __launch_bounds__(256) void k_transpose_t(
        const float* __restrict__ qs, const float* __restrict__ qm,
        const float* __restrict__ pw, const float* __restrict__ W1,
        const float* __restrict__ W2) {
    __shared__ float tile[64][65];
    int bid = blockIdx.x;
    const float* src; __nv_bfloat16* dst; int K, N, tk, tn;
    if (bid < 27)       { src = qs; dst = g_wt_qs; K = 192; N = 576; tk = bid/9; tn = bid%9; }
    else if (bid < 54)  { int j = bid-27; src = qm; dst = g_wt_qm; K = 192; N = 576; tk = j/9; tn = j%9; }
    else if (bid < 72)  { int j = bid-54; src = pw; dst = g_wt_p;  K = 384; N = 192; tk = j/3; tn = j%3; }
    else if (bid < 216) { int j = bid-72;  int e = j/18; j %= 18;
                          src = W1 + (size_t)e*73728; dst = g_wt_w1 + (size_t)e*73728;
                          K = 192; N = 384; tk = j/6; tn = j%6; }
    else                { int j = bid-216; int e = j/18; j %= 18;
                          src = W2 + (size_t)e*73728; dst = g_wt_w2 + (size_t)e*73728;
                          K = 384; N = 192; tk = j/3; tn = j%3; }
    int rr = threadIdx.x >> 6, cc = threadIdx.x & 63;
    #pragma unroll 4
    for (int i = 0; i < 16; i++) {
        int r = rr + 4*i;
        tile[r][cc] = src[(size_t)(tk*64 + r)*N + tn*64 + cc];
    }
    __syncthreads();
    #pragma unroll 4
    for (int i = 0; i < 16; i++) {
        int r = rr + 4*i;
        dst[(size_t)(tn*64 + r)*K + tk*64 + cc] = __float2bfloat16_rn(tile[cc][r]);
    }
}

// ---------------- LN1 + roll + window partition -> bf16 (warp per token) -----
__global__ __launch_bounds__(256) void ln_partition(const float* __restrict__ x,
                             const float* __restrict__ w1,
                             const float* __restrict__ b1) {
    int t = (blockIdx.x*blockDim.x + threadIdx.x) >> 5;
    int lane = threadIdx.x & 31;
    int win = t >> 7, n = t & 127;
    int b_  = win / 192; int rem = win % 192;
    int dd  = rem / 64;  int rem2 = rem % 64;
    int hh  = rem2 >> 3; int ww = rem2 & 7;
    int wd  = n >> 6, wh = (n >> 3) & 7, wwp = n & 7;
    int ds = dd*2 + wd, hs = hh*8 + wh, ws = ww*8 + wwp;
    int d = ds + 1; if (d >= 6) d -= 6;
    int h = (hs + 4) & 63;
    int w = (ws + 4) & 63;
    const float* xr = x + (size_t)(((b_*6 + d)*64 + h)*64 + w)*192;
    float v[6];
    float s1 = 0.f, s2 = 0.f;
    #pragma unroll
    for (int k = 0; k < 6; k++) {
        v[k] = xr[lane + 32*k];
        s1 += v[k]; s2 += v[k]*v[k];
    }
    s1 = warpsum_all(s1); s2 = warpsum_all(s2);
    float mu  = s1 * (1.f/192.f);
    float var = s2 * (1.f/192.f) - mu*mu;
    float rstd = rsqrtf(var + 1e-5f);
    const float* pr = g_pos + (n & 63)*192;
    #pragma unroll
    for (int k = 0; k < 6; k++) {
        int cc = lane + 32*k;
        float y = (v[k] - mu) * rstd * w1[cc] + b1[cc];
        g_xw_bf[(size_t)t*192 + cc] = __float2bfloat16_rn(y);
        g_xm_bf[(size_t)t*192 + cc] = __float2bfloat16_rn(y + pr[cc]);
    }
}

// ------ merged attention: blocks [0,3072) self, [3072,6144) mutual -----------
#define KVS 28   // padded row stride (floats): 112B, 16B-aligned rows
__global__ __launch_bounds__(128) void attn_both(const float* __restrict__ mask) {
    __shared__ __align__(16) float ks[128*KVS];
    __shared__ __align__(16) float vs[128*KVS];
    bool isSelf = blockIdx.x < 3072;
    int bx = isSelf ? blockIdx.x : (blockIdx.x - 3072);
    int win = bx >> 3, h = bx & 7;
    int n = threadIdx.x;
    int p = n >> 6, r = n & 63;
    const float* qkv = isSelf ? g_qkv_s : g_qkv_m;
    int qtok = isSelf ? n : (p == 0 ? 64 + r : r);
    size_t kvb = (size_t)(win*128 + n)*576 + h*24;      // K/V of token n -> row n
    const float4* qp = reinterpret_cast<const float4*>(
        qkv + (size_t)(win*128 + qtok)*576 + h*24);
    const float4* kp = reinterpret_cast<const float4*>(qkv + kvb + 192);
    const float4* vp = reinterpret_cast<const float4*>(qkv + kvb + 384);
    const float SC = 0.20412414523193154f;   // 24^-0.5
    ull q2[12];
    #pragma unroll
    for (int i = 0; i < 6; i++) {
        float4 a = qp[i];
        q2[2*i]   = pack2(a.x*SC, a.y*SC);
        q2[2*i+1] = pack2(a.z*SC, a.w*SC);
        *reinterpret_cast<float4*>(&ks[n*KVS + 4*i]) = kp[i];
        *reinterpret_cast<float4*>(&vs[n*KVS + 4*i]) = vp[i];
    }
    __syncthreads();
    const float* mrow = mask + (size_t)(win % 192)*16384;
    const float* brow = g_biasf + (size_t)h*16384;
    int mbase = isSelf ? 0 : p*64;
    int mcount = isSelf ? 128 : 64;
    ull o2[12] = {};
    float ssum = 0.f;
    #pragma unroll 2
    for (int m = 0; m < mcount; m++) {
        int row = mbase + m;
        const ulonglong2* kr = reinterpret_cast<const ulonglong2*>(ks + row*KVS);
        ull acc = 0ull;
        #pragma unroll
        for (int i = 0; i < 6; i++) {
            ulonglong2 t = kr[i];
            acc = fma2(q2[2*i], t.x, acc);
            acc = fma2(q2[2*i+1], t.y, acc);
        }
        float2 ac = unpack2(acc);
        float badd = isSelf ? (mrow[row*128 + n] + brow[row*128 + n])
                            : mrow[m*128 + r];   // mask symmetric, local idx
        float s = ac.x + ac.y + badd;
        float pv = __expf(s);
        ssum += pv;
        ull pp = pack2(pv, pv);
        const ulonglong2* vr = reinterpret_cast<const ulonglong2*>(vs + row*KVS);
        #pragma unroll
        for (int i = 0; i < 6; i++) {
            ulonglong2 t = vr[i];
            o2[2*i]   = fma2(t.x, pp, o2[2*i]);
            o2[2*i+1] = fma2(t.y, pp, o2[2*i+1]);
        }
    }
    float inv = 1.f / ssum;
    int orow = isSelf ? n : (p == 0 ? r : 64 + r);
    int coff = isSelf ? 192 : 0;
    __nv_bfloat162* ob = reinterpret_cast<__nv_bfloat162*>(
        g_xout_bf + (size_t)(win*128 + orow)*384 + coff + h*24);
    #pragma unroll
    for (int i = 0; i < 12; i++) {
        float2 o = unpack2(o2[i]);
        __nv_bfloat162 pr;
        pr.x = __float2bfloat16_rn(o.x*inv);
        pr.y = __float2bfloat16_rn(o.y*inv);
        ob[i] = pr;
    }
}

// --------- residual scatter + LN2 + gate top-2 (warp per token) --------------
__global__ __launch_bounds__(256) void resid_gate(const float* __restrict__ x,
                           const float* __restrict__ n2w, const float* __restrict__ n2b,
                           const float* __restrict__ gw,  const float* __restrict__ gb) {
    __shared__ float s_gw[8*192];
    for (int i = threadIdx.x; i < 1536; i += 256) {
        int j = i / 192, cc = i % 192;
        s_gw[i] = gw[cc*8 + j];
    }
    __syncthreads();
    int t = (blockIdx.x*blockDim.x + threadIdx.x) >> 5;
    int lane = threadIdx.x & 31;
    int b_ = t / 24576; int rrem = t % 24576;
    int d  = rrem / 4096; int r2 = rrem % 4096;
    int hh_ = r2 / 64; int ww_ = r2 % 64;
    int ds = d - 1; if (ds < 0) ds += 6;
    int hs = (hh_ + 60) & 63;
    int ws = (ww_ + 60) & 63;
    int dd = ds >> 1, wd = ds & 1;
    int hblk = hs >> 3, wh = hs & 7;
    int wblk = ws >> 3, wwp = ws & 7;
    int win = ((b_*3 + dd)*8 + hblk)*8 + wblk;
    int n = wd*64 + wh*8 + wwp;
    const float* ar = g_attnbuf + (size_t)(win*128 + n)*192;
    const float* xr = x + (size_t)t*192;
    float v[6];
    float s1 = 0.f, s2 = 0.f;
    #pragma unroll
    for (int k = 0; k < 6; k++) {
        int cc = lane + 32*k;
        v[k] = xr[cc] + ar[cc];
        g_xres[(size_t)t*192 + cc] = v[k];
        s1 += v[k]; s2 += v[k]*v[k];
    }
    s1 = warpsum_all(s1); s2 = warpsum_all(s2);
    float mu  = s1 * (1.f/192.f);
    float var = s2 * (1.f/192.f) - mu*mu;
    float rstd = rsqrtf(var + 1e-5f);
    float g[8] = {};
    #pragma unroll
    for (int k = 0; k < 6; k++) {
        int cc = lane + 32*k;
        float xn = (v[k] - mu) * rstd * n2w[cc] + n2b[cc];
        g_xn2_bf[(size_t)t*192 + cc] = __float2bfloat16_rn(xn);
        #pragma unroll
        for (int j = 0; j < 8; j++) g[j] = fmaf(xn, s_gw[j*192 + cc], g[j]);
    }
    #pragma unroll
    for (int j = 0; j < 8; j++) g[j] = warpsum_all(g[j]);
    if (lane == 0) {
        float L[8];
        #pragma unroll
        for (int j = 0; j < 8; j++) L[j] = g[j] + gb[j];
        int e0 = 0;
        #pragma unroll
        for (int j = 1; j < 8; j++) if (L[j] > L[e0]) e0 = j;
        int e1 = (e0 == 0) ? 1 : 0;
        #pragma unroll
        for (int j = 0; j < 8; j++) if (j != e0 && L[j] > L[e1]) e1 = j;
        float w0 = 1.f / (1.f + __expf(L[e1] - L[e0]));
        float w1 = 1.f - w0;
        int p0 = atomicAdd(&g_cnt[e0], 1);
        g_gidx[e0*TTOK + p0] = t; g_gw[e0*TTOK + p0] = w0; g_grank[e0*TTOK + p0] = 0;
        int p1 = atomicAdd(&g_cnt[e1], 1);
        g_gidx[e1*TTOK + p1] = t; g_gw[e1*TTOK + p1] = w1; g_grank[e1*TTOK + p1] = 1;
    }
}

// ---------------- finalize ----------------------------------------------------
__global__ void finalize(float* __restrict__ out) {
    int i = blockIdx.x*blockDim.x + threadIdx.x;
    if (i < TTOK*48) {
        float4 a  = reinterpret_cast<const float4*>(g_xres)[i];
        float4 c0 = reinterpret_cast<const float4*>(g_contrib0)[i];
        float4 c1 = reinterpret_cast<const float4*>(g_contrib1)[i];
        reinterpret_cast<float4*>(out)[i] =
            make_float4(a.x + c0.x + c1.x, a.y + c0.y + c1.y,
                        a.z + c0.z + c1.z, a.w + c0.w + c1.w);
    }
}

// ---------------- host launcher -----------------------------------------------
extern "C" void kernel_launch(void* const* d_in, const int* in_sizes, int n_in,
                              void* d_out, int out_size) {
    const float* x    = (const float*)d_in[0];
    const float* mask = (const float*)d_in[1];
    const float* n1w  = (const float*)d_in[2];
    const float* n1b  = (const float*)d_in[3];
    const float* qsw  = (const float*)d_in[4];
    const float* qsb  = (const float*)d_in[5];
    const float* qmw  = (const float*)d_in[6];
    const float* qmb  = (const float*)d_in[7];
    const float* rpb  = (const float*)d_in[8];
    const float* pw   = (const float*)d_in[9];
    const float* pb   = (const float*)d_in[10];
    const float* n2w  = (const float*)d_in[11];
    const float* n2b  = (const float*)d_in[12];
    const float* gw   = (const float*)d_in[13];
    const float* gb   = (const float*)d_in[14];
    const float* W1   = (const float*)d_in[15];
    const float* b1   = (const float*)d_in[16];
    const float* W2   = (const float*)d_in[17];
    const float* b2   = (const float*)d_in[18];
    float* out = (float*)d_out;

    const int DSMEM = 50176;
    cudaFuncSetAttribute(gemm_qkv,    cudaFuncAttributeMaxDynamicSharedMemorySize, DSMEM);
    cudaFuncSetAttribute(gemm_proj,   cudaFuncAttributeMaxDynamicSharedMemorySize, DSMEM);
    cudaFuncSetAttribute(gemm_moe<1>, cudaFuncAttributeMaxDynamicSharedMemorySize, DSMEM);
    cudaFuncSetAttribute(gemm_moe<2>, cudaFuncAttributeMaxDynamicSharedMemorySize, DSMEM);

    void *p_xout, *p_attn, *p_xn2, *p_h, *p_wp, *p_w1, *p_w2;
    cudaGetSymbolAddress(&p_xout, g_xout_bf);
    cudaGetSymbolAddress(&p_attn, g_attnbuf);
    cudaGetSymbolAddress(&p_xn2,  g_xn2_bf);
    cudaGetSymbolAddress(&p_h,    g_hbuf);
    cudaGetSymbolAddress(&p_wp,   g_wt_p);
    cudaGetSymbolAddress(&p_w1,   g_wt_w1);
    cudaGetSymbolAddress(&p_w2,   g_wt_w2);

    k_pos<<<1, 192>>>();
    k_bias<<<128, 128>>>(rpb);
    k_transpose_t<<<360, 256>>>(qsw, qmw, pw, W1, W2);
    ln_partition<<<6144, 256>>>(x, n1w, n1b);
    gemm_qkv<<<dim3(384, 9, 2), 256, DSMEM>>>(qsb, qmb);
    attn_both<<<6144, 128>>>(mask);
    gemm_proj<<<dim3(384, 3), 256, DSMEM>>>((const __nv_bfloat16*)p_xout,
        (const __nv_bfloat16*)p_wp, pb, (float*)p_attn, 384, 192);
    resid_gate<<<6144, 256>>>(x, n2w, n2b, gw, gb);
    gemm_moe<1><<<dim3(384, 6, 8), 256, DSMEM>>>((const __nv_bfloat16*)p_xn2,
        (const __nv_bfloat16*)p_w1, b1, 192, 384);
    gemm_moe<2><<<dim3(384, 3, 8), 256, DSMEM>>>((const __nv_bfloat16*)p_h,
        (const __nv_bfloat16*)p_w2, b2, 384, 192);
    finalize<<<9216, 256>>>(out);
}

// round 8
// speedup vs baseline: 1.1343x; 1.0309x over previous
#include <cuda_runtime.h>
#include <cuda_bf16.h>
#include <math.h>
#include <cstdint>

#define TTOK 49152      // total tokens = 2*6*64*64
#define NWIN 384

// ---------------- scratch (device globals; no allocations allowed) ----------
__device__ float g_qkv_s[TTOK*576];     // qkv fp32 (self)
__device__ float g_qkv_m[TTOK*576];     // qkv fp32 (mutual)
__device__ float g_attnbuf[TTOK*192];   // proj output (window order)
__device__ float g_xres[TTOK*192];      // x + attn residual (original order)
__device__ float g_pos[64*192];
__device__ float g_biasf[8*128*128];    // rel-pos bias per head [h][m_key][n_query]
__device__ int   g_cnt[8];
__device__ int   g_gidx[8*TTOK];
__device__ float g_gw[8*TTOK];
__device__ int   g_grank[8*TTOK];
__device__ float g_contrib0[TTOK*192];
__device__ float g_contrib1[TTOK*192];
// bf16 activation buffers for tensor-core GEMMs
__device__ __nv_bfloat16 g_xw_bf[TTOK*192];
__device__ __nv_bfloat16 g_xm_bf[TTOK*192];
__device__ __nv_bfloat16 g_xout_bf[TTOK*384];
__device__ __nv_bfloat16 g_xn2_bf[TTOK*192];
__device__ __nv_bfloat16 g_hbuf[(size_t)8*TTOK*384];
// transposed bf16 weights [N][K]
__device__ __nv_bfloat16 g_wt_qs[576*192];
__device__ __nv_bfloat16 g_wt_qm[576*192];
__device__ __nv_bfloat16 g_wt_p [192*384];
__device__ __nv_bfloat16 g_wt_w1[8*384*192];
__device__ __nv_bfloat16 g_wt_w2[8*192*384];

// ---------------- helpers ------------------------------------------------
typedef unsigned long long ull;
__device__ __forceinline__ float warpsum_all(float v) {
    #pragma unroll
    for (int o = 16; o; o >>= 1) v += __shfl_xor_sync(0xffffffffu, v, o);
    return v;
}
__device__ __forceinline__ uint32_t smem_u32(const void* p) {
    uint32_t a;
    asm("{ .reg .u64 t; cvta.to.shared.u64 t, %1; cvt.u32.u64 %0, t; }" : "=r"(a) : "l"(p));
    return a;
}
__device__ __forceinline__ void ldsm_x4(uint32_t& r0, uint32_t& r1, uint32_t& r2,
                                        uint32_t& r3, uint32_t addr) {
    asm volatile("ldmatrix.sync.aligned.m8n8.x4.shared.b16 {%0,%1,%2,%3}, [%4];"
                 : "=r"(r0), "=r"(r1), "=r"(r2), "=r"(r3) : "r"(addr));
}
__device__ __forceinline__ void mma16816(float* c, uint32_t a0, uint32_t a1,
                                         uint32_t a2, uint32_t a3,
                                         uint32_t b0, uint32_t b1) {
    asm volatile("mma.sync.aligned.m16n8k16.row.col.f32.bf16.bf16.f32 "
        "{%0,%1,%2,%3}, {%4,%5,%6,%7}, {%8,%9}, {%0,%1,%2,%3};"
        : "+f"(c[0]), "+f"(c[1]), "+f"(c[2]), "+f"(c[3])
        : "r"(a0), "r"(a1), "r"(a2), "r"(a3), "r"(b0), "r"(b1));
}
__device__ __forceinline__ void cp16(uint32_t dst, const void* src, bool v) {
    asm volatile("cp.async.cg.shared.global [%0], [%1], 16, %2;"
                 :: "r"(dst), "l"(src), "r"(v ? 16u : 0u));
}
#define CP_COMMIT() asm volatile("cp.async.commit_group;")
#define CP_WAIT1()  asm volatile("cp.async.wait_group 1;")
#define CP_WAIT0()  asm volatile("cp.async.wait_group 0;")
#define SMEM_SWZ(o) ((o) ^ (((o) >> 3) & 0x70))

// ---- packed f32x2 ops (Blackwell FFMA2) ----
__device__ __forceinline__ ull fma2(ull a, ull b, ull c) {
    ull d;
    asm("fma.rn.f32x2 %0, %1, %2, %3;" : "=l"(d) : "l"(a), "l"(b), "l"(c));
    return d;
}
__device__ __forceinline__ ull pack2(float x, float y) {
    ull r;
    asm("mov.b64 %0, {%1,%2};" : "=l"(r) : "f"(x), "f"(y));
    return r;
}
__device__ __forceinline__ float2 unpack2(ull v) {
    float x, y;
    asm("mov.b64 {%0,%1}, %2;" : "=f"(x), "=f"(y) : "l"(v));
    return make_float2(x, y);
}

// ---- shared 128x64 warp-tile MMA over one 64-K chunk (8 warps: 4m x 2n) ----
__device__ __forceinline__ void mma_tile(uint32_t aB, uint32_t bB,
                                         float (&c)[2][4][4], int wm, int wn, int lane) {
    int g = lane >> 3, l7 = lane & 7;
    #pragma unroll
    for (int ks = 0; ks < 4; ks++) {
        uint32_t a[2][4];
        #pragma unroll
        for (int mi = 0; mi < 2; mi++) {
            int r = wm*32 + mi*16 + ((g & 1) << 3) + l7;
            int kb = ks*32 + ((g >> 1) << 4);
            ldsm_x4(a[mi][0], a[mi][1], a[mi][2], a[mi][3],
                    aB + SMEM_SWZ((uint32_t)(r*128 + kb)));
        }
        uint32_t b[4][2];
        #pragma unroll
        for (int np = 0; np < 2; np++) {
            int r = wn*32 + np*16 + ((g >> 1) << 3) + l7;
            int kb = ks*32 + ((g & 1) << 4);
            uint32_t r0, r1, r2, r3;
            ldsm_x4(r0, r1, r2, r3, bB + SMEM_SWZ((uint32_t)(r*128 + kb)));
            b[np*2][0] = r0;   b[np*2][1] = r1;
            b[np*2+1][0] = r2; b[np*2+1][1] = r3;
        }
        #pragma unroll
        for (int mi = 0; mi < 2; mi++)
            #pragma unroll
            for (int nj = 0; nj < 4; nj++)
                mma16816(c[mi][nj], a[mi][0], a[mi][1], a[mi][2], a[mi][3],
                         b[nj][0], b[nj][1]);
    }
}

// ---- shared mode-0 GEMM core: C fp32 = A @ Bt^T + bias ---------------------
__device__ __forceinline__ void gemm_core0(
        const __nv_bfloat16* __restrict__ A,
        const __nv_bfloat16* __restrict__ Bt,
        const float* __restrict__ bias,
        float* __restrict__ Cf, int K, int ldC, uint8_t* dyn_raw) {
    int tid = threadIdx.x, wid = tid >> 5, lane = tid & 31;
    int wm = wid >> 1, wn = wid & 1;
    int row0 = blockIdx.x * 128, col0 = blockIdx.y * 64;

    uint32_t aBase = (smem_u32(dyn_raw) + 1023u) & ~1023u;
    uint32_t bBase = aBase + 32768;

    int srow = tid >> 3, c16 = tid & 7;
    const __nv_bfloat16* arp[4]; uint32_t aOff[4];
    #pragma unroll
    for (int i = 0; i < 4; i++) {
        int r = i*32 + srow;
        aOff[i] = SMEM_SWZ((uint32_t)(r*128 + c16*16));
        arp[i] = A + (size_t)(row0 + r)*K + c16*8;
    }
    const __nv_bfloat16* brp[2]; uint32_t bOff[2];
    #pragma unroll
    for (int i = 0; i < 2; i++) {
        int r = i*32 + srow;
        bOff[i] = SMEM_SWZ((uint32_t)(r*128 + c16*16));
        brp[i] = Bt + (size_t)(col0 + r)*K + c16*8;
    }

    float c[2][4][4] = {};
    int nch = K >> 6;

    #pragma unroll
    for (int i = 0; i < 4; i++) cp16(aBase + aOff[i], arp[i], true);
    #pragma unroll
    for (int i = 0; i < 2; i++) cp16(bBase + bOff[i], brp[i], true);
    CP_COMMIT();

    for (int ic = 0; ic < nch; ic++) {
        if (ic + 1 < nch) {
            int buf = (ic + 1) & 1, kc = (ic + 1) << 6;
            #pragma unroll
            for (int i = 0; i < 4; i++)
                cp16(aBase + buf*16384 + aOff[i], arp[i] + kc, true);
            #pragma unroll
            for (int i = 0; i < 2; i++)
                cp16(bBase + buf*8192 + bOff[i], brp[i] + kc, true);
            CP_COMMIT();
            CP_WAIT1();
        } else {
            CP_WAIT0();
        }
        __syncthreads();
        mma_tile(aBase + (ic & 1)*16384, bBase + (ic & 1)*8192, c, wm, wn, lane);
        __syncthreads();
    }

    int qr = lane >> 2, qc = (lane & 3) * 2;
    #pragma unroll
    for (int mi = 0; mi < 2; mi++) {
        #pragma unroll
        for (int h = 0; h < 2; h++) {
            int lr = wm*32 + mi*16 + h*8 + qr;
            #pragma unroll
            for (int nj = 0; nj < 4; nj++) {
                int col = col0 + wn*32 + nj*8 + qc;
                size_t crow = (size_t)(row0 + lr)*ldC + col;
                *reinterpret_cast<float2*>(Cf + crow) =
                    make_float2(c[mi][nj][2*h] + bias[col],
                                c[mi][nj][2*h+1] + bias[col+1]);
            }
        }
    }
}

// ---- merged QKV GEMM: z=0 self, z=1 mutual ----------------------------------
__global__ __launch_bounds__(256) void gemm_qkv(const float* __restrict__ qsb,
                                                const float* __restrict__ qmb) {
    extern __shared__ uint8_t dyn_raw[];
    if (blockIdx.z == 0)
        gemm_core0(g_xw_bf, g_wt_qs, qsb, g_qkv_s, 192, 576, dyn_raw);
    else
        gemm_core0(g_xm_bf, g_wt_qm, qmb, g_qkv_m, 192, 576, dyn_raw);
}

// ---- proj GEMM ---------------------------------------------------------------
__global__ __launch_bounds__(256) void gemm_proj(
        const __nv_bfloat16* __restrict__ A, const __nv_bfloat16* __restrict__ Bt,
        const float* __restrict__ bias, float* __restrict__ Cf, int K, int ldC) {
    extern __shared__ uint8_t dyn_raw[];
    gemm_core0(A, Bt, bias, Cf, K, ldC, dyn_raw);
}

// ================= MoE split GEMMs ==========================================
// MODE 1: FC1 gather+gelu -> g_hbuf ; MODE 2: FC2 weighted scatter
template<int MODE>
__global__ __launch_bounds__(256) void gemm_moe(
        const __nv_bfloat16* __restrict__ A,
        const __nv_bfloat16* __restrict__ Bt,
        const float* __restrict__ bias, int K, int ldC) {
    extern __shared__ uint8_t dyn_raw[];
    __shared__ int s_tok[128]; __shared__ float s_wgt[128]; __shared__ int s_rnk[128];

    int tid = threadIdx.x, wid = tid >> 5, lane = tid & 31;
    int wm = wid >> 1, wn = wid & 1;
    int row0 = blockIdx.x * 128, col0 = blockIdx.y * 64;
    int e = blockIdx.z;
    int cnt = g_cnt[e];
    if (row0 >= cnt) return;
    const __nv_bfloat16* Bte = Bt + (size_t)e * ldC * K;
    const float* be = bias + (size_t)e * ldC;
    const __nv_bfloat16* Ae = (MODE == 2) ? (A + (size_t)e * TTOK * K) : A;

    if (tid < 128) {
        int slot = row0 + tid;
        if (slot < cnt) {
            s_tok[tid] = g_gidx[e*TTOK + slot];
            s_wgt[tid] = g_gw[e*TTOK + slot];
            s_rnk[tid] = g_grank[e*TTOK + slot];
        } else s_tok[tid] = -1;
    }
    __syncthreads();

    uint32_t aBase = (smem_u32(dyn_raw) + 1023u) & ~1023u;
    uint32_t bBase = aBase + 32768;

    int srow = tid >> 3, c16 = tid & 7;
    const __nv_bfloat16* arp[4]; bool av[4]; uint32_t aOff[4];
    #pragma unroll
    for (int i = 0; i < 4; i++) {
        int r = i*32 + srow;
        aOff[i] = SMEM_SWZ((uint32_t)(r*128 + c16*16));
        if (MODE == 1) {
            int tk = s_tok[r];
            av[i] = (tk >= 0);
            arp[i] = Ae + (size_t)(av[i] ? tk : 0)*K + c16*8;
        } else {
            av[i] = (row0 + r < cnt);
            arp[i] = Ae + (size_t)(av[i] ? (row0 + r) : 0)*K + c16*8;
        }
    }
    const __nv_bfloat16* brp[2]; uint32_t bOff[2];
    #pragma unroll
    for (int i = 0; i < 2; i++) {
        int r = i*32 + srow;
        bOff[i] = SMEM_SWZ((uint32_t)(r*128 + c16*16));
        brp[i] = Bte + (size_t)(col0 + r)*K + c16*8;
    }

    float c[2][4][4] = {};
    int nch = K >> 6;

    #pragma unroll
    for (int i = 0; i < 4; i++) cp16(aBase + aOff[i], arp[i], av[i]);
    #pragma unroll
    for (int i = 0; i < 2; i++) cp16(bBase + bOff[i], brp[i], true);
    CP_COMMIT();

    for (int ic = 0; ic < nch; ic++) {
        if (ic + 1 < nch) {
            int buf = (ic + 1) & 1, kc = (ic + 1) << 6;
            #pragma unroll
            for (int i = 0; i < 4; i++)
                cp16(aBase + buf*16384 + aOff[i], arp[i] + kc, av[i]);
            #pragma unroll
            for (int i = 0; i < 2; i++)
                cp16(bBase + buf*8192 + bOff[i], brp[i] + kc, true);
            CP_COMMIT();
            CP_WAIT1();
        } else {
            CP_WAIT0();
        }
        __syncthreads();
        mma_tile(aBase + (ic & 1)*16384, bBase + (ic & 1)*8192, c, wm, wn, lane);
        __syncthreads();
    }

    int qr = lane >> 2, qc = (lane & 3) * 2;
    #pragma unroll
    for (int mi = 0; mi < 2; mi++) {
        #pragma unroll
        for (int h = 0; h < 2; h++) {
            int lr = wm*32 + mi*16 + h*8 + qr;
            #pragma unroll
            for (int nj = 0; nj < 4; nj++) {
                int col = col0 + wn*32 + nj*8 + qc;
                float v0 = c[mi][nj][2*h + 0];
                float v1 = c[mi][nj][2*h + 1];
                if (MODE == 1) {
                    if (s_tok[lr] >= 0) {
                        float h0 = v0 + be[col], h1 = v1 + be[col+1];
                        h0 = h0 * normcdff(h0);
                        h1 = h1 * normcdff(h1);
                        __nv_bfloat162 p;
                        p.x = __float2bfloat16_rn(h0); p.y = __float2bfloat16_rn(h1);
                        *reinterpret_cast<__nv_bfloat162*>(
                            g_hbuf + ((size_t)e*TTOK + row0 + lr)*384 + col) = p;
                    }
                } else {
                    int tk = s_tok[lr];
                    if (tk >= 0) {
                        float w = s_wgt[lr];
                        float* dst = (s_rnk[lr] == 0) ? g_contrib0 : g_contrib1;
                        *reinterpret_cast<float2*>(dst + (size_t)tk*192 + col) =
                            make_float2(w*(v0 + be[col]), w*(v1 + be[col+1]));
                    }
                }
            }
        }
    }
}

// ---------------- prep: sine positional encoding + zero counters ------------
__global__ void k_pos() {
    int c = threadIdx.x;
    if (c < 8) g_cnt[c] = 0;
    const float TWO_PI = 6.283185307179586f;
    const float denom = 8.0f + 1e-6f;
    int f = (c < 96) ? c : c - 96;
    float expo = (float)(f & ~1) / 96.0f;
    float dt = powf(10000.0f, expo);
    for (int n = 0; n < 64; n++) {
        int i = n >> 3, j = n & 7;
        float base = (c < 96) ? (float)(i + 1) : (float)(j + 1);
        float v = base / denom * TWO_PI / dt;
        g_pos[n*192 + c] = (f & 1) ? cosf(v) : sinf(v);
    }
}

// ---------------- prep: rel-pos bias table [h][m_key][n_query] ---------------
__global__ void k_bias(const float* __restrict__ rpb) {
    int m = blockIdx.x, n = threadIdx.x;
    int dn = n >> 6, hn = (n >> 3) & 7, wn = n & 7;
    int dm = m >> 6, hm = (m >> 3) & 7, wm = m & 7;
    int rp = (dn - dm + 1)*225 + (hn - hm + 7)*15 + (wn - wm + 7);
    #pragma unroll
    for (int h = 0; h < 8; h++)
        g_biasf[h*16384 + m*128 + n] = rpb[rp*8 + h];
}

// ------------- prep: coalesced tiled weight transpose -> bf16 [N][K] ---------
__global__ __launch_bounds__(256) void k_transpose_t(
        const float* __restrict__ qs, const float* __restrict__ qm,
        const float* __restrict__ pw, const float* __restrict__ W1,
        const float* __restrict__ W2) {
    __shared__ float tile[64][65];
    int bid = blockIdx.x;
    const float* src; __nv_bfloat16* dst; int K, N, tk, tn;
    if (bid < 27)       { src = qs; dst = g_wt_qs; K = 192; N = 576; tk = bid/9; tn = bid%9; }
    else if (bid < 54)  { int j = bid-27; src = qm; dst = g_wt_qm; K = 192; N = 576; tk = j/9; tn = j%9; }
    else if (bid < 72)  { int j = bid-54; src = pw; dst = g_wt_p;  K = 384; N = 192; tk = j/3; tn = j%3; }
    else if (bid < 216) { int j = bid-72;  int e = j/18; j %= 18;
                          src = W1 + (size_t)e*73728; dst = g_wt_w1 + (size_t)e*73728;
                          K = 192; N = 384; tk = j/6; tn = j%6; }
    else                { int j = bid-216; int e = j/18; j %= 18;
                          src = W2 + (size_t)e*73728; dst = g_wt_w2 + (size_t)e*73728;
                          K = 384; N = 192; tk = j/3; tn = j%3; }
    int rr = threadIdx.x >> 6, cc = threadIdx.x & 63;
    #pragma unroll 4
    for (int i = 0; i < 16; i++) {
        int r = rr + 4*i;
        tile[r][cc] = src[(size_t)(tk*64 + r)*N + tn*64 + cc];
    }
    __syncthreads();
    #pragma unroll 4
    for (int i = 0; i < 16; i++) {
        int r = rr + 4*i;
        dst[(size_t)(tn*64 + r)*K + tk*64 + cc] = __float2bfloat16_rn(tile[cc][r]);
    }
}

// ---------------- LN1 + roll + window partition -> bf16 (warp per token) -----
__global__ __launch_bounds__(256) void ln_partition(const float* __restrict__ x,
                             const float* __restrict__ w1,
                             const float* __restrict__ b1) {
    int t = (blockIdx.x*blockDim.x + threadIdx.x) >> 5;
    int lane = threadIdx.x & 31;
    int win = t >> 7, n = t & 127;
    int b_  = win / 192; int rem = win % 192;
    int dd  = rem / 64;  int rem2 = rem % 64;
    int hh  = rem2 >> 3; int ww = rem2 & 7;
    int wd  = n >> 6, wh = (n >> 3) & 7, wwp = n & 7;
    int ds = dd*2 + wd, hs = hh*8 + wh, ws = ww*8 + wwp;
    int d = ds + 1; if (d >= 6) d -= 6;
    int h = (hs + 4) & 63;
    int w = (ws + 4) & 63;
    const float* xr = x + (size_t)(((b_*6 + d)*64 + h)*64 + w)*192;
    float v[6];
    float s1 = 0.f, s2 = 0.f;
    #pragma unroll
    for (int k = 0; k < 6; k++) {
        v[k] = xr[lane + 32*k];
        s1 += v[k]; s2 += v[k]*v[k];
    }
    s1 = warpsum_all(s1); s2 = warpsum_all(s2);
    float mu  = s1 * (1.f/192.f);
    float var = s2 * (1.f/192.f) - mu*mu;
    float rstd = rsqrtf(var + 1e-5f);
    const float* pr = g_pos + (n & 63)*192;
    #pragma unroll
    for (int k = 0; k < 6; k++) {
        int cc = lane + 32*k;
        float y = (v[k] - mu) * rstd * w1[cc] + b1[cc];
        g_xw_bf[(size_t)t*192 + cc] = __float2bfloat16_rn(y);
        g_xm_bf[(size_t)t*192 + cc] = __float2bfloat16_rn(y + pr[cc]);
    }
}

// ---------------- self attention: flash-style, LDS.128 + f32x2 ---------------
#define KVS 28   // padded row stride (floats): 112B, 16B-aligned rows
__global__ __launch_bounds__(128) void attn_self(const float* __restrict__ mask) {
    __shared__ __align__(16) float ks[128*KVS];
    __shared__ __align__(16) float vs[128*KVS];
    int win = blockIdx.x >> 3, h = blockIdx.x & 7;
    int n = threadIdx.x;
    size_t base = (size_t)(win*128 + n)*576 + h*24;
    const float4* qp = reinterpret_cast<const float4*>(g_qkv_s + base);
    const float4* kp = reinterpret_cast<const float4*>(g_qkv_s + base + 192);
    const float4* vp = reinterpret_cast<const float4*>(g_qkv_s + base + 384);
    const float SC = 0.20412414523193154f;   // 24^-0.5
    ull q2[12];
    #pragma unroll
    for (int i = 0; i < 6; i++) {
        float4 a = qp[i];
        q2[2*i]   = pack2(a.x*SC, a.y*SC);
        q2[2*i+1] = pack2(a.z*SC, a.w*SC);
        *reinterpret_cast<float4*>(&ks[n*KVS + 4*i]) = kp[i];
        *reinterpret_cast<float4*>(&vs[n*KVS + 4*i]) = vp[i];
    }
    __syncthreads();
    const float* mrow = mask + (size_t)(win % 192)*16384;
    const float* brow = g_biasf + (size_t)h*16384;
    ull o2[12] = {};
    float ssum = 0.f;
    #pragma unroll 2
    for (int m = 0; m < 128; m++) {
        const ulonglong2* kr = reinterpret_cast<const ulonglong2*>(ks + m*KVS);
        ull acc = 0ull;
        #pragma unroll
        for (int i = 0; i < 6; i++) {
            ulonglong2 t = kr[i];
            acc = fma2(q2[2*i], t.x, acc);
            acc = fma2(q2[2*i+1], t.y, acc);
        }
        float2 ac = unpack2(acc);
        float s = ac.x + ac.y + mrow[m*128 + n] + brow[m*128 + n];
        float p = __expf(s);
        ssum += p;
        ull pp = pack2(p, p);
        const ulonglong2* vr = reinterpret_cast<const ulonglong2*>(vs + m*KVS);
        #pragma unroll
        for (int i = 0; i < 6; i++) {
            ulonglong2 t = vr[i];
            o2[2*i]   = fma2(t.x, pp, o2[2*i]);
            o2[2*i+1] = fma2(t.y, pp, o2[2*i+1]);
        }
    }
    float inv = 1.f / ssum;
    __nv_bfloat162* ob = reinterpret_cast<__nv_bfloat162*>(
        g_xout_bf + (size_t)(win*128 + n)*384 + 192 + h*24);
    #pragma unroll
    for (int i = 0; i < 12; i++) {
        float2 o = unpack2(o2[i]);
        __nv_bfloat162 p;
        p.x = __float2bfloat16_rn(o.x*inv);
        p.y = __float2bfloat16_rn(o.y*inv);
        ob[i] = p;
    }
}

// ---------------- mutual attention: flash-style, LDS.128 + f32x2 -------------
__global__ __launch_bounds__(128) void attn_mut(const float* __restrict__ mask) {
    __shared__ __align__(16) float ks[2][64*KVS];
    __shared__ __align__(16) float vs[2][64*KVS];
    int win = blockIdx.x >> 3, h = blockIdx.x & 7;
    int tid = threadIdx.x;
    int p = tid >> 6, r = tid & 63;
    int kvtok = (p == 0) ? r : 64 + r;
    int qtok  = (p == 0) ? 64 + r : r;
    size_t kb = (size_t)(win*128 + kvtok)*576 + h*24;
    size_t qb = (size_t)(win*128 + qtok)*576 + h*24;
    const float4* qp = reinterpret_cast<const float4*>(g_qkv_m + qb);
    const float4* kp = reinterpret_cast<const float4*>(g_qkv_m + kb + 192);
    const float4* vp = reinterpret_cast<const float4*>(g_qkv_m + kb + 384);
    const float SC = 0.20412414523193154f;
    ull q2[12];
    #pragma unroll
    for (int i = 0; i < 6; i++) {
        float4 a = qp[i];
        q2[2*i]   = pack2(a.x*SC, a.y*SC);
        q2[2*i+1] = pack2(a.z*SC, a.w*SC);
        *reinterpret_cast<float4*>(&ks[p][r*KVS + 4*i]) = kp[i];
        *reinterpret_cast<float4*>(&vs[p][r*KVS + 4*i]) = vp[i];
    }
    __syncthreads();
    const float* mrow = mask + (size_t)(win % 192)*16384;
    ull o2[12] = {};
    float ssum = 0.f;
    #pragma unroll 2
    for (int m = 0; m < 64; m++) {
        const ulonglong2* kr = reinterpret_cast<const ulonglong2*>(&ks[p][m*KVS]);
        ull acc = 0ull;
        #pragma unroll
        for (int i = 0; i < 6; i++) {
            ulonglong2 t = kr[i];
            acc = fma2(q2[2*i], t.x, acc);
            acc = fma2(q2[2*i+1], t.y, acc);
        }
        float2 ac = unpack2(acc);
        float s = ac.x + ac.y + mrow[m*128 + r];   // mask symmetric
        float pv = __expf(s);
        ssum += pv;
        ull pp = pack2(pv, pv);
        const ulonglong2* vr = reinterpret_cast<const ulonglong2*>(&vs[p][m*KVS]);
        #pragma unroll
        for (int i = 0; i < 6; i++) {
            ulonglong2 t = vr[i];
            o2[2*i]   = fma2(t.x, pp, o2[2*i]);
            o2[2*i+1] = fma2(t.y, pp, o2[2*i+1]);
        }
    }
    float inv = 1.f / ssum;
    int orow = (p == 0) ? r : 64 + r;
    __nv_bfloat162* ob = reinterpret_cast<__nv_bfloat162*>(
        g_xout_bf + (size_t)(win*128 + orow)*384 + h*24);
    #pragma unroll
    for (int i = 0; i < 12; i++) {
        float2 o = unpack2(o2[i]);
        __nv_bfloat162 pr;
        pr.x = __float2bfloat16_rn(o.x*inv);
        pr.y = __float2bfloat16_rn(o.y*inv);
        ob[i] = pr;
    }
}

// --------- residual scatter + LN2 + gate top-2 (warp per token) --------------
__global__ __launch_bounds__(256) void resid_gate(const float* __restrict__ x,
                           const float* __restrict__ n2w, const float* __restrict__ n2b,
                           const float* __restrict__ gw,  const float* __restrict__ gb) {
    __shared__ float s_gw[8*192];
    for (int i = threadIdx.x; i < 1536; i += 256) {
        int j = i / 192, cc = i % 192;
        s_gw[i] = gw[cc*8 + j];
    }
    __syncthreads();
    int t = (blockIdx.x*blockDim.x + threadIdx.x) >> 5;
    int lane = threadIdx.x & 31;
    int b_ = t / 24576; int rrem = t % 24576;
    int d  = rrem / 4096; int r2 = rrem % 4096;
    int hh_ = r2 / 64; int ww_ = r2 % 64;
    int ds = d - 1; if (ds < 0) ds += 6;
    int hs = (hh_ + 60) & 63;
    int ws = (ww_ + 60) & 63;
    int dd = ds >> 1, wd = ds & 1;
    int hblk = hs >> 3, wh = hs & 7;
    int wblk = ws >> 3, wwp = ws & 7;
    int win = ((b_*3 + dd)*8 + hblk)*8 + wblk;
    int n = wd*64 + wh*8 + wwp;
    const float* ar = g_attnbuf + (size_t)(win*128 + n)*192;
    const float* xr = x + (size_t)t*192;
    float v[6];
    float s1 = 0.f, s2 = 0.f;
    #pragma unroll
    for (int k = 0; k < 6; k++) {
        int cc = lane + 32*k;
        v[k] = xr[cc] + ar[cc];
        g_xres[(size_t)t*192 + cc] = v[k];
        s1 += v[k]; s2 += v[k]*v[k];
    }
    s1 = warpsum_all(s1); s2 = warpsum_all(s2);
    float mu  = s1 * (1.f/192.f);
    float var = s2 * (1.f/192.f) - mu*mu;
    float rstd = rsqrtf(var + 1e-5f);
    float g[8] = {};
    #pragma unroll
    for (int k = 0; k < 6; k++) {
        int cc = lane + 32*k;
        float xn = (v[k] - mu) * rstd * n2w[cc] + n2b[cc];
        g_xn2_bf[(size_t)t*192 + cc] = __float2bfloat16_rn(xn);
        #pragma unroll
        for (int j = 0; j < 8; j++) g[j] = fmaf(xn, s_gw[j*192 + cc], g[j]);
    }
    #pragma unroll
    for (int j = 0; j < 8; j++) g[j] = warpsum_all(g[j]);
    if (lane == 0) {
        float L[8];
        #pragma unroll
        for (int j = 0; j < 8; j++) L[j] = g[j] + gb[j];
        int e0 = 0;
        #pragma unroll
        for (int j = 1; j < 8; j++) if (L[j] > L[e0]) e0 = j;
        int e1 = (e0 == 0) ? 1 : 0;
        #pragma unroll
        for (int j = 0; j < 8; j++) if (j != e0 && L[j] > L[e1]) e1 = j;
        float w0 = 1.f / (1.f + __expf(L[e1] - L[e0]));
        float w1 = 1.f - w0;
        int p0 = atomicAdd(&g_cnt[e0], 1);
        g_gidx[e0*TTOK + p0] = t; g_gw[e0*TTOK + p0] = w0; g_grank[e0*TTOK + p0] = 0;
        int p1 = atomicAdd(&g_cnt[e1], 1);
        g_gidx[e1*TTOK + p1] = t; g_gw[e1*TTOK + p1] = w1; g_grank[e1*TTOK + p1] = 1;
    }
}

// ---------------- finalize ----------------------------------------------------
__global__ void finalize(float* __restrict__ out) {
    int i = blockIdx.x*blockDim.x + threadIdx.x;
    if (i < TTOK*48) {
        float4 a  = reinterpret_cast<const float4*>(g_xres)[i];
        float4 c0 = reinterpret_cast<const float4*>(g_contrib0)[i];
        float4 c1 = reinterpret_cast<const float4*>(g_contrib1)[i];
        reinterpret_cast<float4*>(out)[i] =
            make_float4(a.x + c0.x + c1.x, a.y + c0.y + c1.y,
                        a.z + c0.z + c1.z, a.w + c0.w + c1.w);
    }
}

// ---------------- host launcher -----------------------------------------------
extern "C" void kernel_launch(void* const* d_in, const int* in_sizes, int n_in,
                              void* d_out, int out_size) {
    const float* x    = (const float*)d_in[0];
    const float* mask = (const float*)d_in[1];
    const float* n1w  = (const float*)d_in[2];
    const float* n1b  = (const float*)d_in[3];
    const float* qsw  = (const float*)d_in[4];
    const float* qsb  = (const float*)d_in[5];
    const float* qmw  = (const float*)d_in[6];
    const float* qmb  = (const float*)d_in[7];
    const float* rpb  = (const float*)d_in[8];
    const float* pw   = (const float*)d_in[9];
    const float* pb   = (const float*)d_in[10];
    const float* n2w  = (const float*)d_in[11];
    const float* n2b  = (const float*)d_in[12];
    const float* gw   = (const float*)d_in[13];
    const float* gb   = (const float*)d_in[14];
    const float* W1   = (const float*)d_in[15];
    const float* b1   = (const float*)d_in[16];
    const float* W2   = (const float*)d_in[17];
    const float* b2   = (const float*)d_in[18];
    float* out = (float*)d_out;

    const int DSMEM = 50176;
    cudaFuncSetAttribute(gemm_qkv,    cudaFuncAttributeMaxDynamicSharedMemorySize, DSMEM);
    cudaFuncSetAttribute(gemm_proj,   cudaFuncAttributeMaxDynamicSharedMemorySize, DSMEM);
    cudaFuncSetAttribute(gemm_moe<1>, cudaFuncAttributeMaxDynamicSharedMemorySize, DSMEM);
    cudaFuncSetAttribute(gemm_moe<2>, cudaFuncAttributeMaxDynamicSharedMemorySize, DSMEM);

    void *p_xout, *p_attn, *p_xn2, *p_h, *p_wp, *p_w1, *p_w2;
    cudaGetSymbolAddress(&p_xout, g_xout_bf);
    cudaGetSymbolAddress(&p_attn, g_attnbuf);
    cudaGetSymbolAddress(&p_xn2,  g_xn2_bf);
    cudaGetSymbolAddress(&p_h,    g_hbuf);
    cudaGetSymbolAddress(&p_wp,   g_wt_p);
    cudaGetSymbolAddress(&p_w1,   g_wt_w1);
    cudaGetSymbolAddress(&p_w2,   g_wt_w2);

    k_pos<<<1, 192>>>();
    k_bias<<<128, 128>>>(rpb);
    k_transpose_t<<<360, 256>>>(qsw, qmw, pw, W1, W2);
    ln_partition<<<6144, 256>>>(x, n1w, n1b);
    gemm_qkv<<<dim3(384, 9, 2), 256, DSMEM>>>(qsb, qmb);
    attn_self<<<NWIN*8, 128>>>(mask);
    attn_mut<<<NWIN*8, 128>>>(mask);
    gemm_proj<<<dim3(384, 3), 256, DSMEM>>>((const __nv_bfloat16*)p_xout,
        (const __nv_bfloat16*)p_wp, pb, (float*)p_attn, 384, 192);
    resid_gate<<<6144, 256>>>(x, n2w, n2b, gw, gb);
    gemm_moe<1><<<dim3(384, 6, 8), 256, DSMEM>>>((const __nv_bfloat16*)p_xn2,
        (const __nv_bfloat16*)p_w1, b1, 192, 384);
    gemm_moe<2><<<dim3(384, 3, 8), 256, DSMEM>>>((const __nv_bfloat16*)p_h,
        (const __nv_bfloat16*)p_w2, b2, 384, 192);
    finalize<<<9216, 256>>>(out);
}

// round 9
// speedup vs baseline: 1.1593x; 1.0221x over previous
#include <cuda_runtime.h>
#include <cuda_bf16.h>
#include <math.h>
#include <cstdint>

#define TTOK 49152      // total tokens = 2*6*64*64
#define NWIN 384

// ---------------- scratch (device globals; no allocations allowed) ----------
__device__ float g_qkv_s[TTOK*576];     // qkv fp32 (self)
__device__ float g_qkv_m[TTOK*576];     // qkv fp32 (mutual)
__device__ float g_attnbuf[TTOK*192];   // proj output (window order)
__device__ float g_pos[64*192];
__device__ float g_biasf[8*128*128];    // rel-pos bias per head [h][m_key][n_query]
__device__ int   g_cnt[8];
__device__ int   g_gidx[8*TTOK];
__device__ float g_gw[8*TTOK];
__device__ int   g_grank[8*TTOK];
__device__ float g_contrib0[TTOK*192];
__device__ float g_contrib1[TTOK*192];
// bf16 activation buffers for tensor-core GEMMs
__device__ __nv_bfloat16 g_xw_bf[TTOK*192];
__device__ __nv_bfloat16 g_xm_bf[TTOK*192];
__device__ __nv_bfloat16 g_xout_bf[TTOK*384];
__device__ __nv_bfloat16 g_xn2_bf[TTOK*192];
__device__ __nv_bfloat16 g_hbuf[(size_t)8*TTOK*384];
// transposed bf16 weights [N][K]
__device__ __nv_bfloat16 g_wt_qs[576*192];
__device__ __nv_bfloat16 g_wt_qm[576*192];
__device__ __nv_bfloat16 g_wt_p [192*384];
__device__ __nv_bfloat16 g_wt_w1[8*384*192];
__device__ __nv_bfloat16 g_wt_w2[8*192*384];

// ---------------- helpers ------------------------------------------------
typedef unsigned long long ull;
__device__ __forceinline__ float warpsum_all(float v) {
    #pragma unroll
    for (int o = 16; o; o >>= 1) v += __shfl_xor_sync(0xffffffffu, v, o);
    return v;
}
__device__ __forceinline__ uint32_t smem_u32(const void* p) {
    uint32_t a;
    asm("{ .reg .u64 t; cvta.to.shared.u64 t, %1; cvt.u32.u64 %0, t; }" : "=r"(a) : "l"(p));
    return a;
}
__device__ __forceinline__ void ldsm_x4(uint32_t& r0, uint32_t& r1, uint32_t& r2,
                                        uint32_t& r3, uint32_t addr) {
    asm volatile("ldmatrix.sync.aligned.m8n8.x4.shared.b16 {%0,%1,%2,%3}, [%4];"
                 : "=r"(r0), "=r"(r1), "=r"(r2), "=r"(r3) : "r"(addr));
}
__device__ __forceinline__ void mma16816(float* c, uint32_t a0, uint32_t a1,
                                         uint32_t a2, uint32_t a3,
                                         uint32_t b0, uint32_t b1) {
    asm volatile("mma.sync.aligned.m16n8k16.row.col.f32.bf16.bf16.f32 "
        "{%0,%1,%2,%3}, {%4,%5,%6,%7}, {%8,%9}, {%0,%1,%2,%3};"
        : "+f"(c[0]), "+f"(c[1]), "+f"(c[2]), "+f"(c[3])
        : "r"(a0), "r"(a1), "r"(a2), "r"(a3), "r"(b0), "r"(b1));
}
__device__ __forceinline__ void cp16(uint32_t dst, const void* src, bool v) {
    asm volatile("cp.async.cg.shared.global [%0], [%1], 16, %2;"
                 :: "r"(dst), "l"(src), "r"(v ? 16u : 0u));
}
#define CP_COMMIT() asm volatile("cp.async.commit_group;")
#define CP_WAIT1()  asm volatile("cp.async.wait_group 1;")
#define CP_WAIT0()  asm volatile("cp.async.wait_group 0;")
#define SMEM_SWZ(o) ((o) ^ (((o) >> 3) & 0x70))

// ---- packed f32x2 ops (Blackwell FFMA2) ----
__device__ __forceinline__ ull fma2(ull a, ull b, ull c) {
    ull d;
    asm("fma.rn.f32x2 %0, %1, %2, %3;" : "=l"(d) : "l"(a), "l"(b), "l"(c));
    return d;
}
__device__ __forceinline__ ull pack2(float x, float y) {
    ull r;
    asm("mov.b64 %0, {%1,%2};" : "=l"(r) : "f"(x), "f"(y));
    return r;
}
__device__ __forceinline__ float2 unpack2(ull v) {
    float x, y;
    asm("mov.b64 {%0,%1}, %2;" : "=f"(x), "=f"(y) : "l"(v));
    return make_float2(x, y);
}

// ---- 128x64 warp-tile MMA over one 64-K chunk (8 warps: 4m x 2n) ----------
__device__ __forceinline__ void mma_tile(uint32_t aB, uint32_t bB,
                                         float (&c)[2][4][4], int wm, int wn, int lane) {
    int g = lane >> 3, l7 = lane & 7;
    #pragma unroll
    for (int ks = 0; ks < 4; ks++) {
        uint32_t a[2][4];
        #pragma unroll
        for (int mi = 0; mi < 2; mi++) {
            int r = wm*32 + mi*16 + ((g & 1) << 3) + l7;
            int kb = ks*32 + ((g >> 1) << 4);
            ldsm_x4(a[mi][0], a[mi][1], a[mi][2], a[mi][3],
                    aB + SMEM_SWZ((uint32_t)(r*128 + kb)));
        }
        uint32_t b[4][2];
        #pragma unroll
        for (int np = 0; np < 2; np++) {
            int r = wn*32 + np*16 + ((g >> 1) << 3) + l7;
            int kb = ks*32 + ((g & 1) << 4);
            uint32_t r0, r1, r2, r3;
            ldsm_x4(r0, r1, r2, r3, bB + SMEM_SWZ((uint32_t)(r*128 + kb)));
            b[np*2][0] = r0;   b[np*2][1] = r1;
            b[np*2+1][0] = r2; b[np*2+1][1] = r3;
        }
        #pragma unroll
        for (int mi = 0; mi < 2; mi++)
            #pragma unroll
            for (int nj = 0; nj < 4; nj++)
                mma16816(c[mi][nj], a[mi][0], a[mi][1], a[mi][2], a[mi][3],
                         b[nj][0], b[nj][1]);
    }
}

// ---- 128x128 wide warp-tile MMA (8 warps: 4m x 2n, 64 n-cols per warp) -----
__device__ __forceinline__ void mma_tile_w(uint32_t aB, uint32_t bB,
                                           float (&c)[2][8][4], int wm, int wn, int lane) {
    int g = lane >> 3, l7 = lane & 7;
    #pragma unroll
    for (int ks = 0; ks < 4; ks++) {
        uint32_t a[2][4];
        #pragma unroll
        for (int mi = 0; mi < 2; mi++) {
            int r = wm*32 + mi*16 + ((g & 1) << 3) + l7;
            int kb = ks*32 + ((g >> 1) << 4);
            ldsm_x4(a[mi][0], a[mi][1], a[mi][2], a[mi][3],
                    aB + SMEM_SWZ((uint32_t)(r*128 + kb)));
        }
        uint32_t b[8][2];
        #pragma unroll
        for (int np = 0; np < 4; np++) {
            int r = wn*64 + np*16 + ((g >> 1) << 3) + l7;
            int kb = ks*32 + ((g & 1) << 4);
            uint32_t r0, r1, r2, r3;
            ldsm_x4(r0, r1, r2, r3, bB + SMEM_SWZ((uint32_t)(r*128 + kb)));
            b[np*2][0] = r0;   b[np*2][1] = r1;
            b[np*2+1][0] = r2; b[np*2+1][1] = r3;
        }
        #pragma unroll
        for (int mi = 0; mi < 2; mi++)
            #pragma unroll
            for (int nj = 0; nj < 8; nj++)
                mma16816(c[mi][nj], a[mi][0], a[mi][1], a[mi][2], a[mi][3],
                         b[nj][0], b[nj][1]);
    }
}

// ---- shared mode-0 GEMM core: C fp32 = A @ Bt^T + bias ---------------------
__device__ __forceinline__ void gemm_core0(
        const __nv_bfloat16* __restrict__ A,
        const __nv_bfloat16* __restrict__ Bt,
        const float* __restrict__ bias,
        float* __restrict__ Cf, int K, int ldC, uint8_t* dyn_raw) {
    int tid = threadIdx.x, wid = tid >> 5, lane = tid & 31;
    int wm = wid >> 1, wn = wid & 1;
    int row0 = blockIdx.x * 128, col0 = blockIdx.y * 64;

    uint32_t aBase = (smem_u32(dyn_raw) + 1023u) & ~1023u;
    uint32_t bBase = aBase + 32768;

    int srow = tid >> 3, c16 = tid & 7;
    const __nv_bfloat16* arp[4]; uint32_t aOff[4];
    #pragma unroll
    for (int i = 0; i < 4; i++) {
        int r = i*32 + srow;
        aOff[i] = SMEM_SWZ((uint32_t)(r*128 + c16*16));
        arp[i] = A + (size_t)(row0 + r)*K + c16*8;
    }
    const __nv_bfloat16* brp[2]; uint32_t bOff[2];
    #pragma unroll
    for (int i = 0; i < 2; i++) {
        int r = i*32 + srow;
        bOff[i] = SMEM_SWZ((uint32_t)(r*128 + c16*16));
        brp[i] = Bt + (size_t)(col0 + r)*K + c16*8;
    }

    float c[2][4][4] = {};
    int nch = K >> 6;

    #pragma unroll
    for (int i = 0; i < 4; i++) cp16(aBase + aOff[i], arp[i], true);
    #pragma unroll
    for (int i = 0; i < 2; i++) cp16(bBase + bOff[i], brp[i], true);
    CP_COMMIT();

    for (int ic = 0; ic < nch; ic++) {
        if (ic + 1 < nch) {
            int buf = (ic + 1) & 1, kc = (ic + 1) << 6;
            #pragma unroll
            for (int i = 0; i < 4; i++)
                cp16(aBase + buf*16384 + aOff[i], arp[i] + kc, true);
            #pragma unroll
            for (int i = 0; i < 2; i++)
                cp16(bBase + buf*8192 + bOff[i], brp[i] + kc, true);
            CP_COMMIT();
            CP_WAIT1();
        } else {
            CP_WAIT0();
        }
        __syncthreads();
        mma_tile(aBase + (ic & 1)*16384, bBase + (ic & 1)*8192, c, wm, wn, lane);
        __syncthreads();
    }

    int qr = lane >> 2, qc = (lane & 3) * 2;
    #pragma unroll
    for (int mi = 0; mi < 2; mi++) {
        #pragma unroll
        for (int h = 0; h < 2; h++) {
            int lr = wm*32 + mi*16 + h*8 + qr;
            #pragma unroll
            for (int nj = 0; nj < 4; nj++) {
                int col = col0 + wn*32 + nj*8 + qc;
                size_t crow = (size_t)(row0 + lr)*ldC + col;
                *reinterpret_cast<float2*>(Cf + crow) =
                    make_float2(c[mi][nj][2*h] + bias[col],
                                c[mi][nj][2*h+1] + bias[col+1]);
            }
        }
    }
}

// ---- merged QKV GEMM: z=0 self, z=1 mutual ----------------------------------
__global__ __launch_bounds__(256) void gemm_qkv(const float* __restrict__ qsb,
                                                const float* __restrict__ qmb) {
    extern __shared__ uint8_t dyn_raw[];
    if (blockIdx.z == 0)
        gemm_core0(g_xw_bf, g_wt_qs, qsb, g_qkv_s, 192, 576, dyn_raw);
    else
        gemm_core0(g_xm_bf, g_wt_qm, qmb, g_qkv_m, 192, 576, dyn_raw);
}

// ---- proj GEMM ---------------------------------------------------------------
__global__ __launch_bounds__(256) void gemm_proj(
        const __nv_bfloat16* __restrict__ A, const __nv_bfloat16* __restrict__ Bt,
        const float* __restrict__ bias, float* __restrict__ Cf, int K, int ldC) {
    extern __shared__ uint8_t dyn_raw[];
    gemm_core0(A, Bt, bias, Cf, K, ldC, dyn_raw);
}

// ======= MoE FC1: gather + gelu -> g_hbuf, wide 128x128 tile, K=192 =========
__global__ __launch_bounds__(256) void gemm_moe1(const float* __restrict__ b1) {
    extern __shared__ uint8_t dyn_raw[];
    __shared__ int s_tok[128];
    int tid = threadIdx.x, wid = tid >> 5, lane = tid & 31;
    int wm = wid >> 1, wn = wid & 1;
    int row0 = blockIdx.x * 128, col0 = blockIdx.y * 128;
    int e = blockIdx.z;
    int cnt = g_cnt[e];
    if (row0 >= cnt) return;
    const __nv_bfloat16* W1te = g_wt_w1 + (size_t)e*73728;
    const float* b1e = b1 + e*384;

    if (tid < 128) {
        int slot = row0 + tid;
        s_tok[tid] = (slot < cnt) ? g_gidx[e*TTOK + slot] : -1;
    }
    __syncthreads();

    uint32_t aBase = (smem_u32(dyn_raw) + 1023u) & ~1023u;
    uint32_t bBase = aBase + 32768;

    int srow = tid >> 3, c16 = tid & 7;
    const __nv_bfloat16* arp[4]; bool av[4]; uint32_t off[4];
    const __nv_bfloat16* brp[4];
    #pragma unroll
    for (int i = 0; i < 4; i++) {
        int r = i*32 + srow;
        off[i] = SMEM_SWZ((uint32_t)(r*128 + c16*16));
        int tk = s_tok[r];
        av[i] = (tk >= 0);
        arp[i] = g_xn2_bf + (size_t)(av[i] ? tk : 0)*192 + c16*8;
        brp[i] = W1te + (size_t)(col0 + r)*192 + c16*8;
    }

    float c[2][8][4] = {};

    #pragma unroll
    for (int i = 0; i < 4; i++) cp16(aBase + off[i], arp[i], av[i]);
    #pragma unroll
    for (int i = 0; i < 4; i++) cp16(bBase + off[i], brp[i], true);
    CP_COMMIT();

    for (int ic = 0; ic < 3; ic++) {
        if (ic + 1 < 3) {
            int buf = (ic + 1) & 1, kc = (ic + 1) << 6;
            #pragma unroll
            for (int i = 0; i < 4; i++)
                cp16(aBase + buf*16384 + off[i], arp[i] + kc, av[i]);
            #pragma unroll
            for (int i = 0; i < 4; i++)
                cp16(bBase + buf*16384 + off[i], brp[i] + kc, true);
            CP_COMMIT();
            CP_WAIT1();
        } else {
            CP_WAIT0();
        }
        __syncthreads();
        mma_tile_w(aBase + (ic & 1)*16384, bBase + (ic & 1)*16384, c, wm, wn, lane);
        __syncthreads();
    }

    int qr = lane >> 2, qc = (lane & 3) * 2;
    #pragma unroll
    for (int mi = 0; mi < 2; mi++) {
        #pragma unroll
        for (int h = 0; h < 2; h++) {
            int lr = wm*32 + mi*16 + h*8 + qr;
            if (s_tok[lr] >= 0) {
                size_t hrow = ((size_t)e*TTOK + row0 + lr)*384;
                #pragma unroll
                for (int nj = 0; nj < 8; nj++) {
                    int col = col0 + wn*64 + nj*8 + qc;
                    float h0 = c[mi][nj][2*h]   + b1e[col];
                    float h1 = c[mi][nj][2*h+1] + b1e[col+1];
                    h0 = h0 * normcdff(h0);
                    h1 = h1 * normcdff(h1);
                    __nv_bfloat162 p;
                    p.x = __float2bfloat16_rn(h0); p.y = __float2bfloat16_rn(h1);
                    *reinterpret_cast<__nv_bfloat162*>(g_hbuf + hrow + col) = p;
                }
            }
        }
    }
}

// ======= MoE FC2: weighted scatter -> contrib buffers, K=384 ================
__global__ __launch_bounds__(256) void gemm_moe2(const float* __restrict__ b2) {
    extern __shared__ uint8_t dyn_raw[];
    __shared__ int s_tok[128]; __shared__ float s_wgt[128]; __shared__ int s_rnk[128];

    int tid = threadIdx.x, wid = tid >> 5, lane = tid & 31;
    int wm = wid >> 1, wn = wid & 1;
    int row0 = blockIdx.x * 128, col0 = blockIdx.y * 64;
    int e = blockIdx.z;
    int cnt = g_cnt[e];
    if (row0 >= cnt) return;
    const __nv_bfloat16* Bte = g_wt_w2 + (size_t)e*73728;
    const float* be = b2 + e*192;
    const __nv_bfloat16* Ae = g_hbuf + (size_t)e*TTOK*384;

    if (tid < 128) {
        int slot = row0 + tid;
        if (slot < cnt) {
            s_tok[tid] = g_gidx[e*TTOK + slot];
            s_wgt[tid] = g_gw[e*TTOK + slot];
            s_rnk[tid] = g_grank[e*TTOK + slot];
        } else s_tok[tid] = -1;
    }
    __syncthreads();

    uint32_t aBase = (smem_u32(dyn_raw) + 1023u) & ~1023u;
    uint32_t bBase = aBase + 32768;

    int srow = tid >> 3, c16 = tid & 7;
    const __nv_bfloat16* arp[4]; bool av[4]; uint32_t aOff[4];
    #pragma unroll
    for (int i = 0; i < 4; i++) {
        int r = i*32 + srow;
        aOff[i] = SMEM_SWZ((uint32_t)(r*128 + c16*16));
        av[i] = (row0 + r < cnt);
        arp[i] = Ae + (size_t)(av[i] ? (row0 + r) : 0)*384 + c16*8;
    }
    const __nv_bfloat16* brp[2]; uint32_t bOff[2];
    #pragma unroll
    for (int i = 0; i < 2; i++) {
        int r = i*32 + srow;
        bOff[i] = SMEM_SWZ((uint32_t)(r*128 + c16*16));
        brp[i] = Bte + (size_t)(col0 + r)*384 + c16*8;
    }

    float c[2][4][4] = {};

    #pragma unroll
    for (int i = 0; i < 4; i++) cp16(aBase + aOff[i], arp[i], av[i]);
    #pragma unroll
    for (int i = 0; i < 2; i++) cp16(bBase + bOff[i], brp[i], true);
    CP_COMMIT();

    for (int ic = 0; ic < 6; ic++) {
        if (ic + 1 < 6) {
            int buf = (ic + 1) & 1, kc = (ic + 1) << 6;
            #pragma unroll
            for (int i = 0; i < 4; i++)
                cp16(aBase + buf*16384 + aOff[i], arp[i] + kc, av[i]);
            #pragma unroll
            for (int i = 0; i < 2; i++)
                cp16(bBase + buf*8192 + bOff[i], brp[i] + kc, true);
            CP_COMMIT();
            CP_WAIT1();
        } else {
            CP_WAIT0();
        }
        __syncthreads();
        mma_tile(aBase + (ic & 1)*16384, bBase + (ic & 1)*8192, c, wm, wn, lane);
        __syncthreads();
    }

    int qr = lane >> 2, qc = (lane & 3) * 2;
    #pragma unroll
    for (int mi = 0; mi < 2; mi++) {
        #pragma unroll
        for (int h = 0; h < 2; h++) {
            int lr = wm*32 + mi*16 + h*8 + qr;
            int tk = s_tok[lr];
            if (tk >= 0) {
                float w = s_wgt[lr];
                float* dst = (s_rnk[lr] == 0) ? g_contrib0 : g_contrib1;
                #pragma unroll
                for (int nj = 0; nj < 4; nj++) {
                    int col = col0 + wn*32 + nj*8 + qc;
                    *reinterpret_cast<float2*>(dst + (size_t)tk*192 + col) =
                        make_float2(w*(c[mi][nj][2*h]   + be[col]),
                                    w*(c[mi][nj][2*h+1] + be[col+1]));
                }
            }
        }
    }
}

// ------- prep: rel-pos bias table + sine pos encoding + counters (merged) ----
__global__ void k_prep(const float* __restrict__ rpb) {
    if (blockIdx.x == 128) {
        int c = threadIdx.x;                 // 0..191
        if (c < 8) g_cnt[c] = 0;
        const float TWO_PI = 6.283185307179586f;
        const float denom = 8.0f + 1e-6f;
        int f = (c < 96) ? c : c - 96;
        float expo = (float)(f & ~1) / 96.0f;
        float dt = powf(10000.0f, expo);
        for (int n = 0; n < 64; n++) {
            int i = n >> 3, j = n & 7;
            float base = (c < 96) ? (float)(i + 1) : (float)(j + 1);
            float v = base / denom * TWO_PI / dt;
            g_pos[n*192 + c] = (f & 1) ? cosf(v) : sinf(v);
        }
    } else {
        int n = threadIdx.x;
        if (n >= 128) return;
        int m = blockIdx.x;                  // m = key
        int dn = n >> 6, hn = (n >> 3) & 7, wn = n & 7;
        int dm = m >> 6, hm = (m >> 3) & 7, wm = m & 7;
        int rp = (dn - dm + 1)*225 + (hn - hm + 7)*15 + (wn - wm + 7);
        #pragma unroll
        for (int h = 0; h < 8; h++)
            g_biasf[h*16384 + m*128 + n] = rpb[rp*8 + h];
    }
}

// ------------- prep: coalesced tiled weight transpose -> bf16 [N][K] ---------
__global__ __launch_bounds__(256) void k_transpose_t(
        const float* __restrict__ qs, const float* __restrict__ qm,
        const float* __restrict__ pw, const float* __restrict__ W1,
        const float* __restrict__ W2) {
    __shared__ float tile[64][65];
    int bid = blockIdx.x;
    const float* src; __nv_bfloat16* dst; int K, N, tk, tn;
    if (bid < 27)       { src = qs; dst = g_wt_qs; K = 192; N = 576; tk = bid/9; tn = bid%9; }
    else if (bid < 54)  { int j = bid-27; src = qm; dst = g_wt_qm; K = 192; N = 576; tk = j/9; tn = j%9; }
    else if (bid < 72)  { int j = bid-54; src = pw; dst = g_wt_p;  K = 384; N = 192; tk = j/3; tn = j%3; }
    else if (bid < 216) { int j = bid-72;  int e = j/18; j %= 18;
                          src = W1 + (size_t)e*73728; dst = g_wt_w1 + (size_t)e*73728;
                          K = 192; N = 384; tk = j/6; tn = j%6; }
    else                { int j = bid-216; int e = j/18; j %= 18;
                          src = W2 + (size_t)e*73728; dst = g_wt_w2 + (size_t)e*73728;
                          K = 384; N = 192; tk = j/3; tn = j%3; }
    int rr = threadIdx.x >> 6, cc = threadIdx.x & 63;
    #pragma unroll 4
    for (int i = 0; i < 16; i++) {
        int r = rr + 4*i;
        tile[r][cc] = src[(size_t)(tk*64 + r)*N + tn*64 + cc];
    }
    __syncthreads();
    #pragma unroll 4
    for (int i = 0; i < 16; i++) {
        int r = rr + 4*i;
        dst[(size_t)(tn*64 + r)*K + tk*64 + cc] = __float2bfloat16_rn(tile[cc][r]);
    }
}

// ---------------- LN1 + roll + window partition -> bf16 (warp per token) -----
__global__ __launch_bounds__(256) void ln_partition(const float* __restrict__ x,
                             const float* __restrict__ w1,
                             const float* __restrict__ b1) {
    int t = (blockIdx.x*blockDim.x + threadIdx.x) >> 5;
    int lane = threadIdx.x & 31;
    int win = t >> 7, n = t & 127;
    int b_  = win / 192; int rem = win % 192;
    int dd  = rem / 64;  int rem2 = rem % 64;
    int hh  = rem2 >> 3; int ww = rem2 & 7;
    int wd  = n >> 6, wh = (n >> 3) & 7, wwp = n & 7;
    int ds = dd*2 + wd, hs = hh*8 + wh, ws = ww*8 + wwp;
    int d = ds + 1; if (d >= 6) d -= 6;
    int h = (hs + 4) & 63;
    int w = (ws + 4) & 63;
    const float* xr = x + (size_t)(((b_*6 + d)*64 + h)*64 + w)*192;
    float v[6];
    float s1 = 0.f, s2 = 0.f;
    #pragma unroll
    for (int k = 0; k < 6; k++) {
        v[k] = xr[lane + 32*k];
        s1 += v[k]; s2 += v[k]*v[k];
    }
    s1 = warpsum_all(s1); s2 = warpsum_all(s2);
    float mu  = s1 * (1.f/192.f);
    float var = s2 * (1.f/192.f) - mu*mu;
    float rstd = rsqrtf(var + 1e-5f);
    const float* pr = g_pos + (n & 63)*192;
    #pragma unroll
    for (int k = 0; k < 6; k++) {
        int cc = lane + 32*k;
        float y = (v[k] - mu) * rstd * w1[cc] + b1[cc];
        g_xw_bf[(size_t)t*192 + cc] = __float2bfloat16_rn(y);
        g_xm_bf[(size_t)t*192 + cc] = __float2bfloat16_rn(y + pr[cc]);
    }
}

// ---------------- self attention: flash-style, LDS.128 + f32x2 ---------------
#define KVS 28   // padded row stride (floats): 112B, 16B-aligned rows
__global__ __launch_bounds__(128) void attn_self(const float* __restrict__ mask) {
    __shared__ __align__(16) float ks[128*KVS];
    __shared__ __align__(16) float vs[128*KVS];
    int win = blockIdx.x >> 3, h = blockIdx.x & 7;
    int n = threadIdx.x;
    size_t base = (size_t)(win*128 + n)*576 + h*24;
    const float4* qp = reinterpret_cast<const float4*>(g_qkv_s + base);
    const float4* kp = reinterpret_cast<const float4*>(g_qkv_s + base + 192);
    const float4* vp = reinterpret_cast<const float4*>(g_qkv_s + base + 384);
    const float SC = 0.20412414523193154f;   // 24^-0.5
    ull q2[12];
    #pragma unroll
    for (int i = 0; i < 6; i++) {
        float4 a = qp[i];
        q2[2*i]   = pack2(a.x*SC, a.y*SC);
        q2[2*i+1] = pack2(a.z*SC, a.w*SC);
        *reinterpret_cast<float4*>(&ks[n*KVS + 4*i]) = kp[i];
        *reinterpret_cast<float4*>(&vs[n*KVS + 4*i]) = vp[i];
    }
    __syncthreads();
    const float* mrow = mask + (size_t)(win % 192)*16384;
    const float* brow = g_biasf + (size_t)h*16384;
    ull o2[12] = {};
    float ssum = 0.f;
    #pragma unroll 2
    for (int m = 0; m < 128; m++) {
        const ulonglong2* kr = reinterpret_cast<const ulonglong2*>(ks + m*KVS);
        ull acc = 0ull;
        #pragma unroll
        for (int i = 0; i < 6; i++) {
            ulonglong2 t = kr[i];
            acc = fma2(q2[2*i], t.x, acc);
            acc = fma2(q2[2*i+1], t.y, acc);
        }
        float2 ac = unpack2(acc);
        float s = ac.x + ac.y + mrow[m*128 + n] + brow[m*128 + n];
        float p = __expf(s);
        ssum += p;
        ull pp = pack2(p, p);
        const ulonglong2* vr = reinterpret_cast<const ulonglong2*>(vs + m*KVS);
        #pragma unroll
        for (int i = 0; i < 6; i++) {
            ulonglong2 t = vr[i];
            o2[2*i]   = fma2(t.x, pp, o2[2*i]);
            o2[2*i+1] = fma2(t.y, pp, o2[2*i+1]);
        }
    }
    float inv = 1.f / ssum;
    __nv_bfloat162* ob = reinterpret_cast<__nv_bfloat162*>(
        g_xout_bf + (size_t)(win*128 + n)*384 + 192 + h*24);
    #pragma unroll
    for (int i = 0; i < 12; i++) {
        float2 o = unpack2(o2[i]);
        __nv_bfloat162 p;
        p.x = __float2bfloat16_rn(o.x*inv);
        p.y = __float2bfloat16_rn(o.y*inv);
        ob[i] = p;
    }
}

// ---------------- mutual attention: flash-style, LDS.128 + f32x2 -------------
__global__ __launch_bounds__(128) void attn_mut(const float* __restrict__ mask) {
    __shared__ __align__(16) float ks[2][64*KVS];
    __shared__ __align__(16) float vs[2][64*KVS];
    int win = blockIdx.x >> 3, h = blockIdx.x & 7;
    int tid = threadIdx.x;
    int p = tid >> 6, r = tid & 63;
    int kvtok = (p == 0) ? r : 64 + r;
    int qtok  = (p == 0) ? 64 + r : r;
    size_t kb = (size_t)(win*128 + kvtok)*576 + h*24;
    size_t qb = (size_t)(win*128 + qtok)*576 + h*24;
    const float4* qp = reinterpret_cast<const float4*>(g_qkv_m + qb);
    const float4* kp = reinterpret_cast<const float4*>(g_qkv_m + kb + 192);
    const float4* vp = reinterpret_cast<const float4*>(g_qkv_m + kb + 384);
    const float SC = 0.20412414523193154f;
    ull q2[12];
    #pragma unroll
    for (int i = 0; i < 6; i++) {
        float4 a = qp[i];
        q2[2*i]   = pack2(a.x*SC, a.y*SC);
        q2[2*i+1] = pack2(a.z*SC, a.w*SC);
        *reinterpret_cast<float4*>(&ks[p][r*KVS + 4*i]) = kp[i];
        *reinterpret_cast<float4*>(&vs[p][r*KVS + 4*i]) = vp[i];
    }
    __syncthreads();
    const float* mrow = mask + (size_t)(win % 192)*16384;
    ull o2[12] = {};
    float ssum = 0.f;
    #pragma unroll 2
    for (int m = 0; m < 64; m++) {
        const ulonglong2* kr = reinterpret_cast<const ulonglong2*>(&ks[p][m*KVS]);
        ull acc = 0ull;
        #pragma unroll
        for (int i = 0; i < 6; i++) {
            ulonglong2 t = kr[i];
            acc = fma2(q2[2*i], t.x, acc);
            acc = fma2(q2[2*i+1], t.y, acc);
        }
        float2 ac = unpack2(acc);
        float s = ac.x + ac.y + mrow[m*128 + r];   // mask symmetric
        float pv = __expf(s);
        ssum += pv;
        ull pp = pack2(pv, pv);
        const ulonglong2* vr = reinterpret_cast<const ulonglong2*>(&vs[p][m*KVS]);
        #pragma unroll
        for (int i = 0; i < 6; i++) {
            ulonglong2 t = vr[i];
            o2[2*i]   = fma2(t.x, pp, o2[2*i]);
            o2[2*i+1] = fma2(t.y, pp, o2[2*i+1]);
        }
    }
    float inv = 1.f / ssum;
    int orow = (p == 0) ? r : 64 + r;
    __nv_bfloat162* ob = reinterpret_cast<__nv_bfloat162*>(
        g_xout_bf + (size_t)(win*128 + orow)*384 + h*24);
    #pragma unroll
    for (int i = 0; i < 12; i++) {
        float2 o = unpack2(o2[i]);
        __nv_bfloat162 pr;
        pr.x = __float2bfloat16_rn(o.x*inv);
        pr.y = __float2bfloat16_rn(o.y*inv);
        ob[i] = pr;
    }
}

// --------- residual (writes out directly) + LN2 + gate top-2 -----------------
__global__ __launch_bounds__(256) void resid_gate(const float* __restrict__ x,
                           const float* __restrict__ n2w, const float* __restrict__ n2b,
                           const float* __restrict__ gw,  const float* __restrict__ gb,
                           float* __restrict__ out) {
    __shared__ float s_gw[8*192];
    for (int i = threadIdx.x; i < 1536; i += 256) {
        int j = i / 192, cc = i % 192;
        s_gw[i] = gw[cc*8 + j];
    }
    __syncthreads();
    int t = (blockIdx.x*blockDim.x + threadIdx.x) >> 5;
    int lane = threadIdx.x & 31;
    int b_ = t / 24576; int rrem = t % 24576;
    int d  = rrem / 4096; int r2 = rrem % 4096;
    int hh_ = r2 / 64; int ww_ = r2 % 64;
    int ds = d - 1; if (ds < 0) ds += 6;
    int hs = (hh_ + 60) & 63;
    int ws = (ww_ + 60) & 63;
    int dd = ds >> 1, wd = ds & 1;
    int hblk = hs >> 3, wh = hs & 7;
    int wblk = ws >> 3, wwp = ws & 7;
    int win = ((b_*3 + dd)*8 + hblk)*8 + wblk;
    int n = wd*64 + wh*8 + wwp;
    const float* ar = g_attnbuf + (size_t)(win*128 + n)*192;
    const float* xr = x + (size_t)t*192;
    float v[6];
    float s1 = 0.f, s2 = 0.f;
    #pragma unroll
    for (int k = 0; k < 6; k++) {
        int cc = lane + 32*k;
        v[k] = xr[cc] + ar[cc];
        out[(size_t)t*192 + cc] = v[k];
        s1 += v[k]; s2 += v[k]*v[k];
    }
    s1 = warpsum_all(s1); s2 = warpsum_all(s2);
    float mu  = s1 * (1.f/192.f);
    float var = s2 * (1.f/192.f) - mu*mu;
    float rstd = rsqrtf(var + 1e-5f);
    float g[8] = {};
    #pragma unroll
    for (int k = 0; k < 6; k++) {
        int cc = lane + 32*k;
        float xn = (v[k] - mu) * rstd * n2w[cc] + n2b[cc];
        g_xn2_bf[(size_t)t*192 + cc] = __float2bfloat16_rn(xn);
        #pragma unroll
        for (int j = 0; j < 8; j++) g[j] = fmaf(xn, s_gw[j*192 + cc], g[j]);
    }
    #pragma unroll
    for (int j = 0; j < 8; j++) g[j] = warpsum_all(g[j]);
    if (lane == 0) {
        float L[8];
        #pragma unroll
        for (int j = 0; j < 8; j++) L[j] = g[j] + gb[j];
        int e0 = 0;
        #pragma unroll
        for (int j = 1; j < 8; j++) if (L[j] > L[e0]) e0 = j;
        int e1 = (e0 == 0) ? 1 : 0;
        #pragma unroll
        for (int j = 0; j < 8; j++) if (j != e0 && L[j] > L[e1]) e1 = j;
        float w0 = 1.f / (1.f + __expf(L[e1] - L[e0]));
        float w1 = 1.f - w0;
        int p0 = atomicAdd(&g_cnt[e0], 1);
        g_gidx[e0*TTOK + p0] = t; g_gw[e0*TTOK + p0] = w0; g_grank[e0*TTOK + p0] = 0;
        int p1 = atomicAdd(&g_cnt[e1], 1);
        g_gidx[e1*TTOK + p1] = t; g_gw[e1*TTOK + p1] = w1; g_grank[e1*TTOK + p1] = 1;
    }
}

// ---------------- finalize: out += contrib0 + contrib1 -----------------------
__global__ void finalize(float* __restrict__ out) {
    int i = blockIdx.x*blockDim.x + threadIdx.x;
    if (i < TTOK*48) {
        float4 a  = reinterpret_cast<const float4*>(out)[i];
        float4 c0 = reinterpret_cast<const float4*>(g_contrib0)[i];
        float4 c1 = reinterpret_cast<const float4*>(g_contrib1)[i];
        reinterpret_cast<float4*>(out)[i] =
            make_float4(a.x + c0.x + c1.x, a.y + c0.y + c1.y,
                        a.z + c0.z + c1.z, a.w + c0.w + c1.w);
    }
}

// ---------------- host launcher -----------------------------------------------
extern "C" void kernel_launch(void* const* d_in, const int* in_sizes, int n_in,
                              void* d_out, int out_size) {
    const float* x    = (const float*)d_in[0];
    const float* mask = (const float*)d_in[1];
    const float* n1w  = (const float*)d_in[2];
    const float* n1b  = (const float*)d_in[3];
    const float* qsw  = (const float*)d_in[4];
    const float* qsb  = (const float*)d_in[5];
    const float* qmw  = (const float*)d_in[6];
    const float* qmb  = (const float*)d_in[7];
    const float* rpb  = (const float*)d_in[8];
    const float* pw   = (const float*)d_in[9];
    const float* pb   = (const float*)d_in[10];
    const float* n2w  = (const float*)d_in[11];
    const float* n2b  = (const float*)d_in[12];
    const float* gw   = (const float*)d_in[13];
    const float* gb   = (const float*)d_in[14];
    const float* W1   = (const float*)d_in[15];
    const float* b1   = (const float*)d_in[16];
    const float* W2   = (const float*)d_in[17];
    const float* b2   = (const float*)d_in[18];
    float* out = (float*)d_out;

    const int DSMEM  = 50176;   // 48KB + align pad
    const int DSMEM1 = 66560;   // 64KB + align pad (wide FC1)
    cudaFuncSetAttribute(gemm_qkv,  cudaFuncAttributeMaxDynamicSharedMemorySize, DSMEM);
    cudaFuncSetAttribute(gemm_proj, cudaFuncAttributeMaxDynamicSharedMemorySize, DSMEM);
    cudaFuncSetAttribute(gemm_moe1, cudaFuncAttributeMaxDynamicSharedMemorySize, DSMEM1);
    cudaFuncSetAttribute(gemm_moe2, cudaFuncAttributeMaxDynamicSharedMemorySize, DSMEM);

    void *p_xout, *p_attn, *p_wp;
    cudaGetSymbolAddress(&p_xout, g_xout_bf);
    cudaGetSymbolAddress(&p_attn, g_attnbuf);
    cudaGetSymbolAddress(&p_wp,   g_wt_p);

    k_prep<<<129, 192>>>(rpb);
    k_transpose_t<<<360, 256>>>(qsw, qmw, pw, W1, W2);
    ln_partition<<<6144, 256>>>(x, n1w, n1b);
    gemm_qkv<<<dim3(384, 9, 2), 256, DSMEM>>>(qsb, qmb);   // <- profiled slot
    attn_self<<<NWIN*8, 128>>>(mask);
    attn_mut<<<NWIN*8, 128>>>(mask);
    gemm_proj<<<dim3(384, 3), 256, DSMEM>>>((const __nv_bfloat16*)p_xout,
        (const __nv_bfloat16*)p_wp, pb, (float*)p_attn, 384, 192);
    resid_gate<<<6144, 256>>>(x, n2w, n2b, gw, gb, out);
    gemm_moe1<<<dim3(384, 3, 8), 256, DSMEM1>>>(b1);
    gemm_moe2<<<dim3(384, 3, 8), 256, DSMEM>>>(b2);
    finalize<<<9216, 256>>>(out);
}

// round 10
// speedup vs baseline: 1.1829x; 1.0204x over previous
#include <cuda_runtime.h>
#include <cuda_bf16.h>
#include <math.h>
#include <cstdint>

#define TTOK 49152      // total tokens = 2*6*64*64
#define NWIN 384

// ---------------- scratch (device globals; no allocations allowed) ----------
__device__ float g_qkv_s[TTOK*576];     // qkv fp32 (self)
__device__ float g_qkv_m[TTOK*576];     // qkv fp32 (mutual)
__device__ float g_attnbuf[TTOK*192];   // proj output (window order)
__device__ float g_pos[64*192];
__device__ float g_biasf[8*128*128];    // rel-pos bias per head [h][m_key][n_query]
__device__ int   g_cnt[8];
__device__ int   g_gidx[8*TTOK];
__device__ float g_gw[8*TTOK];
__device__ int   g_grank[8*TTOK];
__device__ float g_contrib0[TTOK*192];
__device__ float g_contrib1[TTOK*192];
// bf16 activation buffers for tensor-core GEMMs
__device__ __nv_bfloat16 g_xw_bf[TTOK*192];
__device__ __nv_bfloat16 g_xm_bf[TTOK*192];
__device__ __nv_bfloat16 g_xout_bf[TTOK*384];
__device__ __nv_bfloat16 g_xn2_bf[TTOK*192];
__device__ __nv_bfloat16 g_hbuf[(size_t)8*TTOK*384];
// transposed bf16 weights [N][K]
__device__ __nv_bfloat16 g_wt_qs[576*192];
__device__ __nv_bfloat16 g_wt_qm[576*192];
__device__ __nv_bfloat16 g_wt_p [192*384];
__device__ __nv_bfloat16 g_wt_w1[8*384*192];
__device__ __nv_bfloat16 g_wt_w2[8*192*384];

// ---------------- helpers ------------------------------------------------
typedef unsigned long long ull;
__device__ __forceinline__ float warpsum_all(float v) {
    #pragma unroll
    for (int o = 16; o; o >>= 1) v += __shfl_xor_sync(0xffffffffu, v, o);
    return v;
}
__device__ __forceinline__ uint32_t smem_u32(const void* p) {
    uint32_t a;
    asm("{ .reg .u64 t; cvta.to.shared.u64 t, %1; cvt.u32.u64 %0, t; }" : "=r"(a) : "l"(p));
    return a;
}
__device__ __forceinline__ void ldsm_x4(uint32_t& r0, uint32_t& r1, uint32_t& r2,
                                        uint32_t& r3, uint32_t addr) {
    asm volatile("ldmatrix.sync.aligned.m8n8.x4.shared.b16 {%0,%1,%2,%3}, [%4];"
                 : "=r"(r0), "=r"(r1), "=r"(r2), "=r"(r3) : "r"(addr));
}
__device__ __forceinline__ void mma16816(float* c, uint32_t a0, uint32_t a1,
                                         uint32_t a2, uint32_t a3,
                                         uint32_t b0, uint32_t b1) {
    asm volatile("mma.sync.aligned.m16n8k16.row.col.f32.bf16.bf16.f32 "
        "{%0,%1,%2,%3}, {%4,%5,%6,%7}, {%8,%9}, {%0,%1,%2,%3};"
        : "+f"(c[0]), "+f"(c[1]), "+f"(c[2]), "+f"(c[3])
        : "r"(a0), "r"(a1), "r"(a2), "r"(a3), "r"(b0), "r"(b1));
}
__device__ __forceinline__ void cp16(uint32_t dst, const void* src, bool v) {
    asm volatile("cp.async.cg.shared.global [%0], [%1], 16, %2;"
                 :: "r"(dst), "l"(src), "r"(v ? 16u : 0u));
}
#define CP_COMMIT() asm volatile("cp.async.commit_group;")
#define CP_WAIT1()  asm volatile("cp.async.wait_group 1;")
#define CP_WAIT0()  asm volatile("cp.async.wait_group 0;")
#define SMEM_SWZ(o) ((o) ^ (((o) >> 3) & 0x70))

// ---- packed f32x2 ops (Blackwell FFMA2) ----
__device__ __forceinline__ ull fma2(ull a, ull b, ull c) {
    ull d;
    asm("fma.rn.f32x2 %0, %1, %2, %3;" : "=l"(d) : "l"(a), "l"(b), "l"(c));
    return d;
}
__device__ __forceinline__ ull pack2(float x, float y) {
    ull r;
    asm("mov.b64 %0, {%1,%2};" : "=l"(r) : "f"(x), "f"(y));
    return r;
}
__device__ __forceinline__ float2 unpack2(ull v) {
    float x, y;
    asm("mov.b64 {%0,%1}, %2;" : "=f"(x), "=f"(y) : "l"(v));
    return make_float2(x, y);
}

// ---- 128x64 warp-tile MMA over one 64-K chunk (8 warps: 4m x 2n) ----------
__device__ __forceinline__ void mma_tile(uint32_t aB, uint32_t bB,
                                         float (&c)[2][4][4], int wm, int wn, int lane) {
    int g = lane >> 3, l7 = lane & 7;
    #pragma unroll
    for (int ks = 0; ks < 4; ks++) {
        uint32_t a[2][4];
        #pragma unroll
        for (int mi = 0; mi < 2; mi++) {
            int r = wm*32 + mi*16 + ((g & 1) << 3) + l7;
            int kb = ks*32 + ((g >> 1) << 4);
            ldsm_x4(a[mi][0], a[mi][1], a[mi][2], a[mi][3],
                    aB + SMEM_SWZ((uint32_t)(r*128 + kb)));
        }
        uint32_t b[4][2];
        #pragma unroll
        for (int np = 0; np < 2; np++) {
            int r = wn*32 + np*16 + ((g >> 1) << 3) + l7;
            int kb = ks*32 + ((g & 1) << 4);
            uint32_t r0, r1, r2, r3;
            ldsm_x4(r0, r1, r2, r3, bB + SMEM_SWZ((uint32_t)(r*128 + kb)));
            b[np*2][0] = r0;   b[np*2][1] = r1;
            b[np*2+1][0] = r2; b[np*2+1][1] = r3;
        }
        #pragma unroll
        for (int mi = 0; mi < 2; mi++)
            #pragma unroll
            for (int nj = 0; nj < 4; nj++)
                mma16816(c[mi][nj], a[mi][0], a[mi][1], a[mi][2], a[mi][3],
                         b[nj][0], b[nj][1]);
    }
}

// ---- 128x128 wide warp-tile MMA (8 warps: 4m x 2n, 64 n-cols per warp) -----
__device__ __forceinline__ void mma_tile_w(uint32_t aB, uint32_t bB,
                                           float (&c)[2][8][4], int wm, int wn, int lane) {
    int g = lane >> 3, l7 = lane & 7;
    #pragma unroll
    for (int ks = 0; ks < 4; ks++) {
        uint32_t a[2][4];
        #pragma unroll
        for (int mi = 0; mi < 2; mi++) {
            int r = wm*32 + mi*16 + ((g & 1) << 3) + l7;
            int kb = ks*32 + ((g >> 1) << 4);
            ldsm_x4(a[mi][0], a[mi][1], a[mi][2], a[mi][3],
                    aB + SMEM_SWZ((uint32_t)(r*128 + kb)));
        }
        uint32_t b[8][2];
        #pragma unroll
        for (int np = 0; np < 4; np++) {
            int r = wn*64 + np*16 + ((g >> 1) << 3) + l7;
            int kb = ks*32 + ((g & 1) << 4);
            uint32_t r0, r1, r2, r3;
            ldsm_x4(r0, r1, r2, r3, bB + SMEM_SWZ((uint32_t)(r*128 + kb)));
            b[np*2][0] = r0;   b[np*2][1] = r1;
            b[np*2+1][0] = r2; b[np*2+1][1] = r3;
        }
        #pragma unroll
        for (int mi = 0; mi < 2; mi++)
            #pragma unroll
            for (int nj = 0; nj < 8; nj++)
                mma16816(c[mi][nj], a[mi][0], a[mi][1], a[mi][2], a[mi][3],
                         b[nj][0], b[nj][1]);
    }
}

// ---- shared mode-0 GEMM core: C fp32 = A @ Bt^T + bias ---------------------
__device__ __forceinline__ void gemm_core0(
        const __nv_bfloat16* __restrict__ A,
        const __nv_bfloat16* __restrict__ Bt,
        const float* __restrict__ bias,
        float* __restrict__ Cf, int K, int ldC, uint8_t* dyn_raw) {
    int tid = threadIdx.x, wid = tid >> 5, lane = tid & 31;
    int wm = wid >> 1, wn = wid & 1;
    int row0 = blockIdx.x * 128, col0 = blockIdx.y * 64;

    uint32_t aBase = (smem_u32(dyn_raw) + 1023u) & ~1023u;
    uint32_t bBase = aBase + 32768;

    int srow = tid >> 3, c16 = tid & 7;
    const __nv_bfloat16* arp[4]; uint32_t aOff[4];
    #pragma unroll
    for (int i = 0; i < 4; i++) {
        int r = i*32 + srow;
        aOff[i] = SMEM_SWZ((uint32_t)(r*128 + c16*16));
        arp[i] = A + (size_t)(row0 + r)*K + c16*8;
    }
    const __nv_bfloat16* brp[2]; uint32_t bOff[2];
    #pragma unroll
    for (int i = 0; i < 2; i++) {
        int r = i*32 + srow;
        bOff[i] = SMEM_SWZ((uint32_t)(r*128 + c16*16));
        brp[i] = Bt + (size_t)(col0 + r)*K + c16*8;
    }

    float c[2][4][4] = {};
    int nch = K >> 6;

    #pragma unroll
    for (int i = 0; i < 4; i++) cp16(aBase + aOff[i], arp[i], true);
    #pragma unroll
    for (int i = 0; i < 2; i++) cp16(bBase + bOff[i], brp[i], true);
    CP_COMMIT();

    for (int ic = 0; ic < nch; ic++) {
        if (ic + 1 < nch) {
            int buf = (ic + 1) & 1, kc = (ic + 1) << 6;
            #pragma unroll
            for (int i = 0; i < 4; i++)
                cp16(aBase + buf*16384 + aOff[i], arp[i] + kc, true);
            #pragma unroll
            for (int i = 0; i < 2; i++)
                cp16(bBase + buf*8192 + bOff[i], brp[i] + kc, true);
            CP_COMMIT();
            CP_WAIT1();
        } else {
            CP_WAIT0();
        }
        __syncthreads();
        mma_tile(aBase + (ic & 1)*16384, bBase + (ic & 1)*8192, c, wm, wn, lane);
        __syncthreads();
    }

    int qr = lane >> 2, qc = (lane & 3) * 2;
    #pragma unroll
    for (int mi = 0; mi < 2; mi++) {
        #pragma unroll
        for (int h = 0; h < 2; h++) {
            int lr = wm*32 + mi*16 + h*8 + qr;
            #pragma unroll
            for (int nj = 0; nj < 4; nj++) {
                int col = col0 + wn*32 + nj*8 + qc;
                size_t crow = (size_t)(row0 + lr)*ldC + col;
                *reinterpret_cast<float2*>(Cf + crow) =
                    make_float2(c[mi][nj][2*h] + bias[col],
                                c[mi][nj][2*h+1] + bias[col+1]);
            }
        }
    }
}

// ---- merged QKV GEMM: z=0 self, z=1 mutual ----------------------------------
__global__ __launch_bounds__(256, 3) void gemm_qkv(const float* __restrict__ qsb,
                                                   const float* __restrict__ qmb) {
    extern __shared__ uint8_t dyn_raw[];
    if (blockIdx.z == 0)
        gemm_core0(g_xw_bf, g_wt_qs, qsb, g_qkv_s, 192, 576, dyn_raw);
    else
        gemm_core0(g_xm_bf, g_wt_qm, qmb, g_qkv_m, 192, 576, dyn_raw);
}

// ---- proj GEMM ---------------------------------------------------------------
__global__ __launch_bounds__(256, 3) void gemm_proj(
        const __nv_bfloat16* __restrict__ A, const __nv_bfloat16* __restrict__ Bt,
        const float* __restrict__ bias, float* __restrict__ Cf, int K, int ldC) {
    extern __shared__ uint8_t dyn_raw[];
    gemm_core0(A, Bt, bias, Cf, K, ldC, dyn_raw);
}

// ======= MoE FC1: gather + gelu -> g_hbuf, wide 128x128 tile, K=192 =========
__global__ __launch_bounds__(256) void gemm_moe1(const float* __restrict__ b1) {
    extern __shared__ uint8_t dyn_raw[];
    __shared__ int s_tok[128];
    int tid = threadIdx.x, wid = tid >> 5, lane = tid & 31;
    int wm = wid >> 1, wn = wid & 1;
    int row0 = blockIdx.x * 128, col0 = blockIdx.y * 128;
    int e = blockIdx.z;
    int cnt = g_cnt[e];
    if (row0 >= cnt) return;
    const __nv_bfloat16* W1te = g_wt_w1 + (size_t)e*73728;
    const float* b1e = b1 + e*384;

    if (tid < 128) {
        int slot = row0 + tid;
        s_tok[tid] = (slot < cnt) ? g_gidx[e*TTOK + slot] : -1;
    }
    __syncthreads();

    uint32_t aBase = (smem_u32(dyn_raw) + 1023u) & ~1023u;
    uint32_t bBase = aBase + 32768;

    int srow = tid >> 3, c16 = tid & 7;
    const __nv_bfloat16* arp[4]; bool av[4]; uint32_t off[4];
    const __nv_bfloat16* brp[4];
    #pragma unroll
    for (int i = 0; i < 4; i++) {
        int r = i*32 + srow;
        off[i] = SMEM_SWZ((uint32_t)(r*128 + c16*16));
        int tk = s_tok[r];
        av[i] = (tk >= 0);
        arp[i] = g_xn2_bf + (size_t)(av[i] ? tk : 0)*192 + c16*8;
        brp[i] = W1te + (size_t)(col0 + r)*192 + c16*8;
    }

    float c[2][8][4] = {};

    #pragma unroll
    for (int i = 0; i < 4; i++) cp16(aBase + off[i], arp[i], av[i]);
    #pragma unroll
    for (int i = 0; i < 4; i++) cp16(bBase + off[i], brp[i], true);
    CP_COMMIT();

    for (int ic = 0; ic < 3; ic++) {
        if (ic + 1 < 3) {
            int buf = (ic + 1) & 1, kc = (ic + 1) << 6;
            #pragma unroll
            for (int i = 0; i < 4; i++)
                cp16(aBase + buf*16384 + off[i], arp[i] + kc, av[i]);
            #pragma unroll
            for (int i = 0; i < 4; i++)
                cp16(bBase + buf*16384 + off[i], brp[i] + kc, true);
            CP_COMMIT();
            CP_WAIT1();
        } else {
            CP_WAIT0();
        }
        __syncthreads();
        mma_tile_w(aBase + (ic & 1)*16384, bBase + (ic & 1)*16384, c, wm, wn, lane);
        __syncthreads();
    }

    int qr = lane >> 2, qc = (lane & 3) * 2;
    #pragma unroll
    for (int mi = 0; mi < 2; mi++) {
        #pragma unroll
        for (int h = 0; h < 2; h++) {
            int lr = wm*32 + mi*16 + h*8 + qr;
            if (s_tok[lr] >= 0) {
                size_t hrow = ((size_t)e*TTOK + row0 + lr)*384;
                #pragma unroll
                for (int nj = 0; nj < 8; nj++) {
                    int col = col0 + wn*64 + nj*8 + qc;
                    float h0 = c[mi][nj][2*h]   + b1e[col];
                    float h1 = c[mi][nj][2*h+1] + b1e[col+1];
                    h0 = h0 * normcdff(h0);
                    h1 = h1 * normcdff(h1);
                    __nv_bfloat162 p;
                    p.x = __float2bfloat16_rn(h0); p.y = __float2bfloat16_rn(h1);
                    *reinterpret_cast<__nv_bfloat162*>(g_hbuf + hrow + col) = p;
                }
            }
        }
    }
}

// ======= MoE FC2: weighted scatter -> contrib buffers, K=384 ================
__global__ __launch_bounds__(256, 3) void gemm_moe2(const float* __restrict__ b2) {
    extern __shared__ uint8_t dyn_raw[];
    __shared__ int s_tok[128]; __shared__ float s_wgt[128]; __shared__ int s_rnk[128];

    int tid = threadIdx.x, wid = tid >> 5, lane = tid & 31;
    int wm = wid >> 1, wn = wid & 1;
    int row0 = blockIdx.x * 128, col0 = blockIdx.y * 64;
    int e = blockIdx.z;
    int cnt = g_cnt[e];
    if (row0 >= cnt) return;
    const __nv_bfloat16* Bte = g_wt_w2 + (size_t)e*73728;
    const float* be = b2 + e*192;
    const __nv_bfloat16* Ae = g_hbuf + (size_t)e*TTOK*384;

    if (tid < 128) {
        int slot = row0 + tid;
        if (slot < cnt) {
            s_tok[tid] = g_gidx[e*TTOK + slot];
            s_wgt[tid] = g_gw[e*TTOK + slot];
            s_rnk[tid] = g_grank[e*TTOK + slot];
        } else s_tok[tid] = -1;
    }
    __syncthreads();

    uint32_t aBase = (smem_u32(dyn_raw) + 1023u) & ~1023u;
    uint32_t bBase = aBase + 32768;

    int srow = tid >> 3, c16 = tid & 7;
    const __nv_bfloat16* arp[4]; bool av[4]; uint32_t aOff[4];
    #pragma unroll
    for (int i = 0; i < 4; i++) {
        int r = i*32 + srow;
        aOff[i] = SMEM_SWZ((uint32_t)(r*128 + c16*16));
        av[i] = (row0 + r < cnt);
        arp[i] = Ae + (size_t)(av[i] ? (row0 + r) : 0)*384 + c16*8;
    }
    const __nv_bfloat16* brp[2]; uint32_t bOff[2];
    #pragma unroll
    for (int i = 0; i < 2; i++) {
        int r = i*32 + srow;
        bOff[i] = SMEM_SWZ((uint32_t)(r*128 + c16*16));
        brp[i] = Bte + (size_t)(col0 + r)*384 + c16*8;
    }

    float c[2][4][4] = {};

    #pragma unroll
    for (int i = 0; i < 4; i++) cp16(aBase + aOff[i], arp[i], av[i]);
    #pragma unroll
    for (int i = 0; i < 2; i++) cp16(bBase + bOff[i], brp[i], true);
    CP_COMMIT();

    for (int ic = 0; ic < 6; ic++) {
        if (ic + 1 < 6) {
            int buf = (ic + 1) & 1, kc = (ic + 1) << 6;
            #pragma unroll
            for (int i = 0; i < 4; i++)
                cp16(aBase + buf*16384 + aOff[i], arp[i] + kc, av[i]);
            #pragma unroll
            for (int i = 0; i < 2; i++)
                cp16(bBase + buf*8192 + bOff[i], brp[i] + kc, true);
            CP_COMMIT();
            CP_WAIT1();
        } else {
            CP_WAIT0();
        }
        __syncthreads();
        mma_tile(aBase + (ic & 1)*16384, bBase + (ic & 1)*8192, c, wm, wn, lane);
        __syncthreads();
    }

    int qr = lane >> 2, qc = (lane & 3) * 2;
    #pragma unroll
    for (int mi = 0; mi < 2; mi++) {
        #pragma unroll
        for (int h = 0; h < 2; h++) {
            int lr = wm*32 + mi*16 + h*8 + qr;
            int tk = s_tok[lr];
            if (tk >= 0) {
                float w = s_wgt[lr];
                float* dst = (s_rnk[lr] == 0) ? g_contrib0 : g_contrib1;
                #pragma unroll
                for (int nj = 0; nj < 4; nj++) {
                    int col = col0 + wn*32 + nj*8 + qc;
                    *reinterpret_cast<float2*>(dst + (size_t)tk*192 + col) =
                        make_float2(w*(c[mi][nj][2*h]   + be[col]),
                                    w*(c[mi][nj][2*h+1] + be[col+1]));
                }
            }
        }
    }
}

// ---- merged prep: transpose (0-359) | bias (360-487) | pos+cnt (488) --------
__global__ __launch_bounds__(256) void k_prep_all(
        const float* __restrict__ qs, const float* __restrict__ qm,
        const float* __restrict__ pw, const float* __restrict__ W1,
        const float* __restrict__ W2, const float* __restrict__ rpb) {
    __shared__ float tile[64][65];
    int bid = blockIdx.x;
    if (bid < 360) {
        const float* src; __nv_bfloat16* dst; int K, N, tk, tn;
        if (bid < 27)       { src = qs; dst = g_wt_qs; K = 192; N = 576; tk = bid/9; tn = bid%9; }
        else if (bid < 54)  { int j = bid-27; src = qm; dst = g_wt_qm; K = 192; N = 576; tk = j/9; tn = j%9; }
        else if (bid < 72)  { int j = bid-54; src = pw; dst = g_wt_p;  K = 384; N = 192; tk = j/3; tn = j%3; }
        else if (bid < 216) { int j = bid-72;  int e = j/18; j %= 18;
                              src = W1 + (size_t)e*73728; dst = g_wt_w1 + (size_t)e*73728;
                              K = 192; N = 384; tk = j/6; tn = j%6; }
        else                { int j = bid-216; int e = j/18; j %= 18;
                              src = W2 + (size_t)e*73728; dst = g_wt_w2 + (size_t)e*73728;
                              K = 384; N = 192; tk = j/3; tn = j%3; }
        int rr = threadIdx.x >> 6, cc = threadIdx.x & 63;
        #pragma unroll 4
        for (int i = 0; i < 16; i++) {
            int r = rr + 4*i;
            tile[r][cc] = src[(size_t)(tk*64 + r)*N + tn*64 + cc];
        }
        __syncthreads();
        #pragma unroll 4
        for (int i = 0; i < 16; i++) {
            int r = rr + 4*i;
            dst[(size_t)(tn*64 + r)*K + tk*64 + cc] = __float2bfloat16_rn(tile[cc][r]);
        }
    } else if (bid < 488) {
        int n = threadIdx.x;
        if (n >= 128) return;
        int m = bid - 360;                   // m = key
        int dn = n >> 6, hn = (n >> 3) & 7, wn = n & 7;
        int dm = m >> 6, hm = (m >> 3) & 7, wm = m & 7;
        int rp = (dn - dm + 1)*225 + (hn - hm + 7)*15 + (wn - wm + 7);
        #pragma unroll
        for (int h = 0; h < 8; h++)
            g_biasf[h*16384 + m*128 + n] = rpb[rp*8 + h];
    } else {
        int c = threadIdx.x;
        if (c >= 192) return;
        if (c < 8) g_cnt[c] = 0;
        const float TWO_PI = 6.283185307179586f;
        const float denom = 8.0f + 1e-6f;
        int f = (c < 96) ? c : c - 96;
        float expo = (float)(f & ~1) / 96.0f;
        float dt = powf(10000.0f, expo);
        for (int n = 0; n < 64; n++) {
            int i = n >> 3, j = n & 7;
            float base = (c < 96) ? (float)(i + 1) : (float)(j + 1);
            float v = base / denom * TWO_PI / dt;
            g_pos[n*192 + c] = (f & 1) ? cosf(v) : sinf(v);
        }
    }
}

// ---------------- LN1 + roll + window partition -> bf16 (warp per token) -----
__global__ __launch_bounds__(256) void ln_partition(const float* __restrict__ x,
                             const float* __restrict__ w1,
                             const float* __restrict__ b1) {
    int t = (blockIdx.x*blockDim.x + threadIdx.x) >> 5;
    int lane = threadIdx.x & 31;
    int win = t >> 7, n = t & 127;
    int b_  = win / 192; int rem = win % 192;
    int dd  = rem / 64;  int rem2 = rem % 64;
    int hh  = rem2 >> 3; int ww = rem2 & 7;
    int wd  = n >> 6, wh = (n >> 3) & 7, wwp = n & 7;
    int ds = dd*2 + wd, hs = hh*8 + wh, ws = ww*8 + wwp;
    int d = ds + 1; if (d >= 6) d -= 6;
    int h = (hs + 4) & 63;
    int w = (ws + 4) & 63;
    const float* xr = x + (size_t)(((b_*6 + d)*64 + h)*64 + w)*192;
    float v[6];
    float s1 = 0.f, s2 = 0.f;
    #pragma unroll
    for (int k = 0; k < 6; k++) {
        v[k] = xr[lane + 32*k];
        s1 += v[k]; s2 += v[k]*v[k];
    }
    s1 = warpsum_all(s1); s2 = warpsum_all(s2);
    float mu  = s1 * (1.f/192.f);
    float var = s2 * (1.f/192.f) - mu*mu;
    float rstd = rsqrtf(var + 1e-5f);
    const float* pr = g_pos + (n & 63)*192;
    #pragma unroll
    for (int k = 0; k < 6; k++) {
        int cc = lane + 32*k;
        float y = (v[k] - mu) * rstd * w1[cc] + b1[cc];
        g_xw_bf[(size_t)t*192 + cc] = __float2bfloat16_rn(y);
        g_xm_bf[(size_t)t*192 + cc] = __float2bfloat16_rn(y + pr[cc]);
    }
}

// ---------------- self attention: flash-style, LDS.128 + f32x2 ---------------
#define KVS 28   // padded row stride (floats): 112B, 16B-aligned rows
__global__ __launch_bounds__(128) void attn_self(const float* __restrict__ mask) {
    __shared__ __align__(16) float ks[128*KVS];
    __shared__ __align__(16) float vs[128*KVS];
    int win = blockIdx.x >> 3, h = blockIdx.x & 7;
    int n = threadIdx.x;
    size_t base = (size_t)(win*128 + n)*576 + h*24;
    const float4* qp = reinterpret_cast<const float4*>(g_qkv_s + base);
    const float4* kp = reinterpret_cast<const float4*>(g_qkv_s + base + 192);
    const float4* vp = reinterpret_cast<const float4*>(g_qkv_s + base + 384);
    const float SC = 0.20412414523193154f;   // 24^-0.5
    ull q2[12];
    #pragma unroll
    for (int i = 0; i < 6; i++) {
        float4 a = qp[i];
        q2[2*i]   = pack2(a.x*SC, a.y*SC);
        q2[2*i+1] = pack2(a.z*SC, a.w*SC);
        *reinterpret_cast<float4*>(&ks[n*KVS + 4*i]) = kp[i];
        *reinterpret_cast<float4*>(&vs[n*KVS + 4*i]) = vp[i];
    }
    __syncthreads();
    const float* mrow = mask + (size_t)(win % 192)*16384;
    const float* brow = g_biasf + (size_t)h*16384;
    ull o2[12] = {};
    float ssum = 0.f;
    #pragma unroll 2
    for (int m = 0; m < 128; m++) {
        const ulonglong2* kr = reinterpret_cast<const ulonglong2*>(ks + m*KVS);
        ull acc = 0ull;
        #pragma unroll
        for (int i = 0; i < 6; i++) {
            ulonglong2 t = kr[i];
            acc = fma2(q2[2*i], t.x, acc);
            acc = fma2(q2[2*i+1], t.y, acc);
        }
        float2 ac = unpack2(acc);
        float s = ac.x + ac.y + mrow[m*128 + n] + brow[m*128 + n];
        float p = __expf(s);
        ssum += p;
        ull pp = pack2(p, p);
        const ulonglong2* vr = reinterpret_cast<const ulonglong2*>(vs + m*KVS);
        #pragma unroll
        for (int i = 0; i < 6; i++) {
            ulonglong2 t = vr[i];
            o2[2*i]   = fma2(t.x, pp, o2[2*i]);
            o2[2*i+1] = fma2(t.y, pp, o2[2*i+1]);
        }
    }
    float inv = 1.f / ssum;
    __nv_bfloat162* ob = reinterpret_cast<__nv_bfloat162*>(
        g_xout_bf + (size_t)(win*128 + n)*384 + 192 + h*24);
    #pragma unroll
    for (int i = 0; i < 12; i++) {
        float2 o = unpack2(o2[i]);
        __nv_bfloat162 p;
        p.x = __float2bfloat16_rn(o.x*inv);
        p.y = __float2bfloat16_rn(o.y*inv);
        ob[i] = p;
    }
}

// ---------------- mutual attention: flash-style, LDS.128 + f32x2 -------------
__global__ __launch_bounds__(128) void attn_mut(const float* __restrict__ mask) {
    __shared__ __align__(16) float ks[2][64*KVS];
    __shared__ __align__(16) float vs[2][64*KVS];
    int win = blockIdx.x >> 3, h = blockIdx.x & 7;
    int tid = threadIdx.x;
    int p = tid >> 6, r = tid & 63;
    int kvtok = (p == 0) ? r : 64 + r;
    int qtok  = (p == 0) ? 64 + r : r;
    size_t kb = (size_t)(win*128 + kvtok)*576 + h*24;
    size_t qb = (size_t)(win*128 + qtok)*576 + h*24;
    const float4* qp = reinterpret_cast<const float4*>(g_qkv_m + qb);
    const float4* kp = reinterpret_cast<const float4*>(g_qkv_m + kb + 192);
    const float4* vp = reinterpret_cast<const float4*>(g_qkv_m + kb + 384);
    const float SC = 0.20412414523193154f;
    ull q2[12];
    #pragma unroll
    for (int i = 0; i < 6; i++) {
        float4 a = qp[i];
        q2[2*i]   = pack2(a.x*SC, a.y*SC);
        q2[2*i+1] = pack2(a.z*SC, a.w*SC);
        *reinterpret_cast<float4*>(&ks[p][r*KVS + 4*i]) = kp[i];
        *reinterpret_cast<float4*>(&vs[p][r*KVS + 4*i]) = vp[i];
    }
    __syncthreads();
    const float* mrow = mask + (size_t)(win % 192)*16384;
    ull o2[12] = {};
    float ssum = 0.f;
    #pragma unroll 2
    for (int m = 0; m < 64; m++) {
        const ulonglong2* kr = reinterpret_cast<const ulonglong2*>(&ks[p][m*KVS]);
        ull acc = 0ull;
        #pragma unroll
        for (int i = 0; i < 6; i++) {
            ulonglong2 t = kr[i];
            acc = fma2(q2[2*i], t.x, acc);
            acc = fma2(q2[2*i+1], t.y, acc);
        }
        float2 ac = unpack2(acc);
        float s = ac.x + ac.y + mrow[m*128 + r];   // mask symmetric
        float pv = __expf(s);
        ssum += pv;
        ull pp = pack2(pv, pv);
        const ulonglong2* vr = reinterpret_cast<const ulonglong2*>(&vs[p][m*KVS]);
        #pragma unroll
        for (int i = 0; i < 6; i++) {
            ulonglong2 t = vr[i];
            o2[2*i]   = fma2(t.x, pp, o2[2*i]);
            o2[2*i+1] = fma2(t.y, pp, o2[2*i+1]);
        }
    }
    float inv = 1.f / ssum;
    int orow = (p == 0) ? r : 64 + r;
    __nv_bfloat162* ob = reinterpret_cast<__nv_bfloat162*>(
        g_xout_bf + (size_t)(win*128 + orow)*384 + h*24);
    #pragma unroll
    for (int i = 0; i < 12; i++) {
        float2 o = unpack2(o2[i]);
        __nv_bfloat162 pr;
        pr.x = __float2bfloat16_rn(o.x*inv);
        pr.y = __float2bfloat16_rn(o.y*inv);
        ob[i] = pr;
    }
}

// --------- residual (writes out directly) + LN2 + gate top-2 -----------------
__global__ __launch_bounds__(256) void resid_gate(const float* __restrict__ x,
                           const float* __restrict__ n2w, const float* __restrict__ n2b,
                           const float* __restrict__ gw,  const float* __restrict__ gb,
                           float* __restrict__ out) {
    __shared__ float s_gw[8*192];
    for (int i = threadIdx.x; i < 1536; i += 256) {
        int j = i / 192, cc = i % 192;
        s_gw[i] = gw[cc*8 + j];
    }
    __syncthreads();
    int t = (blockIdx.x*blockDim.x + threadIdx.x) >> 5;
    int lane = threadIdx.x & 31;
    int b_ = t / 24576; int rrem = t % 24576;
    int d  = rrem / 4096; int r2 = rrem % 4096;
    int hh_ = r2 / 64; int ww_ = r2 % 64;
    int ds = d - 1; if (ds < 0) ds += 6;
    int hs = (hh_ + 60) & 63;
    int ws = (ww_ + 60) & 63;
    int dd = ds >> 1, wd = ds & 1;
    int hblk = hs >> 3, wh = hs & 7;
    int wblk = ws >> 3, wwp = ws & 7;
    int win = ((b_*3 + dd)*8 + hblk)*8 + wblk;
    int n = wd*64 + wh*8 + wwp;
    const float* ar = g_attnbuf + (size_t)(win*128 + n)*192;
    const float* xr = x + (size_t)t*192;
    float v[6];
    float s1 = 0.f, s2 = 0.f;
    #pragma unroll
    for (int k = 0; k < 6; k++) {
        int cc = lane + 32*k;
        v[k] = xr[cc] + ar[cc];
        out[(size_t)t*192 + cc] = v[k];
        s1 += v[k]; s2 += v[k]*v[k];
    }
    s1 = warpsum_all(s1); s2 = warpsum_all(s2);
    float mu  = s1 * (1.f/192.f);
    float var = s2 * (1.f/192.f) - mu*mu;
    float rstd = rsqrtf(var + 1e-5f);
    float g[8] = {};
    #pragma unroll
    for (int k = 0; k < 6; k++) {
        int cc = lane + 32*k;
        float xn = (v[k] - mu) * rstd * n2w[cc] + n2b[cc];
        g_xn2_bf[(size_t)t*192 + cc] = __float2bfloat16_rn(xn);
        #pragma unroll
        for (int j = 0; j < 8; j++) g[j] = fmaf(xn, s_gw[j*192 + cc], g[j]);
    }
    #pragma unroll
    for (int j = 0; j < 8; j++) g[j] = warpsum_all(g[j]);
    if (lane == 0) {
        float L[8];
        #pragma unroll
        for (int j = 0; j < 8; j++) L[j] = g[j] + gb[j];
        int e0 = 0;
        #pragma unroll
        for (int j = 1; j < 8; j++) if (L[j] > L[e0]) e0 = j;
        int e1 = (e0 == 0) ? 1 : 0;
        #pragma unroll
        for (int j = 0; j < 8; j++) if (j != e0 && L[j] > L[e1]) e1 = j;
        float w0 = 1.f / (1.f + __expf(L[e1] - L[e0]));
        float w1 = 1.f - w0;
        int p0 = atomicAdd(&g_cnt[e0], 1);
        g_gidx[e0*TTOK + p0] = t; g_gw[e0*TTOK + p0] = w0; g_grank[e0*TTOK + p0] = 0;
        int p1 = atomicAdd(&g_cnt[e1], 1);
        g_gidx[e1*TTOK + p1] = t; g_gw[e1*TTOK + p1] = w1; g_grank[e1*TTOK + p1] = 1;
    }
}

// ---------------- finalize: out += contrib0 + contrib1 -----------------------
__global__ void finalize(float* __restrict__ out) {
    int i = blockIdx.x*blockDim.x + threadIdx.x;
    if (i < TTOK*48) {
        float4 a  = reinterpret_cast<const float4*>(out)[i];
        float4 c0 = reinterpret_cast<const float4*>(g_contrib0)[i];
        float4 c1 = reinterpret_cast<const float4*>(g_contrib1)[i];
        reinterpret_cast<float4*>(out)[i] =
            make_float4(a.x + c0.x + c1.x, a.y + c0.y + c1.y,
                        a.z + c0.z + c1.z, a.w + c0.w + c1.w);
    }
}

// ---------------- host launcher -----------------------------------------------
extern "C" void kernel_launch(void* const* d_in, const int* in_sizes, int n_in,
                              void* d_out, int out_size) {
    const float* x    = (const float*)d_in[0];
    const float* mask = (const float*)d_in[1];
    const float* n1w  = (const float*)d_in[2];
    const float* n1b  = (const float*)d_in[3];
    const float* qsw  = (const float*)d_in[4];
    const float* qsb  = (const float*)d_in[5];
    const float* qmw  = (const float*)d_in[6];
    const float* qmb  = (const float*)d_in[7];
    const float* rpb  = (const float*)d_in[8];
    const float* pw   = (const float*)d_in[9];
    const float* pb   = (const float*)d_in[10];
    const float* n2w  = (const float*)d_in[11];
    const float* n2b  = (const float*)d_in[12];
    const float* gw   = (const float*)d_in[13];
    const float* gb   = (const float*)d_in[14];
    const float* W1   = (const float*)d_in[15];
    const float* b1   = (const float*)d_in[16];
    const float* W2   = (const float*)d_in[17];
    const float* b2   = (const float*)d_in[18];
    float* out = (float*)d_out;

    const int DSMEM  = 50176;   // 48KB + align pad
    const int DSMEM1 = 66560;   // 64KB + align pad (wide FC1)
    cudaFuncSetAttribute(gemm_qkv,  cudaFuncAttributeMaxDynamicSharedMemorySize, DSMEM);
    cudaFuncSetAttribute(gemm_proj, cudaFuncAttributeMaxDynamicSharedMemorySize, DSMEM);
    cudaFuncSetAttribute(gemm_moe1, cudaFuncAttributeMaxDynamicSharedMemorySize, DSMEM1);
    cudaFuncSetAttribute(gemm_moe2, cudaFuncAttributeMaxDynamicSharedMemorySize, DSMEM);

    void *p_xout, *p_attn, *p_wp;
    cudaGetSymbolAddress(&p_xout, g_xout_bf);
    cudaGetSymbolAddress(&p_attn, g_attnbuf);
    cudaGetSymbolAddress(&p_wp,   g_wt_p);

    k_prep_all<<<489, 256>>>(qsw, qmw, pw, W1, W2, rpb);
    ln_partition<<<6144, 256>>>(x, n1w, n1b);
    gemm_qkv<<<dim3(384, 9, 2), 256, DSMEM>>>(qsb, qmb);
    attn_self<<<NWIN*8, 128>>>(mask);                      // <- profiled slot
    attn_mut<<<NWIN*8, 128>>>(mask);
    gemm_proj<<<dim3(384, 3), 256, DSMEM>>>((const __nv_bfloat16*)p_xout,
        (const __nv_bfloat16*)p_wp, pb, (float*)p_attn, 384, 192);
    resid_gate<<<6144, 256>>>(x, n2w, n2b, gw, gb, out);
    gemm_moe1<<<dim3(384, 3, 8), 256, DSMEM1>>>(b1);
    gemm_moe2<<<dim3(384, 3, 8), 256, DSMEM>>>(b2);
    finalize<<<9216, 256>>>(out);
}

// round 11
// speedup vs baseline: 1.3772x; 1.1643x over previous
#include <cuda_runtime.h>
#include <cuda_bf16.h>
#include <math.h>
#include <cstdint>

#define TTOK 49152      // total tokens = 2*6*64*64
#define NWIN 384

// ---------------- scratch (device globals; no allocations allowed) ----------
__device__ float g_qkv_s[TTOK*576];     // qkv fp32 (self)
__device__ float g_qkv_m[TTOK*576];     // qkv fp32 (mutual)
__device__ float g_attnbuf[TTOK*192];   // proj output (window order)
__device__ float g_pos[64*192];
__device__ float g_biasf[8*128*128];    // rel-pos bias per head [h][q][k] (transposed!)
__device__ int   g_cnt[8];
__device__ int   g_gidx[8*TTOK];
__device__ float g_gw[8*TTOK];
__device__ int   g_grank[8*TTOK];
__device__ float g_contrib0[TTOK*192];
__device__ float g_contrib1[TTOK*192];
// bf16 activation buffers for tensor-core GEMMs
__device__ __nv_bfloat16 g_xw_bf[TTOK*192];
__device__ __nv_bfloat16 g_xm_bf[TTOK*192];
__device__ __nv_bfloat16 g_xout_bf[TTOK*384];
__device__ __nv_bfloat16 g_xn2_bf[TTOK*192];
__device__ __nv_bfloat16 g_hbuf[(size_t)8*TTOK*384];
// transposed bf16 weights [N][K]
__device__ __nv_bfloat16 g_wt_qs[576*192];
__device__ __nv_bfloat16 g_wt_qm[576*192];
__device__ __nv_bfloat16 g_wt_p [192*384];
__device__ __nv_bfloat16 g_wt_w1[8*384*192];
__device__ __nv_bfloat16 g_wt_w2[8*192*384];

// ---------------- helpers ------------------------------------------------
typedef unsigned long long ull;
__device__ __forceinline__ float warpsum_all(float v) {
    #pragma unroll
    for (int o = 16; o; o >>= 1) v += __shfl_xor_sync(0xffffffffu, v, o);
    return v;
}
__device__ __forceinline__ uint32_t smem_u32(const void* p) {
    uint32_t a;
    asm("{ .reg .u64 t; cvta.to.shared.u64 t, %1; cvt.u32.u64 %0, t; }" : "=r"(a) : "l"(p));
    return a;
}
__device__ __forceinline__ void ldsm_x4(uint32_t& r0, uint32_t& r1, uint32_t& r2,
                                        uint32_t& r3, uint32_t addr) {
    asm volatile("ldmatrix.sync.aligned.m8n8.x4.shared.b16 {%0,%1,%2,%3}, [%4];"
                 : "=r"(r0), "=r"(r1), "=r"(r2), "=r"(r3) : "r"(addr));
}
__device__ __forceinline__ void mma16816(float* c, uint32_t a0, uint32_t a1,
                                         uint32_t a2, uint32_t a3,
                                         uint32_t b0, uint32_t b1) {
    asm volatile("mma.sync.aligned.m16n8k16.row.col.f32.bf16.bf16.f32 "
        "{%0,%1,%2,%3}, {%4,%5,%6,%7}, {%8,%9}, {%0,%1,%2,%3};"
        : "+f"(c[0]), "+f"(c[1]), "+f"(c[2]), "+f"(c[3])
        : "r"(a0), "r"(a1), "r"(a2), "r"(a3), "r"(b0), "r"(b1));
}
__device__ __forceinline__ void cp16(uint32_t dst, const void* src, bool v) {
    asm volatile("cp.async.cg.shared.global [%0], [%1], 16, %2;"
                 :: "r"(dst), "l"(src), "r"(v ? 16u : 0u));
}
#define CP_COMMIT() asm volatile("cp.async.commit_group;")
#define CP_WAIT1()  asm volatile("cp.async.wait_group 1;")
#define CP_WAIT0()  asm volatile("cp.async.wait_group 0;")
#define SMEM_SWZ(o) ((o) ^ (((o) >> 3) & 0x70))

__device__ __forceinline__ uint32_t bf2(float x, float y) {
    __nv_bfloat162 t = __floats2bfloat162_rn(x, y);
    return *reinterpret_cast<uint32_t*>(&t);
}

// ---- 128x64 warp-tile MMA over one 64-K chunk (8 warps: 4m x 2n) ----------
__device__ __forceinline__ void mma_tile(uint32_t aB, uint32_t bB,
                                         float (&c)[2][4][4], int wm, int wn, int lane) {
    int g = lane >> 3, l7 = lane & 7;
    #pragma unroll
    for (int ks = 0; ks < 4; ks++) {
        uint32_t a[2][4];
        #pragma unroll
        for (int mi = 0; mi < 2; mi++) {
            int r = wm*32 + mi*16 + ((g & 1) << 3) + l7;
            int kb = ks*32 + ((g >> 1) << 4);
            ldsm_x4(a[mi][0], a[mi][1], a[mi][2], a[mi][3],
                    aB + SMEM_SWZ((uint32_t)(r*128 + kb)));
        }
        uint32_t b[4][2];
        #pragma unroll
        for (int np = 0; np < 2; np++) {
            int r = wn*32 + np*16 + ((g >> 1) << 3) + l7;
            int kb = ks*32 + ((g & 1) << 4);
            uint32_t r0, r1, r2, r3;
            ldsm_x4(r0, r1, r2, r3, bB + SMEM_SWZ((uint32_t)(r*128 + kb)));
            b[np*2][0] = r0;   b[np*2][1] = r1;
            b[np*2+1][0] = r2; b[np*2+1][1] = r3;
        }
        #pragma unroll
        for (int mi = 0; mi < 2; mi++)
            #pragma unroll
            for (int nj = 0; nj < 4; nj++)
                mma16816(c[mi][nj], a[mi][0], a[mi][1], a[mi][2], a[mi][3],
                         b[nj][0], b[nj][1]);
    }
}

// ---- 128x128 wide warp-tile MMA (8 warps: 4m x 2n, 64 n-cols per warp) -----
__device__ __forceinline__ void mma_tile_w(uint32_t aB, uint32_t bB,
                                           float (&c)[2][8][4], int wm, int wn, int lane) {
    int g = lane >> 3, l7 = lane & 7;
    #pragma unroll
    for (int ks = 0; ks < 4; ks++) {
        uint32_t a[2][4];
        #pragma unroll
        for (int mi = 0; mi < 2; mi++) {
            int r = wm*32 + mi*16 + ((g & 1) << 3) + l7;
            int kb = ks*32 + ((g >> 1) << 4);
            ldsm_x4(a[mi][0], a[mi][1], a[mi][2], a[mi][3],
                    aB + SMEM_SWZ((uint32_t)(r*128 + kb)));
        }
        uint32_t b[8][2];
        #pragma unroll
        for (int np = 0; np < 4; np++) {
            int r = wn*64 + np*16 + ((g >> 1) << 3) + l7;
            int kb = ks*32 + ((g & 1) << 4);
            uint32_t r0, r1, r2, r3;
            ldsm_x4(r0, r1, r2, r3, bB + SMEM_SWZ((uint32_t)(r*128 + kb)));
            b[np*2][0] = r0;   b[np*2][1] = r1;
            b[np*2+1][0] = r2; b[np*2+1][1] = r3;
        }
        #pragma unroll
        for (int mi = 0; mi < 2; mi++)
            #pragma unroll
            for (int nj = 0; nj < 8; nj++)
                mma16816(c[mi][nj], a[mi][0], a[mi][1], a[mi][2], a[mi][3],
                         b[nj][0], b[nj][1]);
    }
}

// ================= HMMA flash attention (self & mutual) =====================
// Block = (win, head), 256 threads / 8 warps.
// smem: sQ 16K | sK 16K | sP 32K (2 panels) | sVT 8K (2 panels) | srs 1K
template<int MUT>
__global__ __launch_bounds__(256) void attn_mma(const float* __restrict__ mask) {
    extern __shared__ uint8_t sm[];
    uint32_t base = (smem_u32(sm) + 1023u) & ~1023u;
    uint8_t* smp = sm + (base - smem_u32(sm));
    const uint32_t sQ = base, sK = base + 16384, sP = base + 32768, sVT = base + 65536;
    float* srs = reinterpret_cast<float*>(smp + 73728);

    int tid = threadIdx.x, wid = tid >> 5, lane = tid & 31;
    int win = blockIdx.x >> 3, h = blockIdx.x & 7;
    const float* qkv = MUT ? g_qkv_m : g_qkv_s;
    const float SC = 0.20412414523193154f;   // 24^-0.5

    // ---------- staging ----------
    if (tid < 128) {
        int r = tid;
        int qrow = MUT ? ((r + 64) & 127) : r;
        const float4* qp = reinterpret_cast<const float4*>(
            qkv + (size_t)(win*128 + qrow)*576 + h*24);
        uint32_t w[12];
        #pragma unroll
        for (int i = 0; i < 6; i++) {
            float4 a = qp[i];
            w[2*i]   = bf2(a.x*SC, a.y*SC);
            w[2*i+1] = bf2(a.z*SC, a.w*SC);
        }
        *reinterpret_cast<uint4*>(smp + SMEM_SWZ((uint32_t)(r*128 + 0)))  = make_uint4(w[0],w[1],w[2],w[3]);
        *reinterpret_cast<uint4*>(smp + SMEM_SWZ((uint32_t)(r*128 + 16))) = make_uint4(w[4],w[5],w[6],w[7]);
        *reinterpret_cast<uint4*>(smp + SMEM_SWZ((uint32_t)(r*128 + 32))) = make_uint4(w[8],w[9],w[10],w[11]);
        *reinterpret_cast<uint4*>(smp + SMEM_SWZ((uint32_t)(r*128 + 48))) = make_uint4(0,0,0,0);
        // V transposed scatter: sVT[dim][key], bf16
        const float4* vp = reinterpret_cast<const float4*>(
            qkv + (size_t)(win*128 + r)*576 + h*24 + 384);
        uint8_t* vbase = smp + 32768 + 32768 + (r >> 6)*4096;  // sVT panel
        int kc = (r & 63) * 2;
        #pragma unroll
        for (int i = 0; i < 6; i++) {
            float4 a = vp[i];
            *reinterpret_cast<__nv_bfloat16*>(vbase + SMEM_SWZ((uint32_t)((4*i+0)*128 + kc))) = __float2bfloat16_rn(a.x);
            *reinterpret_cast<__nv_bfloat16*>(vbase + SMEM_SWZ((uint32_t)((4*i+1)*128 + kc))) = __float2bfloat16_rn(a.y);
            *reinterpret_cast<__nv_bfloat16*>(vbase + SMEM_SWZ((uint32_t)((4*i+2)*128 + kc))) = __float2bfloat16_rn(a.z);
            *reinterpret_cast<__nv_bfloat16*>(vbase + SMEM_SWZ((uint32_t)((4*i+3)*128 + kc))) = __float2bfloat16_rn(a.w);
        }
    } else {
        int r = tid - 128;
        const float4* kp = reinterpret_cast<const float4*>(
            qkv + (size_t)(win*128 + r)*576 + h*24 + 192);
        uint32_t w[12];
        #pragma unroll
        for (int i = 0; i < 6; i++) {
            float4 a = kp[i];
            w[2*i]   = bf2(a.x, a.y);
            w[2*i+1] = bf2(a.z, a.w);
        }
        uint8_t* kbp = smp + 16384;
        *reinterpret_cast<uint4*>(kbp + SMEM_SWZ((uint32_t)(r*128 + 0)))  = make_uint4(w[0],w[1],w[2],w[3]);
        *reinterpret_cast<uint4*>(kbp + SMEM_SWZ((uint32_t)(r*128 + 16))) = make_uint4(w[4],w[5],w[6],w[7]);
        *reinterpret_cast<uint4*>(kbp + SMEM_SWZ((uint32_t)(r*128 + 32))) = make_uint4(w[8],w[9],w[10],w[11]);
        *reinterpret_cast<uint4*>(kbp + SMEM_SWZ((uint32_t)(r*128 + 48))) = make_uint4(0,0,0,0);
        // zero VT rows 24-31 (read by ldsm but must not contribute)
        int pn = r >> 6, j = r & 63;
        int rr = 24 + (j >> 3), cc = (j & 7) * 16;
        *reinterpret_cast<uint4*>(smp + 65536 + pn*4096 + SMEM_SWZ((uint32_t)(rr*128 + cc)))
            = make_uint4(0,0,0,0);
    }
    __syncthreads();

    // ---------- S = Q @ K^T (K-dim 32, 2 k-steps) ----------
    int wm = wid >> 1, wn = wid & 1;
    float c[2][8][4] = {};
    {
        int g = lane >> 3, l7 = lane & 7;
        #pragma unroll
        for (int ks = 0; ks < 2; ks++) {
            uint32_t a[2][4];
            #pragma unroll
            for (int mi = 0; mi < 2; mi++) {
                int r = wm*32 + mi*16 + ((g & 1) << 3) + l7;
                int kb = ks*32 + ((g >> 1) << 4);
                ldsm_x4(a[mi][0], a[mi][1], a[mi][2], a[mi][3],
                        sQ + SMEM_SWZ((uint32_t)(r*128 + kb)));
            }
            uint32_t b[8][2];
            #pragma unroll
            for (int np = 0; np < 4; np++) {
                int r = wn*64 + np*16 + ((g >> 1) << 3) + l7;
                int kb = ks*32 + ((g & 1) << 4);
                uint32_t r0, r1, r2, r3;
                ldsm_x4(r0, r1, r2, r3, sK + SMEM_SWZ((uint32_t)(r*128 + kb)));
                b[np*2][0] = r0;   b[np*2][1] = r1;
                b[np*2+1][0] = r2; b[np*2+1][1] = r3;
            }
            #pragma unroll
            for (int mi = 0; mi < 2; mi++)
                #pragma unroll
                for (int nj = 0; nj < 8; nj++)
                    mma16816(c[mi][nj], a[mi][0], a[mi][1], a[mi][2], a[mi][3],
                             b[nj][0], b[nj][1]);
        }
    }

    // ---------- softmax (no max-sub; scores O(1)) ----------
    int qr = lane >> 2, qc = (lane & 3) * 2;
    const float* mrow = mask + (size_t)(win % 192) * 16384;
    const float* brow = g_biasf + (size_t)h * 16384;
    #pragma unroll
    for (int mi = 0; mi < 2; mi++) {
        #pragma unroll
        for (int hh = 0; hh < 2; hh++) {
            int row = wm*32 + mi*16 + hh*8 + qr;
            float sum = 0.f;
            #pragma unroll
            for (int nj = 0; nj < 8; nj++) {
                int col = wn*64 + nj*8 + qc;
                float bx, by;
                if (MUT) {
                    float2 m2 = *reinterpret_cast<const float2*>(
                        mrow + (row & 63)*128 + (col & 63));
                    float gate = ((row ^ col) & 64) ? -10000.f : 0.f;
                    bx = m2.x + gate; by = m2.y + gate;
                } else {
                    float2 m2 = *reinterpret_cast<const float2*>(mrow + row*128 + col);
                    float2 b2 = *reinterpret_cast<const float2*>(brow + row*128 + col);
                    bx = m2.x + b2.x; by = m2.y + b2.y;
                }
                float p0 = __expf(c[mi][nj][2*hh]   + bx);
                float p1 = __expf(c[mi][nj][2*hh+1] + by);
                sum += p0 + p1;
                *reinterpret_cast<uint32_t*>(smp + 32768 + (col >> 6)*16384 +
                    SMEM_SWZ((uint32_t)(row*128 + (col & 63)*2))) = bf2(p0, p1);
            }
            sum += __shfl_xor_sync(0xffffffffu, sum, 1);
            sum += __shfl_xor_sync(0xffffffffu, sum, 2);
            if ((lane & 3) == 0) srs[wn*128 + row] = sum;
        }
    }
    __syncthreads();

    // ---------- O = P @ V (8 warps x 16 rows, N=24 via 4 n-tiles) ----------
    float o[4][4] = {};
    {
        int g = lane >> 3, l7 = lane & 7;
        #pragma unroll
        for (int kp = 0; kp < 2; kp++) {
            #pragma unroll
            for (int ks = 0; ks < 4; ks++) {
                uint32_t a0, a1, a2, a3;
                int ar = wid*16 + ((g & 1) << 3) + l7;
                int akb = ks*32 + ((g >> 1) << 4);
                ldsm_x4(a0, a1, a2, a3,
                        sP + kp*16384 + SMEM_SWZ((uint32_t)(ar*128 + akb)));
                uint32_t b[4][2];
                #pragma unroll
                for (int np = 0; np < 2; np++) {
                    int r = np*16 + ((g >> 1) << 3) + l7;
                    int kb = ks*32 + ((g & 1) << 4);
                    uint32_t r0, r1, r2, r3;
                    ldsm_x4(r0, r1, r2, r3,
                            sVT + kp*4096 + SMEM_SWZ((uint32_t)(r*128 + kb)));
                    b[np*2][0] = r0;   b[np*2][1] = r1;
                    b[np*2+1][0] = r2; b[np*2+1][1] = r3;
                }
                #pragma unroll
                for (int nj = 0; nj < 4; nj++)
                    mma16816(o[nj], a0, a1, a2, a3, b[nj][0], b[nj][1]);
            }
        }
    }

    // ---------- epilogue: divide by row sums, store bf16 ----------
    int coff = MUT ? 0 : 192;
    #pragma unroll
    for (int hh = 0; hh < 2; hh++) {
        int row = wid*16 + hh*8 + qr;
        float inv = 1.f / (srs[row] + srs[128 + row]);
        __nv_bfloat16* ob = g_xout_bf + (size_t)(win*128 + row)*384 + coff + h*24;
        #pragma unroll
        for (int nj = 0; nj < 3; nj++) {
            float v0 = o[nj][2*hh]   * inv;
            float v1 = o[nj][2*hh+1] * inv;
            *reinterpret_cast<uint32_t*>(ob + nj*8 + qc) = bf2(v0, v1);
        }
    }
}

// ---- shared mode-0 GEMM core: C fp32 = A @ Bt^T + bias ---------------------
__device__ __forceinline__ void gemm_core0(
        const __nv_bfloat16* __restrict__ A,
        const __nv_bfloat16* __restrict__ Bt,
        const float* __restrict__ bias,
        float* __restrict__ Cf, int K, int ldC, uint8_t* dyn_raw) {
    int tid = threadIdx.x, wid = tid >> 5, lane = tid & 31;
    int wm = wid >> 1, wn = wid & 1;
    int row0 = blockIdx.x * 128, col0 = blockIdx.y * 64;

    uint32_t aBase = (smem_u32(dyn_raw) + 1023u) & ~1023u;
    uint32_t bBase = aBase + 32768;

    int srow = tid >> 3, c16 = tid & 7;
    const __nv_bfloat16* arp[4]; uint32_t aOff[4];
    #pragma unroll
    for (int i = 0; i < 4; i++) {
        int r = i*32 + srow;
        aOff[i] = SMEM_SWZ((uint32_t)(r*128 + c16*16));
        arp[i] = A + (size_t)(row0 + r)*K + c16*8;
    }
    const __nv_bfloat16* brp[2]; uint32_t bOff[2];
    #pragma unroll
    for (int i = 0; i < 2; i++) {
        int r = i*32 + srow;
        bOff[i] = SMEM_SWZ((uint32_t)(r*128 + c16*16));
        brp[i] = Bt + (size_t)(col0 + r)*K + c16*8;
    }

    float c[2][4][4] = {};
    int nch = K >> 6;

    #pragma unroll
    for (int i = 0; i < 4; i++) cp16(aBase + aOff[i], arp[i], true);
    #pragma unroll
    for (int i = 0; i < 2; i++) cp16(bBase + bOff[i], brp[i], true);
    CP_COMMIT();

    for (int ic = 0; ic < nch; ic++) {
        if (ic + 1 < nch) {
            int buf = (ic + 1) & 1, kc = (ic + 1) << 6;
            #pragma unroll
            for (int i = 0; i < 4; i++)
                cp16(aBase + buf*16384 + aOff[i], arp[i] + kc, true);
            #pragma unroll
            for (int i = 0; i < 2; i++)
                cp16(bBase + buf*8192 + bOff[i], brp[i] + kc, true);
            CP_COMMIT();
            CP_WAIT1();
        } else {
            CP_WAIT0();
        }
        __syncthreads();
        mma_tile(aBase + (ic & 1)*16384, bBase + (ic & 1)*8192, c, wm, wn, lane);
        __syncthreads();
    }

    int qr = lane >> 2, qc = (lane & 3) * 2;
    #pragma unroll
    for (int mi = 0; mi < 2; mi++) {
        #pragma unroll
        for (int h = 0; h < 2; h++) {
            int lr = wm*32 + mi*16 + h*8 + qr;
            #pragma unroll
            for (int nj = 0; nj < 4; nj++) {
                int col = col0 + wn*32 + nj*8 + qc;
                size_t crow = (size_t)(row0 + lr)*ldC + col;
                *reinterpret_cast<float2*>(Cf + crow) =
                    make_float2(c[mi][nj][2*h] + bias[col],
                                c[mi][nj][2*h+1] + bias[col+1]);
            }
        }
    }
}

// ---- merged QKV GEMM: z=0 self, z=1 mutual ----------------------------------
__global__ __launch_bounds__(256, 3) void gemm_qkv(const float* __restrict__ qsb,
                                                   const float* __restrict__ qmb) {
    extern __shared__ uint8_t dyn_raw[];
    if (blockIdx.z == 0)
        gemm_core0(g_xw_bf, g_wt_qs, qsb, g_qkv_s, 192, 576, dyn_raw);
    else
        gemm_core0(g_xm_bf, g_wt_qm, qmb, g_qkv_m, 192, 576, dyn_raw);
}

// ---- proj GEMM ---------------------------------------------------------------
__global__ __launch_bounds__(256, 3) void gemm_proj(
        const __nv_bfloat16* __restrict__ A, const __nv_bfloat16* __restrict__ Bt,
        const float* __restrict__ bias, float* __restrict__ Cf, int K, int ldC) {
    extern __shared__ uint8_t dyn_raw[];
    gemm_core0(A, Bt, bias, Cf, K, ldC, dyn_raw);
}

// ======= MoE FC1: gather + gelu -> g_hbuf, wide 128x128 tile, K=192 =========
__global__ __launch_bounds__(256) void gemm_moe1(const float* __restrict__ b1) {
    extern __shared__ uint8_t dyn_raw[];
    __shared__ int s_tok[128];
    int tid = threadIdx.x, wid = tid >> 5, lane = tid & 31;
    int wm = wid >> 1, wn = wid & 1;
    int row0 = blockIdx.x * 128, col0 = blockIdx.y * 128;
    int e = blockIdx.z;
    int cnt = g_cnt[e];
    if (row0 >= cnt) return;
    const __nv_bfloat16* W1te = g_wt_w1 + (size_t)e*73728;
    const float* b1e = b1 + e*384;

    if (tid < 128) {
        int slot = row0 + tid;
        s_tok[tid] = (slot < cnt) ? g_gidx[e*TTOK + slot] : -1;
    }
    __syncthreads();

    uint32_t aBase = (smem_u32(dyn_raw) + 1023u) & ~1023u;
    uint32_t bBase = aBase + 32768;

    int srow = tid >> 3, c16 = tid & 7;
    const __nv_bfloat16* arp[4]; bool av[4]; uint32_t off[4];
    const __nv_bfloat16* brp[4];
    #pragma unroll
    for (int i = 0; i < 4; i++) {
        int r = i*32 + srow;
        off[i] = SMEM_SWZ((uint32_t)(r*128 + c16*16));
        int tk = s_tok[r];
        av[i] = (tk >= 0);
        arp[i] = g_xn2_bf + (size_t)(av[i] ? tk : 0)*192 + c16*8;
        brp[i] = W1te + (size_t)(col0 + r)*192 + c16*8;
    }

    float c[2][8][4] = {};

    #pragma unroll
    for (int i = 0; i < 4; i++) cp16(aBase + off[i], arp[i], av[i]);
    #pragma unroll
    for (int i = 0; i < 4; i++) cp16(bBase + off[i], brp[i], true);
    CP_COMMIT();

    for (int ic = 0; ic < 3; ic++) {
        if (ic + 1 < 3) {
            int buf = (ic + 1) & 1, kc = (ic + 1) << 6;
            #pragma unroll
            for (int i = 0; i < 4; i++)
                cp16(aBase + buf*16384 + off[i], arp[i] + kc, av[i]);
            #pragma unroll
            for (int i = 0; i < 4; i++)
                cp16(bBase + buf*16384 + off[i], brp[i] + kc, true);
            CP_COMMIT();
            CP_WAIT1();
        } else {
            CP_WAIT0();
        }
        __syncthreads();
        mma_tile_w(aBase + (ic & 1)*16384, bBase + (ic & 1)*16384, c, wm, wn, lane);
        __syncthreads();
    }

    int qr = lane >> 2, qc = (lane & 3) * 2;
    #pragma unroll
    for (int mi = 0; mi < 2; mi++) {
        #pragma unroll
        for (int h = 0; h < 2; h++) {
            int lr = wm*32 + mi*16 + h*8 + qr;
            if (s_tok[lr] >= 0) {
                size_t hrow = ((size_t)e*TTOK + row0 + lr)*384;
                #pragma unroll
                for (int nj = 0; nj < 8; nj++) {
                    int col = col0 + wn*64 + nj*8 + qc;
                    float h0 = c[mi][nj][2*h]   + b1e[col];
                    float h1 = c[mi][nj][2*h+1] + b1e[col+1];
                    h0 = h0 * normcdff(h0);
                    h1 = h1 * normcdff(h1);
                    *reinterpret_cast<uint32_t*>(g_hbuf + hrow + col) = bf2(h0, h1);
                }
            }
        }
    }
}

// ======= MoE FC2: weighted scatter -> contrib buffers, K=384 ================
__global__ __launch_bounds__(256, 3) void gemm_moe2(const float* __restrict__ b2) {
    extern __shared__ uint8_t dyn_raw[];
    __shared__ int s_tok[128]; __shared__ float s_wgt[128]; __shared__ int s_rnk[128];

    int tid = threadIdx.x, wid = tid >> 5, lane = tid & 31;
    int wm = wid >> 1, wn = wid & 1;
    int row0 = blockIdx.x * 128, col0 = blockIdx.y * 64;
    int e = blockIdx.z;
    int cnt = g_cnt[e];
    if (row0 >= cnt) return;
    const __nv_bfloat16* Bte = g_wt_w2 + (size_t)e*73728;
    const float* be = b2 + e*192;
    const __nv_bfloat16* Ae = g_hbuf + (size_t)e*TTOK*384;

    if (tid < 128) {
        int slot = row0 + tid;
        if (slot < cnt) {
            s_tok[tid] = g_gidx[e*TTOK + slot];
            s_wgt[tid] = g_gw[e*TTOK + slot];
            s_rnk[tid] = g_grank[e*TTOK + slot];
        } else s_tok[tid] = -1;
    }
    __syncthreads();

    uint32_t aBase = (smem_u32(dyn_raw) + 1023u) & ~1023u;
    uint32_t bBase = aBase + 32768;

    int srow = tid >> 3, c16 = tid & 7;
    const __nv_bfloat16* arp[4]; bool av[4]; uint32_t aOff[4];
    #pragma unroll
    for (int i = 0; i < 4; i++) {
        int r = i*32 + srow;
        aOff[i] = SMEM_SWZ((uint32_t)(r*128 + c16*16));
        av[i] = (row0 + r < cnt);
        arp[i] = Ae + (size_t)(av[i] ? (row0 + r) : 0)*384 + c16*8;
    }
    const __nv_bfloat16* brp[2]; uint32_t bOff[2];
    #pragma unroll
    for (int i = 0; i < 2; i++) {
        int r = i*32 + srow;
        bOff[i] = SMEM_SWZ((uint32_t)(r*128 + c16*16));
        brp[i] = Bte + (size_t)(col0 + r)*384 + c16*8;
    }

    float c[2][4][4] = {};

    #pragma unroll
    for (int i = 0; i < 4; i++) cp16(aBase + aOff[i], arp[i], av[i]);
    #pragma unroll
    for (int i = 0; i < 2; i++) cp16(bBase + bOff[i], brp[i], true);
    CP_COMMIT();

    for (int ic = 0; ic < 6; ic++) {
        if (ic + 1 < 6) {
            int buf = (ic + 1) & 1, kc = (ic + 1) << 6;
            #pragma unroll
            for (int i = 0; i < 4; i++)
                cp16(aBase + buf*16384 + aOff[i], arp[i] + kc, av[i]);
            #pragma unroll
            for (int i = 0; i < 2; i++)
                cp16(bBase + buf*8192 + bOff[i], brp[i] + kc, true);
            CP_COMMIT();
            CP_WAIT1();
        } else {
            CP_WAIT0();
        }
        __syncthreads();
        mma_tile(aBase + (ic & 1)*16384, bBase + (ic & 1)*8192, c, wm, wn, lane);
        __syncthreads();
    }

    int qr = lane >> 2, qc = (lane & 3) * 2;
    #pragma unroll
    for (int mi = 0; mi < 2; mi++) {
        #pragma unroll
        for (int h = 0; h < 2; h++) {
            int lr = wm*32 + mi*16 + h*8 + qr;
            int tk = s_tok[lr];
            if (tk >= 0) {
                float w = s_wgt[lr];
                float* dst = (s_rnk[lr] == 0) ? g_contrib0 : g_contrib1;
                #pragma unroll
                for (int nj = 0; nj < 4; nj++) {
                    int col = col0 + wn*32 + nj*8 + qc;
                    *reinterpret_cast<float2*>(dst + (size_t)tk*192 + col) =
                        make_float2(w*(c[mi][nj][2*h]   + be[col]),
                                    w*(c[mi][nj][2*h+1] + be[col+1]));
                }
            }
        }
    }
}

// ---- merged prep: transpose (0-359) | bias [h][q][k] (360-487) | pos (488) --
__global__ __launch_bounds__(256) void k_prep_all(
        const float* __restrict__ qs, const float* __restrict__ qm,
        const float* __restrict__ pw, const float* __restrict__ W1,
        const float* __restrict__ W2, const float* __restrict__ rpb) {
    __shared__ float tile[64][65];
    int bid = blockIdx.x;
    if (bid < 360) {
        const float* src; __nv_bfloat16* dst; int K, N, tk, tn;
        if (bid < 27)       { src = qs; dst = g_wt_qs; K = 192; N = 576; tk = bid/9; tn = bid%9; }
        else if (bid < 54)  { int j = bid-27; src = qm; dst = g_wt_qm; K = 192; N = 576; tk = j/9; tn = j%9; }
        else if (bid < 72)  { int j = bid-54; src = pw; dst = g_wt_p;  K = 384; N = 192; tk = j/3; tn = j%3; }
        else if (bid < 216) { int j = bid-72;  int e = j/18; j %= 18;
                              src = W1 + (size_t)e*73728; dst = g_wt_w1 + (size_t)e*73728;
                              K = 192; N = 384; tk = j/6; tn = j%6; }
        else                { int j = bid-216; int e = j/18; j %= 18;
                              src = W2 + (size_t)e*73728; dst = g_wt_w2 + (size_t)e*73728;
                              K = 384; N = 192; tk = j/3; tn = j%3; }
        int rr = threadIdx.x >> 6, cc = threadIdx.x & 63;
        #pragma unroll 4
        for (int i = 0; i < 16; i++) {
            int r = rr + 4*i;
            tile[r][cc] = src[(size_t)(tk*64 + r)*N + tn*64 + cc];
        }
        __syncthreads();
        #pragma unroll 4
        for (int i = 0; i < 16; i++) {
            int r = rr + 4*i;
            dst[(size_t)(tn*64 + r)*K + tk*64 + cc] = __float2bfloat16_rn(tile[cc][r]);
        }
    } else if (bid < 488) {
        int m = threadIdx.x;                 // m = key
        if (m >= 128) return;
        int n = bid - 360;                   // n = query
        int dn = n >> 6, hn = (n >> 3) & 7, wn = n & 7;
        int dm = m >> 6, hm = (m >> 3) & 7, wm = m & 7;
        int rp = (dn - dm + 1)*225 + (hn - hm + 7)*15 + (wn - wm + 7);
        #pragma unroll
        for (int h = 0; h < 8; h++)
            g_biasf[h*16384 + n*128 + m] = rpb[rp*8 + h];
    } else {
        int c = threadIdx.x;
        if (c >= 192) return;
        if (c < 8) g_cnt[c] = 0;
        const float TWO_PI = 6.283185307179586f;
        const float denom = 8.0f + 1e-6f;
        int f = (c < 96) ? c : c - 96;
        float expo = (float)(f & ~1) / 96.0f;
        float dt = powf(10000.0f, expo);
        for (int n = 0; n < 64; n++) {
            int i = n >> 3, j = n & 7;
            float base = (c < 96) ? (float)(i + 1) : (float)(j + 1);
            float v = base / denom * TWO_PI / dt;
            g_pos[n*192 + c] = (f & 1) ? cosf(v) : sinf(v);
        }
    }
}

// ---------------- LN1 + roll + window partition -> bf16 (warp per token) -----
__global__ __launch_bounds__(256) void ln_partition(const float* __restrict__ x,
                             const float* __restrict__ w1,
                             const float* __restrict__ b1) {
    int t = (blockIdx.x*blockDim.x + threadIdx.x) >> 5;
    int lane = threadIdx.x & 31;
    int win = t >> 7, n = t & 127;
    int b_  = win / 192; int rem = win % 192;
    int dd  = rem / 64;  int rem2 = rem % 64;
    int hh  = rem2 >> 3; int ww = rem2 & 7;
    int wd  = n >> 6, wh = (n >> 3) & 7, wwp = n & 7;
    int ds = dd*2 + wd, hs = hh*8 + wh, ws = ww*8 + wwp;
    int d = ds + 1; if (d >= 6) d -= 6;
    int h = (hs + 4) & 63;
    int w = (ws + 4) & 63;
    const float* xr = x + (size_t)(((b_*6 + d)*64 + h)*64 + w)*192;
    float v[6];
    float s1 = 0.f, s2 = 0.f;
    #pragma unroll
    for (int k = 0; k < 6; k++) {
        v[k] = xr[lane + 32*k];
        s1 += v[k]; s2 += v[k]*v[k];
    }
    s1 = warpsum_all(s1); s2 = warpsum_all(s2);
    float mu  = s1 * (1.f/192.f);
    float var = s2 * (1.f/192.f) - mu*mu;
    float rstd = rsqrtf(var + 1e-5f);
    const float* pr = g_pos + (n & 63)*192;
    #pragma unroll
    for (int k = 0; k < 6; k++) {
        int cc = lane + 32*k;
        float y = (v[k] - mu) * rstd * w1[cc] + b1[cc];
        g_xw_bf[(size_t)t*192 + cc] = __float2bfloat16_rn(y);
        g_xm_bf[(size_t)t*192 + cc] = __float2bfloat16_rn(y + pr[cc]);
    }
}

// --------- residual (writes out directly) + LN2 + gate top-2 -----------------
__global__ __launch_bounds__(256) void resid_gate(const float* __restrict__ x,
                           const float* __restrict__ n2w, const float* __restrict__ n2b,
                           const float* __restrict__ gw,  const float* __restrict__ gb,
                           float* __restrict__ out) {
    __shared__ float s_gw[8*192];
    for (int i = threadIdx.x; i < 1536; i += 256) {
        int j = i / 192, cc = i % 192;
        s_gw[i] = gw[cc*8 + j];
    }
    __syncthreads();
    int t = (blockIdx.x*blockDim.x + threadIdx.x) >> 5;
    int lane = threadIdx.x & 31;
    int b_ = t / 24576; int rrem = t % 24576;
    int d  = rrem / 4096; int r2 = rrem % 4096;
    int hh_ = r2 / 64; int ww_ = r2 % 64;
    int ds = d - 1; if (ds < 0) ds += 6;
    int hs = (hh_ + 60) & 63;
    int ws = (ww_ + 60) & 63;
    int dd = ds >> 1, wd = ds & 1;
    int hblk = hs >> 3, wh = hs & 7;
    int wblk = ws >> 3, wwp = ws & 7;
    int win = ((b_*3 + dd)*8 + hblk)*8 + wblk;
    int n = wd*64 + wh*8 + wwp;
    const float* ar = g_attnbuf + (size_t)(win*128 + n)*192;
    const float* xr = x + (size_t)t*192;
    float v[6];
    float s1 = 0.f, s2 = 0.f;
    #pragma unroll
    for (int k = 0; k < 6; k++) {
        int cc = lane + 32*k;
        v[k] = xr[cc] + ar[cc];
        out[(size_t)t*192 + cc] = v[k];
        s1 += v[k]; s2 += v[k]*v[k];
    }
    s1 = warpsum_all(s1); s2 = warpsum_all(s2);
    float mu  = s1 * (1.f/192.f);
    float var = s2 * (1.f/192.f) - mu*mu;
    float rstd = rsqrtf(var + 1e-5f);
    float g[8] = {};
    #pragma unroll
    for (int k = 0; k < 6; k++) {
        int cc = lane + 32*k;
        float xn = (v[k] - mu) * rstd * n2w[cc] + n2b[cc];
        g_xn2_bf[(size_t)t*192 + cc] = __float2bfloat16_rn(xn);
        #pragma unroll
        for (int j = 0; j < 8; j++) g[j] = fmaf(xn, s_gw[j*192 + cc], g[j]);
    }
    #pragma unroll
    for (int j = 0; j < 8; j++) g[j] = warpsum_all(g[j]);
    if (lane == 0) {
        float L[8];
        #pragma unroll
        for (int j = 0; j < 8; j++) L[j] = g[j] + gb[j];
        int e0 = 0;
        #pragma unroll
        for (int j = 1; j < 8; j++) if (L[j] > L[e0]) e0 = j;
        int e1 = (e0 == 0) ? 1 : 0;
        #pragma unroll
        for (int j = 0; j < 8; j++) if (j != e0 && L[j] > L[e1]) e1 = j;
        float w0 = 1.f / (1.f + __expf(L[e1] - L[e0]));
        float w1 = 1.f - w0;
        int p0 = atomicAdd(&g_cnt[e0], 1);
        g_gidx[e0*TTOK + p0] = t; g_gw[e0*TTOK + p0] = w0; g_grank[e0*TTOK + p0] = 0;
        int p1 = atomicAdd(&g_cnt[e1], 1);
        g_gidx[e1*TTOK + p1] = t; g_gw[e1*TTOK + p1] = w1; g_grank[e1*TTOK + p1] = 1;
    }
}

// ---------------- finalize: out += contrib0 + contrib1 -----------------------
__global__ void finalize(float* __restrict__ out) {
    int i = blockIdx.x*blockDim.x + threadIdx.x;
    if (i < TTOK*48) {
        float4 a  = reinterpret_cast<const float4*>(out)[i];
        float4 c0 = reinterpret_cast<const float4*>(g_contrib0)[i];
        float4 c1 = reinterpret_cast<const float4*>(g_contrib1)[i];
        reinterpret_cast<float4*>(out)[i] =
            make_float4(a.x + c0.x + c1.x, a.y + c0.y + c1.y,
                        a.z + c0.z + c1.z, a.w + c0.w + c1.w);
    }
}

// ---------------- host launcher -----------------------------------------------
extern "C" void kernel_launch(void* const* d_in, const int* in_sizes, int n_in,
                              void* d_out, int out_size) {
    const float* x    = (const float*)d_in[0];
    const float* mask = (const float*)d_in[1];
    const float* n1w  = (const float*)d_in[2];
    const float* n1b  = (const float*)d_in[3];
    const float* qsw  = (const float*)d_in[4];
    const float* qsb  = (const float*)d_in[5];
    const float* qmw  = (const float*)d_in[6];
    const float* qmb  = (const float*)d_in[7];
    const float* rpb  = (const float*)d_in[8];
    const float* pw   = (const float*)d_in[9];
    const float* pb   = (const float*)d_in[10];
    const float* n2w  = (const float*)d_in[11];
    const float* n2b  = (const float*)d_in[12];
    const float* gw   = (const float*)d_in[13];
    const float* gb   = (const float*)d_in[14];
    const float* W1   = (const float*)d_in[15];
    const float* b1   = (const float*)d_in[16];
    const float* W2   = (const float*)d_in[17];
    const float* b2   = (const float*)d_in[18];
    float* out = (float*)d_out;

    const int DSMEM  = 50176;   // 48KB + align pad
    const int DSMEM1 = 66560;   // 64KB + align pad (wide FC1)
    const int ASMEM  = 76800;   // attn: 73KB tiles + srs + align pad
    cudaFuncSetAttribute(gemm_qkv,    cudaFuncAttributeMaxDynamicSharedMemorySize, DSMEM);
    cudaFuncSetAttribute(gemm_proj,   cudaFuncAttributeMaxDynamicSharedMemorySize, DSMEM);
    cudaFuncSetAttribute(gemm_moe1,   cudaFuncAttributeMaxDynamicSharedMemorySize, DSMEM1);
    cudaFuncSetAttribute(gemm_moe2,   cudaFuncAttributeMaxDynamicSharedMemorySize, DSMEM);
    cudaFuncSetAttribute(attn_mma<0>, cudaFuncAttributeMaxDynamicSharedMemorySize, ASMEM);
    cudaFuncSetAttribute(attn_mma<1>, cudaFuncAttributeMaxDynamicSharedMemorySize, ASMEM);

    void *p_xout, *p_attn, *p_wp;
    cudaGetSymbolAddress(&p_xout, g_xout_bf);
    cudaGetSymbolAddress(&p_attn, g_attnbuf);
    cudaGetSymbolAddress(&p_wp,   g_wt_p);

    k_prep_all<<<489, 256>>>(qsw, qmw, pw, W1, W2, rpb);
    ln_partition<<<6144, 256>>>(x, n1w, n1b);
    gemm_qkv<<<dim3(384, 9, 2), 256, DSMEM>>>(qsb, qmb);
    attn_mma<0><<<3072, 256, ASMEM>>>(mask);               // <- profiled slot
    attn_mma<1><<<3072, 256, ASMEM>>>(mask);
    gemm_proj<<<dim3(384, 3), 256, DSMEM>>>((const __nv_bfloat16*)p_xout,
        (const __nv_bfloat16*)p_wp, pb, (float*)p_attn, 384, 192);
    resid_gate<<<6144, 256>>>(x, n2w, n2b, gw, gb, out);
    gemm_moe1<<<dim3(384, 3, 8), 256, DSMEM1>>>(b1);
    gemm_moe2<<<dim3(384, 3, 8), 256, DSMEM>>>(b2);
    finalize<<<9216, 256>>>(out);
}

// round 12
// speedup vs baseline: 1.4627x; 1.0620x over previous
#include <cuda_runtime.h>
#include <cuda_bf16.h>
#include <math.h>
#include <cstdint>

#define TTOK 49152      // total tokens = 2*6*64*64
#define NWIN 384

// ---------------- scratch (device globals; no allocations allowed) ----------
__device__ float g_qkv_s[TTOK*576];     // qkv fp32 (self)
__device__ float g_qkv_m[TTOK*576];     // qkv fp32 (mutual)
__device__ float g_attnbuf[TTOK*192];   // proj output (window order)
__device__ float g_pos[64*192];
__device__ float g_biasf[8*128*128];    // rel-pos bias per head [h][q][k] (transposed!)
__device__ int   g_cnt[8];
__device__ int   g_gidx[8*TTOK];
__device__ float g_gw[8*TTOK];
__device__ int   g_grank[8*TTOK];
__device__ float g_contrib0[TTOK*192];
__device__ float g_contrib1[TTOK*192];
// bf16 activation buffers for tensor-core GEMMs
__device__ __nv_bfloat16 g_xw_bf[TTOK*192];
__device__ __nv_bfloat16 g_xm_bf[TTOK*192];
__device__ __nv_bfloat16 g_xout_bf[TTOK*384];
__device__ __nv_bfloat16 g_xn2_bf[TTOK*192];
__device__ __nv_bfloat16 g_hbuf[(size_t)8*TTOK*384];
// transposed bf16 weights [N][K]
__device__ __nv_bfloat16 g_wt_qs[576*192];
__device__ __nv_bfloat16 g_wt_qm[576*192];
__device__ __nv_bfloat16 g_wt_p [192*384];
__device__ __nv_bfloat16 g_wt_w1[8*384*192];
__device__ __nv_bfloat16 g_wt_w2[8*192*384];

// ---------------- helpers ------------------------------------------------
typedef unsigned long long ull;
__device__ __forceinline__ float warpsum_all(float v) {
    #pragma unroll
    for (int o = 16; o; o >>= 1) v += __shfl_xor_sync(0xffffffffu, v, o);
    return v;
}
__device__ __forceinline__ uint32_t smem_u32(const void* p) {
    uint32_t a;
    asm("{ .reg .u64 t; cvta.to.shared.u64 t, %1; cvt.u32.u64 %0, t; }" : "=r"(a) : "l"(p));
    return a;
}
__device__ __forceinline__ void ldsm_x4(uint32_t& r0, uint32_t& r1, uint32_t& r2,
                                        uint32_t& r3, uint32_t addr) {
    asm volatile("ldmatrix.sync.aligned.m8n8.x4.shared.b16 {%0,%1,%2,%3}, [%4];"
                 : "=r"(r0), "=r"(r1), "=r"(r2), "=r"(r3) : "r"(addr));
}
__device__ __forceinline__ void mma16816(float* c, uint32_t a0, uint32_t a1,
                                         uint32_t a2, uint32_t a3,
                                         uint32_t b0, uint32_t b1) {
    asm volatile("mma.sync.aligned.m16n8k16.row.col.f32.bf16.bf16.f32 "
        "{%0,%1,%2,%3}, {%4,%5,%6,%7}, {%8,%9}, {%0,%1,%2,%3};"
        : "+f"(c[0]), "+f"(c[1]), "+f"(c[2]), "+f"(c[3])
        : "r"(a0), "r"(a1), "r"(a2), "r"(a3), "r"(b0), "r"(b1));
}
__device__ __forceinline__ void cp16(uint32_t dst, const void* src, bool v) {
    asm volatile("cp.async.cg.shared.global [%0], [%1], 16, %2;"
                 :: "r"(dst), "l"(src), "r"(v ? 16u : 0u));
}
#define CP_COMMIT() asm volatile("cp.async.commit_group;")
#define CP_WAIT1()  asm volatile("cp.async.wait_group 1;")
#define CP_WAIT0()  asm volatile("cp.async.wait_group 0;")
#define SMEM_SWZ(o) ((o) ^ (((o) >> 3) & 0x70))

__device__ __forceinline__ uint32_t bf2(float x, float y) {
    __nv_bfloat162 t = __floats2bfloat162_rn(x, y);
    return *reinterpret_cast<uint32_t*>(&t);
}

// ---- 128x64 warp-tile MMA over one 64-K chunk (8 warps: 4m x 2n) ----------
__device__ __forceinline__ void mma_tile(uint32_t aB, uint32_t bB,
                                         float (&c)[2][4][4], int wm, int wn, int lane) {
    int g = lane >> 3, l7 = lane & 7;
    #pragma unroll
    for (int ks = 0; ks < 4; ks++) {
        uint32_t a[2][4];
        #pragma unroll
        for (int mi = 0; mi < 2; mi++) {
            int r = wm*32 + mi*16 + ((g & 1) << 3) + l7;
            int kb = ks*32 + ((g >> 1) << 4);
            ldsm_x4(a[mi][0], a[mi][1], a[mi][2], a[mi][3],
                    aB + SMEM_SWZ((uint32_t)(r*128 + kb)));
        }
        uint32_t b[4][2];
        #pragma unroll
        for (int np = 0; np < 2; np++) {
            int r = wn*32 + np*16 + ((g >> 1) << 3) + l7;
            int kb = ks*32 + ((g & 1) << 4);
            uint32_t r0, r1, r2, r3;
            ldsm_x4(r0, r1, r2, r3, bB + SMEM_SWZ((uint32_t)(r*128 + kb)));
            b[np*2][0] = r0;   b[np*2][1] = r1;
            b[np*2+1][0] = r2; b[np*2+1][1] = r3;
        }
        #pragma unroll
        for (int mi = 0; mi < 2; mi++)
            #pragma unroll
            for (int nj = 0; nj < 4; nj++)
                mma16816(c[mi][nj], a[mi][0], a[mi][1], a[mi][2], a[mi][3],
                         b[nj][0], b[nj][1]);
    }
}

// ---- 128x128 wide warp-tile MMA (8 warps: 4m x 2n, 64 n-cols per warp) -----
__device__ __forceinline__ void mma_tile_w(uint32_t aB, uint32_t bB,
                                           float (&c)[2][8][4], int wm, int wn, int lane) {
    int g = lane >> 3, l7 = lane & 7;
    #pragma unroll
    for (int ks = 0; ks < 4; ks++) {
        uint32_t a[2][4];
        #pragma unroll
        for (int mi = 0; mi < 2; mi++) {
            int r = wm*32 + mi*16 + ((g & 1) << 3) + l7;
            int kb = ks*32 + ((g >> 1) << 4);
            ldsm_x4(a[mi][0], a[mi][1], a[mi][2], a[mi][3],
                    aB + SMEM_SWZ((uint32_t)(r*128 + kb)));
        }
        uint32_t b[8][2];
        #pragma unroll
        for (int np = 0; np < 4; np++) {
            int r = wn*64 + np*16 + ((g >> 1) << 3) + l7;
            int kb = ks*32 + ((g & 1) << 4);
            uint32_t r0, r1, r2, r3;
            ldsm_x4(r0, r1, r2, r3, bB + SMEM_SWZ((uint32_t)(r*128 + kb)));
            b[np*2][0] = r0;   b[np*2][1] = r1;
            b[np*2+1][0] = r2; b[np*2+1][1] = r3;
        }
        #pragma unroll
        for (int mi = 0; mi < 2; mi++)
            #pragma unroll
            for (int nj = 0; nj < 8; nj++)
                mma16816(c[mi][nj], a[mi][0], a[mi][1], a[mi][2], a[mi][3],
                         b[nj][0], b[nj][1]);
    }
}

// ================= HMMA flash attention (self & mutual) =====================
// Block = (win, head), 256 threads / 8 warps. 2 CTAs/SM via launch bounds.
template<int MUT>
__global__ __launch_bounds__(256, 2) void attn_mma(const float* __restrict__ mask) {
    extern __shared__ uint8_t sm[];
    uint32_t base = (smem_u32(sm) + 1023u) & ~1023u;
    uint8_t* smp = sm + (base - smem_u32(sm));
    const uint32_t sQ = base, sK = base + 16384, sP = base + 32768, sVT = base + 65536;
    float* srs = reinterpret_cast<float*>(smp + 73728);

    int tid = threadIdx.x, wid = tid >> 5, lane = tid & 31;
    int win = blockIdx.x >> 3, h = blockIdx.x & 7;
    const float* qkv = MUT ? g_qkv_m : g_qkv_s;
    const float SC = 0.20412414523193154f;   // 24^-0.5

    // ---------- staging ----------
    if (tid < 128) {
        int r = tid;
        int qrow = MUT ? ((r + 64) & 127) : r;
        const float4* qp = reinterpret_cast<const float4*>(
            qkv + (size_t)(win*128 + qrow)*576 + h*24);
        uint32_t w[12];
        #pragma unroll
        for (int i = 0; i < 6; i++) {
            float4 a = qp[i];
            w[2*i]   = bf2(a.x*SC, a.y*SC);
            w[2*i+1] = bf2(a.z*SC, a.w*SC);
        }
        *reinterpret_cast<uint4*>(smp + SMEM_SWZ((uint32_t)(r*128 + 0)))  = make_uint4(w[0],w[1],w[2],w[3]);
        *reinterpret_cast<uint4*>(smp + SMEM_SWZ((uint32_t)(r*128 + 16))) = make_uint4(w[4],w[5],w[6],w[7]);
        *reinterpret_cast<uint4*>(smp + SMEM_SWZ((uint32_t)(r*128 + 32))) = make_uint4(w[8],w[9],w[10],w[11]);
        *reinterpret_cast<uint4*>(smp + SMEM_SWZ((uint32_t)(r*128 + 48))) = make_uint4(0,0,0,0);
        // V transposed scatter: sVT[dim][key], bf16
        const float4* vp = reinterpret_cast<const float4*>(
            qkv + (size_t)(win*128 + r)*576 + h*24 + 384);
        uint8_t* vbase = smp + 32768 + 32768 + (r >> 6)*4096;  // sVT panel
        int kc = (r & 63) * 2;
        #pragma unroll
        for (int i = 0; i < 6; i++) {
            float4 a = vp[i];
            *reinterpret_cast<__nv_bfloat16*>(vbase + SMEM_SWZ((uint32_t)((4*i+0)*128 + kc))) = __float2bfloat16_rn(a.x);
            *reinterpret_cast<__nv_bfloat16*>(vbase + SMEM_SWZ((uint32_t)((4*i+1)*128 + kc))) = __float2bfloat16_rn(a.y);
            *reinterpret_cast<__nv_bfloat16*>(vbase + SMEM_SWZ((uint32_t)((4*i+2)*128 + kc))) = __float2bfloat16_rn(a.z);
            *reinterpret_cast<__nv_bfloat16*>(vbase + SMEM_SWZ((uint32_t)((4*i+3)*128 + kc))) = __float2bfloat16_rn(a.w);
        }
    } else {
        int r = tid - 128;
        const float4* kp = reinterpret_cast<const float4*>(
            qkv + (size_t)(win*128 + r)*576 + h*24 + 192);
        uint32_t w[12];
        #pragma unroll
        for (int i = 0; i < 6; i++) {
            float4 a = kp[i];
            w[2*i]   = bf2(a.x, a.y);
            w[2*i+1] = bf2(a.z, a.w);
        }
        uint8_t* kbp = smp + 16384;
        *reinterpret_cast<uint4*>(kbp + SMEM_SWZ((uint32_t)(r*128 + 0)))  = make_uint4(w[0],w[1],w[2],w[3]);
        *reinterpret_cast<uint4*>(kbp + SMEM_SWZ((uint32_t)(r*128 + 16))) = make_uint4(w[4],w[5],w[6],w[7]);
        *reinterpret_cast<uint4*>(kbp + SMEM_SWZ((uint32_t)(r*128 + 32))) = make_uint4(w[8],w[9],w[10],w[11]);
        *reinterpret_cast<uint4*>(kbp + SMEM_SWZ((uint32_t)(r*128 + 48))) = make_uint4(0,0,0,0);
        // zero VT rows 24-31 (read by ldsm but must not contribute)
        int pn = r >> 6, j = r & 63;
        int rr = 24 + (j >> 3), cc = (j & 7) * 16;
        *reinterpret_cast<uint4*>(smp + 65536 + pn*4096 + SMEM_SWZ((uint32_t)(rr*128 + cc)))
            = make_uint4(0,0,0,0);
    }
    __syncthreads();

    // ---------- S = Q @ K^T (K-dim 32, 2 k-steps) ----------
    int wm = wid >> 1, wn = wid & 1;
    float c[2][8][4] = {};
    {
        int g = lane >> 3, l7 = lane & 7;
        #pragma unroll
        for (int ks = 0; ks < 2; ks++) {
            uint32_t a[2][4];
            #pragma unroll
            for (int mi = 0; mi < 2; mi++) {
                int r = wm*32 + mi*16 + ((g & 1) << 3) + l7;
                int kb = ks*32 + ((g >> 1) << 4);
                ldsm_x4(a[mi][0], a[mi][1], a[mi][2], a[mi][3],
                        sQ + SMEM_SWZ((uint32_t)(r*128 + kb)));
            }
            uint32_t b[8][2];
            #pragma unroll
            for (int np = 0; np < 4; np++) {
                int r = wn*64 + np*16 + ((g >> 1) << 3) + l7;
                int kb = ks*32 + ((g & 1) << 4);
                uint32_t r0, r1, r2, r3;
                ldsm_x4(r0, r1, r2, r3, sK + SMEM_SWZ((uint32_t)(r*128 + kb)));
                b[np*2][0] = r0;   b[np*2][1] = r1;
                b[np*2+1][0] = r2; b[np*2+1][1] = r3;
            }
            #pragma unroll
            for (int mi = 0; mi < 2; mi++)
                #pragma unroll
                for (int nj = 0; nj < 8; nj++)
                    mma16816(c[mi][nj], a[mi][0], a[mi][1], a[mi][2], a[mi][3],
                             b[nj][0], b[nj][1]);
        }
    }

    // ---------- softmax (no max-sub; scores O(1)) ----------
    int qr = lane >> 2, qc = (lane & 3) * 2;
    const float* mrow = mask + (size_t)(win % 192) * 16384;
    const float* brow = g_biasf + (size_t)h * 16384;
    #pragma unroll
    for (int mi = 0; mi < 2; mi++) {
        #pragma unroll
        for (int hh = 0; hh < 2; hh++) {
            int row = wm*32 + mi*16 + hh*8 + qr;
            float sum = 0.f;
            #pragma unroll
            for (int nj = 0; nj < 8; nj++) {
                int col = wn*64 + nj*8 + qc;
                float bx, by;
                if (MUT) {
                    float2 m2 = *reinterpret_cast<const float2*>(
                        mrow + (row & 63)*128 + (col & 63));
                    float gate = ((row ^ col) & 64) ? -10000.f : 0.f;
                    bx = m2.x + gate; by = m2.y + gate;
                } else {
                    float2 m2 = *reinterpret_cast<const float2*>(mrow + row*128 + col);
                    float2 b2 = *reinterpret_cast<const float2*>(brow + row*128 + col);
                    bx = m2.x + b2.x; by = m2.y + b2.y;
                }
                float p0 = __expf(c[mi][nj][2*hh]   + bx);
                float p1 = __expf(c[mi][nj][2*hh+1] + by);
                sum += p0 + p1;
                *reinterpret_cast<uint32_t*>(smp + 32768 + (col >> 6)*16384 +
                    SMEM_SWZ((uint32_t)(row*128 + (col & 63)*2))) = bf2(p0, p1);
            }
            sum += __shfl_xor_sync(0xffffffffu, sum, 1);
            sum += __shfl_xor_sync(0xffffffffu, sum, 2);
            if ((lane & 3) == 0) srs[wn*128 + row] = sum;
        }
    }
    __syncthreads();

    // ---------- O = P @ V (8 warps x 16 rows, N=24 via 4 n-tiles) ----------
    float o[4][4] = {};
    {
        int g = lane >> 3, l7 = lane & 7;
        #pragma unroll
        for (int kp = 0; kp < 2; kp++) {
            #pragma unroll
            for (int ks = 0; ks < 4; ks++) {
                uint32_t a0, a1, a2, a3;
                int ar = wid*16 + ((g & 1) << 3) + l7;
                int akb = ks*32 + ((g >> 1) << 4);
                ldsm_x4(a0, a1, a2, a3,
                        sP + kp*16384 + SMEM_SWZ((uint32_t)(ar*128 + akb)));
                uint32_t b[4][2];
                #pragma unroll
                for (int np = 0; np < 2; np++) {
                    int r = np*16 + ((g >> 1) << 3) + l7;
                    int kb = ks*32 + ((g & 1) << 4);
                    uint32_t r0, r1, r2, r3;
                    ldsm_x4(r0, r1, r2, r3,
                            sVT + kp*4096 + SMEM_SWZ((uint32_t)(r*128 + kb)));
                    b[np*2][0] = r0;   b[np*2][1] = r1;
                    b[np*2+1][0] = r2; b[np*2+1][1] = r3;
                }
                #pragma unroll
                for (int nj = 0; nj < 4; nj++)
                    mma16816(o[nj], a0, a1, a2, a3, b[nj][0], b[nj][1]);
            }
        }
    }

    // ---------- epilogue: divide by row sums, store bf16 ----------
    int coff = MUT ? 0 : 192;
    #pragma unroll
    for (int hh = 0; hh < 2; hh++) {
        int row = wid*16 + hh*8 + qr;
        float inv = 1.f / (srs[row] + srs[128 + row]);
        __nv_bfloat16* ob = g_xout_bf + (size_t)(win*128 + row)*384 + coff + h*24;
        #pragma unroll
        for (int nj = 0; nj < 3; nj++) {
            float v0 = o[nj][2*hh]   * inv;
            float v1 = o[nj][2*hh+1] * inv;
            *reinterpret_cast<uint32_t*>(ob + nj*8 + qc) = bf2(v0, v1);
        }
    }
}

// ---- shared mode-0 GEMM core: C fp32 = A @ Bt^T + bias ---------------------
__device__ __forceinline__ void gemm_core0(
        const __nv_bfloat16* __restrict__ A,
        const __nv_bfloat16* __restrict__ Bt,
        const float* __restrict__ bias,
        float* __restrict__ Cf, int K, int ldC, uint8_t* dyn_raw) {
    int tid = threadIdx.x, wid = tid >> 5, lane = tid & 31;
    int wm = wid >> 1, wn = wid & 1;
    int row0 = blockIdx.x * 128, col0 = blockIdx.y * 64;

    uint32_t aBase = (smem_u32(dyn_raw) + 1023u) & ~1023u;
    uint32_t bBase = aBase + 32768;

    int srow = tid >> 3, c16 = tid & 7;
    const __nv_bfloat16* arp[4]; uint32_t aOff[4];
    #pragma unroll
    for (int i = 0; i < 4; i++) {
        int r = i*32 + srow;
        aOff[i] = SMEM_SWZ((uint32_t)(r*128 + c16*16));
        arp[i] = A + (size_t)(row0 + r)*K + c16*8;
    }
    const __nv_bfloat16* brp[2]; uint32_t bOff[2];
    #pragma unroll
    for (int i = 0; i < 2; i++) {
        int r = i*32 + srow;
        bOff[i] = SMEM_SWZ((uint32_t)(r*128 + c16*16));
        brp[i] = Bt + (size_t)(col0 + r)*K + c16*8;
    }

    float c[2][4][4] = {};
    int nch = K >> 6;

    #pragma unroll
    for (int i = 0; i < 4; i++) cp16(aBase + aOff[i], arp[i], true);
    #pragma unroll
    for (int i = 0; i < 2; i++) cp16(bBase + bOff[i], brp[i], true);
    CP_COMMIT();

    for (int ic = 0; ic < nch; ic++) {
        if (ic + 1 < nch) {
            int buf = (ic + 1) & 1, kc = (ic + 1) << 6;
            #pragma unroll
            for (int i = 0; i < 4; i++)
                cp16(aBase + buf*16384 + aOff[i], arp[i] + kc, true);
            #pragma unroll
            for (int i = 0; i < 2; i++)
                cp16(bBase + buf*8192 + bOff[i], brp[i] + kc, true);
            CP_COMMIT();
            CP_WAIT1();
        } else {
            CP_WAIT0();
        }
        __syncthreads();
        mma_tile(aBase + (ic & 1)*16384, bBase + (ic & 1)*8192, c, wm, wn, lane);
        __syncthreads();
    }

    int qr = lane >> 2, qc = (lane & 3) * 2;
    #pragma unroll
    for (int mi = 0; mi < 2; mi++) {
        #pragma unroll
        for (int h = 0; h < 2; h++) {
            int lr = wm*32 + mi*16 + h*8 + qr;
            #pragma unroll
            for (int nj = 0; nj < 4; nj++) {
                int col = col0 + wn*32 + nj*8 + qc;
                size_t crow = (size_t)(row0 + lr)*ldC + col;
                *reinterpret_cast<float2*>(Cf + crow) =
                    make_float2(c[mi][nj][2*h] + bias[col],
                                c[mi][nj][2*h+1] + bias[col+1]);
            }
        }
    }
}

// ---- merged QKV GEMM: z=0 self, z=1 mutual ----------------------------------
__global__ __launch_bounds__(256, 3) void gemm_qkv(const float* __restrict__ qsb,
                                                   const float* __restrict__ qmb) {
    extern __shared__ uint8_t dyn_raw[];
    if (blockIdx.z == 0)
        gemm_core0(g_xw_bf, g_wt_qs, qsb, g_qkv_s, 192, 576, dyn_raw);
    else
        gemm_core0(g_xm_bf, g_wt_qm, qmb, g_qkv_m, 192, 576, dyn_raw);
}

// ---- proj GEMM ---------------------------------------------------------------
__global__ __launch_bounds__(256, 3) void gemm_proj(
        const __nv_bfloat16* __restrict__ A, const __nv_bfloat16* __restrict__ Bt,
        const float* __restrict__ bias, float* __restrict__ Cf, int K, int ldC) {
    extern __shared__ uint8_t dyn_raw[];
    gemm_core0(A, Bt, bias, Cf, K, ldC, dyn_raw);
}

// ======= MoE FC1: gather + gelu -> g_hbuf, wide 128x128 tile, K=192 =========
__global__ __launch_bounds__(256) void gemm_moe1(const float* __restrict__ b1) {
    extern __shared__ uint8_t dyn_raw[];
    __shared__ int s_tok[128];
    int tid = threadIdx.x, wid = tid >> 5, lane = tid & 31;
    int wm = wid >> 1, wn = wid & 1;
    int row0 = blockIdx.x * 128, col0 = blockIdx.y * 128;
    int e = blockIdx.z;
    int cnt = g_cnt[e];
    if (row0 >= cnt) return;
    const __nv_bfloat16* W1te = g_wt_w1 + (size_t)e*73728;
    const float* b1e = b1 + e*384;

    if (tid < 128) {
        int slot = row0 + tid;
        s_tok[tid] = (slot < cnt) ? g_gidx[e*TTOK + slot] : -1;
    }
    __syncthreads();

    uint32_t aBase = (smem_u32(dyn_raw) + 1023u) & ~1023u;
    uint32_t bBase = aBase + 32768;

    int srow = tid >> 3, c16 = tid & 7;
    const __nv_bfloat16* arp[4]; bool av[4]; uint32_t off[4];
    const __nv_bfloat16* brp[4];
    #pragma unroll
    for (int i = 0; i < 4; i++) {
        int r = i*32 + srow;
        off[i] = SMEM_SWZ((uint32_t)(r*128 + c16*16));
        int tk = s_tok[r];
        av[i] = (tk >= 0);
        arp[i] = g_xn2_bf + (size_t)(av[i] ? tk : 0)*192 + c16*8;
        brp[i] = W1te + (size_t)(col0 + r)*192 + c16*8;
    }

    float c[2][8][4] = {};

    #pragma unroll
    for (int i = 0; i < 4; i++) cp16(aBase + off[i], arp[i], av[i]);
    #pragma unroll
    for (int i = 0; i < 4; i++) cp16(bBase + off[i], brp[i], true);
    CP_COMMIT();

    for (int ic = 0; ic < 3; ic++) {
        if (ic + 1 < 3) {
            int buf = (ic + 1) & 1, kc = (ic + 1) << 6;
            #pragma unroll
            for (int i = 0; i < 4; i++)
                cp16(aBase + buf*16384 + off[i], arp[i] + kc, av[i]);
            #pragma unroll
            for (int i = 0; i < 4; i++)
                cp16(bBase + buf*16384 + off[i], brp[i] + kc, true);
            CP_COMMIT();
            CP_WAIT1();
        } else {
            CP_WAIT0();
        }
        __syncthreads();
        mma_tile_w(aBase + (ic & 1)*16384, bBase + (ic & 1)*16384, c, wm, wn, lane);
        __syncthreads();
    }

    int qr = lane >> 2, qc = (lane & 3) * 2;
    #pragma unroll
    for (int mi = 0; mi < 2; mi++) {
        #pragma unroll
        for (int h = 0; h < 2; h++) {
            int lr = wm*32 + mi*16 + h*8 + qr;
            if (s_tok[lr] >= 0) {
                size_t hrow = ((size_t)e*TTOK + row0 + lr)*384;
                #pragma unroll
                for (int nj = 0; nj < 8; nj++) {
                    int col = col0 + wn*64 + nj*8 + qc;
                    float h0 = c[mi][nj][2*h]   + b1e[col];
                    float h1 = c[mi][nj][2*h+1] + b1e[col+1];
                    h0 = h0 * normcdff(h0);
                    h1 = h1 * normcdff(h1);
                    *reinterpret_cast<uint32_t*>(g_hbuf + hrow + col) = bf2(h0, h1);
                }
            }
        }
    }
}

// ======= MoE FC2: weighted scatter -> contrib buffers, K=384 ================
__global__ __launch_bounds__(256, 3) void gemm_moe2(const float* __restrict__ b2) {
    extern __shared__ uint8_t dyn_raw[];
    __shared__ int s_tok[128]; __shared__ float s_wgt[128]; __shared__ int s_rnk[128];

    int tid = threadIdx.x, wid = tid >> 5, lane = tid & 31;
    int wm = wid >> 1, wn = wid & 1;
    int row0 = blockIdx.x * 128, col0 = blockIdx.y * 64;
    int e = blockIdx.z;
    int cnt = g_cnt[e];
    if (row0 >= cnt) return;
    const __nv_bfloat16* Bte = g_wt_w2 + (size_t)e*73728;
    const float* be = b2 + e*192;
    const __nv_bfloat16* Ae = g_hbuf + (size_t)e*TTOK*384;

    if (tid < 128) {
        int slot = row0 + tid;
        if (slot < cnt) {
            s_tok[tid] = g_gidx[e*TTOK + slot];
            s_wgt[tid] = g_gw[e*TTOK + slot];
            s_rnk[tid] = g_grank[e*TTOK + slot];
        } else s_tok[tid] = -1;
    }
    __syncthreads();

    uint32_t aBase = (smem_u32(dyn_raw) + 1023u) & ~1023u;
    uint32_t bBase = aBase + 32768;

    int srow = tid >> 3, c16 = tid & 7;
    const __nv_bfloat16* arp[4]; bool av[4]; uint32_t aOff[4];
    #pragma unroll
    for (int i = 0; i < 4; i++) {
        int r = i*32 + srow;
        aOff[i] = SMEM_SWZ((uint32_t)(r*128 + c16*16));
        av[i] = (row0 + r < cnt);
        arp[i] = Ae + (size_t)(av[i] ? (row0 + r) : 0)*384 + c16*8;
    }
    const __nv_bfloat16* brp[2]; uint32_t bOff[2];
    #pragma unroll
    for (int i = 0; i < 2; i++) {
        int r = i*32 + srow;
        bOff[i] = SMEM_SWZ((uint32_t)(r*128 + c16*16));
        brp[i] = Bte + (size_t)(col0 + r)*384 + c16*8;
    }

    float c[2][4][4] = {};

    #pragma unroll
    for (int i = 0; i < 4; i++) cp16(aBase + aOff[i], arp[i], av[i]);
    #pragma unroll
    for (int i = 0; i < 2; i++) cp16(bBase + bOff[i], brp[i], true);
    CP_COMMIT();

    for (int ic = 0; ic < 6; ic++) {
        if (ic + 1 < 6) {
            int buf = (ic + 1) & 1, kc = (ic + 1) << 6;
            #pragma unroll
            for (int i = 0; i < 4; i++)
                cp16(aBase + buf*16384 + aOff[i], arp[i] + kc, av[i]);
            #pragma unroll
            for (int i = 0; i < 2; i++)
                cp16(bBase + buf*8192 + bOff[i], brp[i] + kc, true);
            CP_COMMIT();
            CP_WAIT1();
        } else {
            CP_WAIT0();
        }
        __syncthreads();
        mma_tile(aBase + (ic & 1)*16384, bBase + (ic & 1)*8192, c, wm, wn, lane);
        __syncthreads();
    }

    int qr = lane >> 2, qc = (lane & 3) * 2;
    #pragma unroll
    for (int mi = 0; mi < 2; mi++) {
        #pragma unroll
        for (int h = 0; h < 2; h++) {
            int lr = wm*32 + mi*16 + h*8 + qr;
            int tk = s_tok[lr];
            if (tk >= 0) {
                float w = s_wgt[lr];
                float* dst = (s_rnk[lr] == 0) ? g_contrib0 : g_contrib1;
                #pragma unroll
                for (int nj = 0; nj < 4; nj++) {
                    int col = col0 + wn*32 + nj*8 + qc;
                    *reinterpret_cast<float2*>(dst + (size_t)tk*192 + col) =
                        make_float2(w*(c[mi][nj][2*h]   + be[col]),
                                    w*(c[mi][nj][2*h+1] + be[col+1]));
                }
            }
        }
    }
}

// ---- merged prep: transpose (0-359) | bias [h][q][k] (360-487) | pos (488) --
__global__ __launch_bounds__(256) void k_prep_all(
        const float* __restrict__ qs, const float* __restrict__ qm,
        const float* __restrict__ pw, const float* __restrict__ W1,
        const float* __restrict__ W2, const float* __restrict__ rpb) {
    __shared__ float tile[64][65];
    int bid = blockIdx.x;
    if (bid < 360) {
        const float* src; __nv_bfloat16* dst; int K, N, tk, tn;
        if (bid < 27)       { src = qs; dst = g_wt_qs; K = 192; N = 576; tk = bid/9; tn = bid%9; }
        else if (bid < 54)  { int j = bid-27; src = qm; dst = g_wt_qm; K = 192; N = 576; tk = j/9; tn = j%9; }
        else if (bid < 72)  { int j = bid-54; src = pw; dst = g_wt_p;  K = 384; N = 192; tk = j/3; tn = j%3; }
        else if (bid < 216) { int j = bid-72;  int e = j/18; j %= 18;
                              src = W1 + (size_t)e*73728; dst = g_wt_w1 + (size_t)e*73728;
                              K = 192; N = 384; tk = j/6; tn = j%6; }
        else                { int j = bid-216; int e = j/18; j %= 18;
                              src = W2 + (size_t)e*73728; dst = g_wt_w2 + (size_t)e*73728;
                              K = 384; N = 192; tk = j/3; tn = j%3; }
        int rr = threadIdx.x >> 6, cc = threadIdx.x & 63;
        #pragma unroll 4
        for (int i = 0; i < 16; i++) {
            int r = rr + 4*i;
            tile[r][cc] = src[(size_t)(tk*64 + r)*N + tn*64 + cc];
        }
        __syncthreads();
        #pragma unroll 4
        for (int i = 0; i < 16; i++) {
            int r = rr + 4*i;
            dst[(size_t)(tn*64 + r)*K + tk*64 + cc] = __float2bfloat16_rn(tile[cc][r]);
        }
    } else if (bid < 488) {
        int m = threadIdx.x;                 // m = key
        if (m >= 128) return;
        int n = bid - 360;                   // n = query
        int dn = n >> 6, hn = (n >> 3) & 7, wn = n & 7;
        int dm = m >> 6, hm = (m >> 3) & 7, wm = m & 7;
        int rp = (dn - dm + 1)*225 + (hn - hm + 7)*15 + (wn - wm + 7);
        #pragma unroll
        for (int h = 0; h < 8; h++)
            g_biasf[h*16384 + n*128 + m] = rpb[rp*8 + h];
    } else {
        int c = threadIdx.x;
        if (c >= 192) return;
        if (c < 8) g_cnt[c] = 0;
        const float TWO_PI = 6.283185307179586f;
        const float denom = 8.0f + 1e-6f;
        int f = (c < 96) ? c : c - 96;
        float expo = (float)(f & ~1) / 96.0f;
        float dt = powf(10000.0f, expo);
        for (int n = 0; n < 64; n++) {
            int i = n >> 3, j = n & 7;
            float base = (c < 96) ? (float)(i + 1) : (float)(j + 1);
            float v = base / denom * TWO_PI / dt;
            g_pos[n*192 + c] = (f & 1) ? cosf(v) : sinf(v);
        }
    }
}

// ---------------- LN1 + roll + window partition -> bf16 (warp per token) -----
__global__ __launch_bounds__(256) void ln_partition(const float* __restrict__ x,
                             const float* __restrict__ w1,
                             const float* __restrict__ b1) {
    int t = (blockIdx.x*blockDim.x + threadIdx.x) >> 5;
    int lane = threadIdx.x & 31;
    int win = t >> 7, n = t & 127;
    int b_  = win / 192; int rem = win % 192;
    int dd  = rem / 64;  int rem2 = rem % 64;
    int hh  = rem2 >> 3; int ww = rem2 & 7;
    int wd  = n >> 6, wh = (n >> 3) & 7, wwp = n & 7;
    int ds = dd*2 + wd, hs = hh*8 + wh, ws = ww*8 + wwp;
    int d = ds + 1; if (d >= 6) d -= 6;
    int h = (hs + 4) & 63;
    int w = (ws + 4) & 63;
    const float* xr = x + (size_t)(((b_*6 + d)*64 + h)*64 + w)*192;
    float v[6];
    float s1 = 0.f, s2 = 0.f;
    #pragma unroll
    for (int k = 0; k < 6; k++) {
        v[k] = xr[lane + 32*k];
        s1 += v[k]; s2 += v[k]*v[k];
    }
    s1 = warpsum_all(s1); s2 = warpsum_all(s2);
    float mu  = s1 * (1.f/192.f);
    float var = s2 * (1.f/192.f) - mu*mu;
    float rstd = rsqrtf(var + 1e-5f);
    const float* pr = g_pos + (n & 63)*192;
    #pragma unroll
    for (int k = 0; k < 6; k++) {
        int cc = lane + 32*k;
        float y = (v[k] - mu) * rstd * w1[cc] + b1[cc];
        g_xw_bf[(size_t)t*192 + cc] = __float2bfloat16_rn(y);
        g_xm_bf[(size_t)t*192 + cc] = __float2bfloat16_rn(y + pr[cc]);
    }
}

// --------- residual (writes out directly) + LN2 + gate top-2 -----------------
__global__ __launch_bounds__(256) void resid_gate(const float* __restrict__ x,
                           const float* __restrict__ n2w, const float* __restrict__ n2b,
                           const float* __restrict__ gw,  const float* __restrict__ gb,
                           float* __restrict__ out) {
    __shared__ float s_gw[8*192];
    for (int i = threadIdx.x; i < 1536; i += 256) {
        int j = i / 192, cc = i % 192;
        s_gw[i] = gw[cc*8 + j];
    }
    __syncthreads();
    int t = (blockIdx.x*blockDim.x + threadIdx.x) >> 5;
    int lane = threadIdx.x & 31;
    int b_ = t / 24576; int rrem = t % 24576;
    int d  = rrem / 4096; int r2 = rrem % 4096;
    int hh_ = r2 / 64; int ww_ = r2 % 64;
    int ds = d - 1; if (ds < 0) ds += 6;
    int hs = (hh_ + 60) & 63;
    int ws = (ww_ + 60) & 63;
    int dd = ds >> 1, wd = ds & 1;
    int hblk = hs >> 3, wh = hs & 7;
    int wblk = ws >> 3, wwp = ws & 7;
    int win = ((b_*3 + dd)*8 + hblk)*8 + wblk;
    int n = wd*64 + wh*8 + wwp;
    const float* ar = g_attnbuf + (size_t)(win*128 + n)*192;
    const float* xr = x + (size_t)t*192;
    float v[6];
    float s1 = 0.f, s2 = 0.f;
    #pragma unroll
    for (int k = 0; k < 6; k++) {
        int cc = lane + 32*k;
        v[k] = xr[cc] + ar[cc];
        out[(size_t)t*192 + cc] = v[k];
        s1 += v[k]; s2 += v[k]*v[k];
    }
    s1 = warpsum_all(s1); s2 = warpsum_all(s2);
    float mu  = s1 * (1.f/192.f);
    float var = s2 * (1.f/192.f) - mu*mu;
    float rstd = rsqrtf(var + 1e-5f);
    float g[8] = {};
    #pragma unroll
    for (int k = 0; k < 6; k++) {
        int cc = lane + 32*k;
        float xn = (v[k] - mu) * rstd * n2w[cc] + n2b[cc];
        g_xn2_bf[(size_t)t*192 + cc] = __float2bfloat16_rn(xn);
        #pragma unroll
        for (int j = 0; j < 8; j++) g[j] = fmaf(xn, s_gw[j*192 + cc], g[j]);
    }
    #pragma unroll
    for (int j = 0; j < 8; j++) g[j] = warpsum_all(g[j]);
    if (lane == 0) {
        float L[8];
        #pragma unroll
        for (int j = 0; j < 8; j++) L[j] = g[j] + gb[j];
        int e0 = 0;
        #pragma unroll
        for (int j = 1; j < 8; j++) if (L[j] > L[e0]) e0 = j;
        int e1 = (e0 == 0) ? 1 : 0;
        #pragma unroll
        for (int j = 0; j < 8; j++) if (j != e0 && L[j] > L[e1]) e1 = j;
        float w0 = 1.f / (1.f + __expf(L[e1] - L[e0]));
        float w1 = 1.f - w0;
        int p0 = atomicAdd(&g_cnt[e0], 1);
        g_gidx[e0*TTOK + p0] = t; g_gw[e0*TTOK + p0] = w0; g_grank[e0*TTOK + p0] = 0;
        int p1 = atomicAdd(&g_cnt[e1], 1);
        g_gidx[e1*TTOK + p1] = t; g_gw[e1*TTOK + p1] = w1; g_grank[e1*TTOK + p1] = 1;
    }
}

// ---------------- finalize: out += contrib0 + contrib1 -----------------------
__global__ void finalize(float* __restrict__ out) {
    int i = blockIdx.x*blockDim.x + threadIdx.x;
    if (i < TTOK*48) {
        float4 a  = reinterpret_cast<const float4*>(out)[i];
        float4 c0 = reinterpret_cast<const float4*>(g_contrib0)[i];
        float4 c1 = reinterpret_cast<const float4*>(g_contrib1)[i];
        reinterpret_cast<float4*>(out)[i] =
            make_float4(a.x + c0.x + c1.x, a.y + c0.y + c1.y,
                        a.z + c0.z + c1.z, a.w + c0.w + c1.w);
    }
}

// ---------------- host launcher -----------------------------------------------
extern "C" void kernel_launch(void* const* d_in, const int* in_sizes, int n_in,
                              void* d_out, int out_size) {
    const float* x    = (const float*)d_in[0];
    const float* mask = (const float*)d_in[1];
    const float* n1w  = (const float*)d_in[2];
    const float* n1b  = (const float*)d_in[3];
    const float* qsw  = (const float*)d_in[4];
    const float* qsb  = (const float*)d_in[5];
    const float* qmw  = (const float*)d_in[6];
    const float* qmb  = (const float*)d_in[7];
    const float* rpb  = (const float*)d_in[8];
    const float* pw   = (const float*)d_in[9];
    const float* pb   = (const float*)d_in[10];
    const float* n2w  = (const float*)d_in[11];
    const float* n2b  = (const float*)d_in[12];
    const float* gw   = (const float*)d_in[13];
    const float* gb   = (const float*)d_in[14];
    const float* W1   = (const float*)d_in[15];
    const float* b1   = (const float*)d_in[16];
    const float* W2   = (const float*)d_in[17];
    const float* b2   = (const float*)d_in[18];
    float* out = (float*)d_out;

    const int DSMEM  = 50176;   // 48KB + align pad
    const int DSMEM1 = 66560;   // 64KB + align pad (wide FC1)
    const int ASMEM  = 76800;   // attn: 73KB tiles + srs + align pad
    cudaFuncSetAttribute(gemm_qkv,    cudaFuncAttributeMaxDynamicSharedMemorySize, DSMEM);
    cudaFuncSetAttribute(gemm_proj,   cudaFuncAttributeMaxDynamicSharedMemorySize, DSMEM);
    cudaFuncSetAttribute(gemm_moe1,   cudaFuncAttributeMaxDynamicSharedMemorySize, DSMEM1);
    cudaFuncSetAttribute(gemm_moe2,   cudaFuncAttributeMaxDynamicSharedMemorySize, DSMEM);
    cudaFuncSetAttribute(attn_mma<0>, cudaFuncAttributeMaxDynamicSharedMemorySize, ASMEM);
    cudaFuncSetAttribute(attn_mma<1>, cudaFuncAttributeMaxDynamicSharedMemorySize, ASMEM);

    void *p_xout, *p_attn, *p_wp;
    cudaGetSymbolAddress(&p_xout, g_xout_bf);
    cudaGetSymbolAddress(&p_attn, g_attnbuf);
    cudaGetSymbolAddress(&p_wp,   g_wt_p);

    k_prep_all<<<489, 256>>>(qsw, qmw, pw, W1, W2, rpb);
    ln_partition<<<6144, 256>>>(x, n1w, n1b);
    gemm_qkv<<<dim3(384, 9, 2), 256, DSMEM>>>(qsb, qmb);
    attn_mma<0><<<3072, 256, ASMEM>>>(mask);               // <- profiled slot
    attn_mma<1><<<3072, 256, ASMEM>>>(mask);
    gemm_proj<<<dim3(384, 3), 256, DSMEM>>>((const __nv_bfloat16*)p_xout,
        (const __nv_bfloat16*)p_wp, pb, (float*)p_attn, 384, 192);
    resid_gate<<<6144, 256>>>(x, n2w, n2b, gw, gb, out);
    gemm_moe1<<<dim3(384, 3, 8), 256, DSMEM1>>>(b1);
    gemm_moe2<<<dim3(384, 3, 8), 256, DSMEM>>>(b2);
    finalize<<<9216, 256>>>(out);
}